// round 9
// baseline (speedup 1.0000x reference)
#include <cuda_runtime.h>
#include <cuda_bf16.h>
#include <cstdint>

#define NUc 50000
#define NVc 50000
#define ESc 800000
#define ERc 1000000
#define AS 68   // smem A-tile stride (floats) for FFMA GEMMs
#define WS 68

// ---------------- device scratch (no allocations allowed) ----------------
__device__ __align__(16) float g_s_social[(size_t)NUc * 64];
__device__ __align__(16) float g_s_ru[(size_t)NUc * 64];
__device__ __align__(16) float g_s_rv[(size_t)NVc * 64];
__device__ float g_deg_s[NUc];
__device__ float g_deg_ru[NUc];
__device__ float g_deg_rv[NVc];
__device__ __align__(16) float g_hu[(size_t)NUc * 64];
__device__ __align__(16) float g_hv[(size_t)NVc * 64];
__device__ __align__(16) float g_tu[(size_t)NUc * 64];
__device__ __align__(16) float g_tv[(size_t)NVc * 64];
__device__ __align__(16) float g_xu[(size_t)NUc * 64];
__device__ __align__(16) float g_xv[(size_t)NVc * 64];
__device__ __align__(16) float g_y2[(size_t)ERc * 16];   // 64 MB (y1 is never materialized)
__device__ double g_statU[128];
__device__ double g_statV[128];
__device__ double g_stat1[128];
__device__ double g_stat2[32];
__device__ __align__(16) float g_affU[128];
__device__ __align__(16) float g_affV[128];
__device__ __align__(16) float g_aff1[128];
__device__ __align__(16) float g_aff2[32];
// Wuv1 pre-packed into per-lane m16n8k16 B-fragment order (hi/lo bf16 split)
__device__ __align__(16) uint32_t g_fragH[2048];
__device__ __align__(16) uint32_t g_fragL[2048];
// Wuv2 (64x16) pre-packed the same way: (kt*2+nt)*64 + lane*2 + r
__device__ __align__(16) uint32_t g_frag2H[512];
__device__ __align__(16) uint32_t g_frag2L[512];

// ---------------- zero scratch ----------------
__global__ void k_zero() {
    size_t tid = (size_t)blockIdx.x * blockDim.x + threadIdx.x;
    size_t stride = (size_t)gridDim.x * blockDim.x;
    const size_t n4 = (size_t)NUc * 16;
    float4 z = make_float4(0.f, 0.f, 0.f, 0.f);
    for (size_t j = tid; j < n4; j += stride) {
        ((float4*)g_s_social)[j] = z;
        ((float4*)g_s_ru)[j] = z;
        ((float4*)g_s_rv)[j] = z;
    }
    for (size_t j = tid; j < NUc; j += stride) {
        g_deg_s[j] = 0.f;
        g_deg_ru[j] = 0.f;
        g_deg_rv[j] = 0.f;
    }
    if (tid < 128) { g_statU[tid] = 0.0; g_statV[tid] = 0.0; g_stat1[tid] = 0.0; }
    if (tid < 32) g_stat2[tid] = 0.0;
}

// ---------------- prep: pack Wuv1 + Wuv2 into mma B-fragment layout, bf16 hi/lo ----------------
__global__ void k_prepW(const float* __restrict__ W1, const float* __restrict__ W2) {
    int t = threadIdx.x;
    for (int idx = t; idx < 2048; idx += 256) {
        int r = idx & 1;
        int lane = (idx >> 1) & 31;
        int grp = idx >> 6;
        int kt = grp >> 3, nt = grp & 7;
        int g = lane >> 2, tig = lane & 3;
        int n = nt * 8 + g;
        int k0 = kt * 16 + 2 * tig + (r ? 8 : 0);
        float w0 = __ldg(W1 + k0 * 64 + n);
        float w1 = __ldg(W1 + (k0 + 1) * 64 + n);
        __nv_bfloat16 h0 = __float2bfloat16(w0), h1 = __float2bfloat16(w1);
        float l0 = w0 - __bfloat162float(h0);
        float l1 = w1 - __bfloat162float(h1);
        __nv_bfloat162 hh; hh.x = h0; hh.y = h1;
        __nv_bfloat162 ll; ll.x = __float2bfloat16(l0); ll.y = __float2bfloat16(l1);
        g_fragH[idx] = *(const uint32_t*)&hh;
        g_fragL[idx] = *(const uint32_t*)&ll;
    }
    for (int idx = t; idx < 512; idx += 256) {
        int r = idx & 1;
        int lane = (idx >> 1) & 31;
        int grp = idx >> 6;          // 0..7
        int kt = grp >> 1, nt = grp & 1;
        int g = lane >> 2, tig = lane & 3;
        int n = nt * 8 + g;
        int k0 = kt * 16 + 2 * tig + (r ? 8 : 0);
        float w0 = __ldg(W2 + k0 * 16 + n);
        float w1 = __ldg(W2 + (k0 + 1) * 16 + n);
        __nv_bfloat16 h0 = __float2bfloat16(w0), h1 = __float2bfloat16(w1);
        float l0 = w0 - __bfloat162float(h0);
        float l1 = w1 - __bfloat162float(h1);
        __nv_bfloat162 hh; hh.x = h0; hh.y = h1;
        __nv_bfloat162 ll; ll.x = __float2bfloat16(l0); ll.y = __float2bfloat16(l1);
        g_frag2H[idx] = *(const uint32_t*)&hh;
        g_frag2L[idx] = *(const uint32_t*)&ll;
    }
}

// ---------------- edge scatter: acc[dst] += feat[src] via red.v4 ----------------
__global__ __launch_bounds__(256) void k_scatter(
    const float* __restrict__ feat, const int* __restrict__ src,
    const int* __restrict__ dst, float* __restrict__ acc,
    float* __restrict__ deg, int E) {
    int g = blockIdx.x * blockDim.x + threadIdx.x;
    int e = g >> 4;
    int q = g & 15;
    if (e >= E) return;
    int s = __ldg(src + e);
    int d = __ldg(dst + e);
    float4 v = __ldg((const float4*)feat + (size_t)s * 16 + q);
    float* p = acc + (size_t)d * 64 + q * 4;
    asm volatile("red.global.add.v4.f32 [%0], {%1, %2, %3, %4};"
                 :: "l"(p), "f"(v.x), "f"(v.y), "f"(v.z), "f"(v.w) : "memory");
    if (q == 0) atomicAdd(deg + d, 1.0f);
}

// ---------------- shared GEMM helpers (64-row block, 256 threads) ----------------
__device__ __forceinline__ void mma64(const float* __restrict__ As_,
                                      const float* __restrict__ Ws_,
                                      int ty, int tx, float acc[4][4]) {
#pragma unroll 16
    for (int k = 0; k < 64; k++) {
        float4 b = *(const float4*)(Ws_ + k * WS + tx * 4);
        float a0 = As_[(ty * 4 + 0) * AS + k];
        float a1 = As_[(ty * 4 + 1) * AS + k];
        float a2 = As_[(ty * 4 + 2) * AS + k];
        float a3 = As_[(ty * 4 + 3) * AS + k];
        acc[0][0] += a0 * b.x; acc[0][1] += a0 * b.y; acc[0][2] += a0 * b.z; acc[0][3] += a0 * b.w;
        acc[1][0] += a1 * b.x; acc[1][1] += a1 * b.y; acc[1][2] += a1 * b.z; acc[1][3] += a1 * b.w;
        acc[2][0] += a2 * b.x; acc[2][1] += a2 * b.y; acc[2][2] += a2 * b.z; acc[2][3] += a2 * b.w;
        acc[3][0] += a3 * b.x; acc[3][1] += a3 * b.y; acc[3][2] += a3 * b.z; acc[3][3] += a3 * b.w;
    }
}

__device__ __forceinline__ void loadW(const float* __restrict__ W, float* __restrict__ Ws_) {
    int t = threadIdx.x, r = t >> 2, cg = (t & 3) << 4;
#pragma unroll
    for (int j = 0; j < 16; j += 4) {
        float4 v = *(const float4*)(W + r * 64 + cg + j);
        *(float4*)(Ws_ + r * WS + cg + j) = v;
    }
}

__device__ __forceinline__ void loadWsum(const float* __restrict__ Wa, const float* __restrict__ Wb,
                                         float* __restrict__ Ws_) {
    int t = threadIdx.x, r = t >> 2, cg = (t & 3) << 4;
#pragma unroll
    for (int j = 0; j < 16; j += 4) {
        float4 a = *(const float4*)(Wa + r * 64 + cg + j);
        float4 b = *(const float4*)(Wb + r * 64 + cg + j);
        *(float4*)(Ws_ + r * WS + cg + j) = make_float4(a.x + b.x, a.y + b.y, a.z + b.z, a.w + b.w);
    }
}

__device__ __forceinline__ void loadA_plain(const float* __restrict__ src, int rowBase, int N,
                                            float* __restrict__ As_) {
    int t = threadIdx.x, r = t >> 2, cg = (t & 3) << 4;
    int row = rowBase + r;
#pragma unroll
    for (int j = 0; j < 16; j += 4) {
        float4 v = make_float4(0.f, 0.f, 0.f, 0.f);
        if (row < N) v = *(const float4*)(src + (size_t)row * 64 + cg + j);
        *(float4*)(As_ + r * AS + cg + j) = v;
    }
}

__device__ __forceinline__ void loadA_mean(const float* __restrict__ src, const float* __restrict__ deg,
                                           int rowBase, int N, float* __restrict__ As_) {
    int t = threadIdx.x, r = t >> 2, cg = (t & 3) << 4;
    int row = rowBase + r;
    float sc = 0.f;
    if (row < N) sc = 1.f / fmaxf(__ldg(deg + row), 1.f);
#pragma unroll
    for (int j = 0; j < 16; j += 4) {
        float4 v = make_float4(0.f, 0.f, 0.f, 0.f);
        if (row < N) {
            v = *(const float4*)(src + (size_t)row * 64 + cg + j);
            v.x *= sc; v.y *= sc; v.z *= sc; v.w *= sc;
        }
        *(float4*)(As_ + r * AS + cg + j) = v;
    }
}

__device__ __forceinline__ void loadA_bnrelu(const float* __restrict__ src, const float* __restrict__ aff,
                                             int rowBase, int N, float* __restrict__ As_) {
    int t = threadIdx.x, r = t >> 2, cg = (t & 3) << 4;
    int row = rowBase + r;
#pragma unroll
    for (int j = 0; j < 16; j += 4) {
        float4 v = make_float4(0.f, 0.f, 0.f, 0.f);
        if (row < N) {
            v = *(const float4*)(src + (size_t)row * 64 + cg + j);
            float4 a = *(const float4*)(aff + cg + j);
            float4 c = *(const float4*)(aff + 64 + cg + j);
            v.x = fmaxf(v.x * a.x + c.x, 0.f);
            v.y = fmaxf(v.y * a.y + c.y, 0.f);
            v.z = fmaxf(v.z * a.z + c.z, 0.f);
            v.w = fmaxf(v.w * a.w + c.w, 0.f);
        }
        *(float4*)(As_ + r * AS + cg + j) = v;
    }
}

// ---------------- node combine: user ----------------
__global__ __launch_bounds__(256) void k_comb_user(
    const float* __restrict__ u2e, const float* __restrict__ Wself,
    const float* __restrict__ bself, const float* __restrict__ Wneigh,
    float* __restrict__ out) {
    __shared__ __align__(16) float As_[64 * AS];
    __shared__ __align__(16) float Ws_[64 * WS];
    int t = threadIdx.x, tx = t & 15, ty = t >> 4;
    int rowBase = blockIdx.x * 64;
    float acc[4][4] = {};

    loadA_plain(u2e, rowBase, NUc, As_);
    loadWsum(Wself, Wself + 2 * 4096, Ws_);
    __syncthreads();
    mma64(As_, Ws_, ty, tx, acc);
    __syncthreads();

    loadA_mean(g_s_social, g_deg_s, rowBase, NUc, As_);
    loadW(Wneigh, Ws_);
    __syncthreads();
    mma64(As_, Ws_, ty, tx, acc);
    __syncthreads();

    loadA_mean(g_s_ru, g_deg_ru, rowBase, NUc, As_);
    loadW(Wneigh + 2 * 4096, Ws_);
    __syncthreads();
    mma64(As_, Ws_, ty, tx, acc);

    float4 b0 = *(const float4*)(bself + tx * 4);
    float4 b2 = *(const float4*)(bself + 128 + tx * 4);
    float4 bias = make_float4(b0.x + b2.x, b0.y + b2.y, b0.z + b2.z, b0.w + b2.w);
#pragma unroll
    for (int i = 0; i < 4; i++) {
        int row = rowBase + ty * 4 + i;
        if (row < NUc) {
            *(float4*)(out + (size_t)row * 64 + tx * 4) =
                make_float4(acc[i][0] + bias.x, acc[i][1] + bias.y,
                            acc[i][2] + bias.z, acc[i][3] + bias.w);
        }
    }
}

// ---------------- node combine: item ----------------
__global__ __launch_bounds__(256) void k_comb_item(
    const float* __restrict__ v2e, const float* __restrict__ Wself,
    const float* __restrict__ bself, const float* __restrict__ Wneigh,
    float* __restrict__ out) {
    __shared__ __align__(16) float As_[64 * AS];
    __shared__ __align__(16) float Ws_[64 * WS];
    int t = threadIdx.x, tx = t & 15, ty = t >> 4;
    int rowBase = blockIdx.x * 64;
    float acc[4][4] = {};

    loadA_plain(v2e, rowBase, NVc, As_);
    loadW(Wself + 4096, Ws_);
    __syncthreads();
    mma64(As_, Ws_, ty, tx, acc);
    __syncthreads();

    loadA_mean(g_s_rv, g_deg_rv, rowBase, NVc, As_);
    loadW(Wneigh + 4096, Ws_);
    __syncthreads();
    mma64(As_, Ws_, ty, tx, acc);

    float4 bias = *(const float4*)(bself + 64 + tx * 4);
#pragma unroll
    for (int i = 0; i < 4; i++) {
        int row = rowBase + ty * 4 + i;
        if (row < NVc) {
            *(float4*)(out + (size_t)row * 64 + tx * 4) =
                make_float4(acc[i][0] + bias.x, acc[i][1] + bias.y,
                            acc[i][2] + bias.z, acc[i][3] + bias.w);
        }
    }
}

// ---------------- tower stage 1: out = in@W + b, column stats ----------------
__global__ __launch_bounds__(256) void k_tower1(
    const float* __restrict__ in, const float* __restrict__ W, const float* __restrict__ b,
    float* __restrict__ out, double* __restrict__ stats, int N) {
    __shared__ __align__(16) float As_[64 * AS];
    __shared__ __align__(16) float Ws_[64 * WS];
    __shared__ float ssum[64], ssq[64];
    int t = threadIdx.x, tx = t & 15, ty = t >> 4;
    if (t < 64) { ssum[t] = 0.f; ssq[t] = 0.f; }
    int rowBase = blockIdx.x * 64;

    loadA_plain(in, rowBase, N, As_);
    loadW(W, Ws_);
    __syncthreads();
    float acc[4][4] = {};
    mma64(As_, Ws_, ty, tx, acc);

    float4 bias = *(const float4*)(b + tx * 4);
    float cs[4] = {0, 0, 0, 0}, cq[4] = {0, 0, 0, 0};
#pragma unroll
    for (int i = 0; i < 4; i++) {
        int row = rowBase + ty * 4 + i;
        if (row < N) {
            float v0 = acc[i][0] + bias.x, v1 = acc[i][1] + bias.y;
            float v2 = acc[i][2] + bias.z, v3 = acc[i][3] + bias.w;
            *(float4*)(out + (size_t)row * 64 + tx * 4) = make_float4(v0, v1, v2, v3);
            cs[0] += v0; cq[0] += v0 * v0;
            cs[1] += v1; cq[1] += v1 * v1;
            cs[2] += v2; cq[2] += v2 * v2;
            cs[3] += v3; cq[3] += v3 * v3;
        }
    }
#pragma unroll
    for (int j = 0; j < 4; j++) {
        atomicAdd(&ssum[tx * 4 + j], cs[j]);
        atomicAdd(&ssq[tx * 4 + j], cq[j]);
    }
    __syncthreads();
    if (t < 64) atomicAdd(&stats[t], (double)ssum[t]);
    else if (t < 128) atomicAdd(&stats[t], (double)ssq[t - 64]);
}

// ---------------- BN finalize ----------------
__global__ void k_fin(const double* __restrict__ stats, const float* __restrict__ gamma,
                      const float* __restrict__ beta, float* __restrict__ aff,
                      int C, float invN) {
    int c = threadIdx.x;
    if (c < C) {
        float mean = (float)(stats[c] * (double)invN);
        float ex2 = (float)(stats[C + c] * (double)invN);
        float var = ex2 - mean * mean;
        float a = gamma[c] * rsqrtf(var + 1e-5f);
        aff[c] = a;
        aff[C + c] = beta[c] - mean * a;
    }
}

// ---------------- tower stage 2: out = relu(in*a+c) @ W + b ----------------
__global__ __launch_bounds__(256) void k_tower2(
    const float* __restrict__ in, const float* __restrict__ aff,
    const float* __restrict__ W, const float* __restrict__ b,
    float* __restrict__ out, int N) {
    __shared__ __align__(16) float As_[64 * AS];
    __shared__ __align__(16) float Ws_[64 * WS];
    int t = threadIdx.x, tx = t & 15, ty = t >> 4;
    int rowBase = blockIdx.x * 64;

    loadA_bnrelu(in, aff, rowBase, N, As_);
    loadW(W, Ws_);
    __syncthreads();
    float acc[4][4] = {};
    mma64(As_, Ws_, ty, tx, acc);

    float4 bias = *(const float4*)(b + tx * 4);
#pragma unroll
    for (int i = 0; i < 4; i++) {
        int row = rowBase + ty * 4 + i;
        if (row < N) {
            *(float4*)(out + (size_t)row * 64 + tx * 4) =
                make_float4(acc[i][0] + bias.x, acc[i][1] + bias.y,
                            acc[i][2] + bias.z, acc[i][3] + bias.w);
        }
    }
}

// ================= mma.sync edge pipeline (y1 never materialized) =================
// GEMM-1: y1 = (x_u[src] * x_v[dst]) @ Wuv1 + buv1, bf16 hi/lo split HMMA
// 128 edges/block, 8 warps, each warp m16 x n64 x k64
#define E1_SMEM 51200
#define OFF_AH 0
#define OFF_AL 17408
#define OFF_BH 34816
#define OFF_BL 43008
#define AROW 136   // bytes per A row (64 bf16 = 128B + 8B pad)

__device__ __forceinline__ void mma16816(float c[4], uint32_t a0, uint32_t a1,
                                         uint32_t a2, uint32_t a3,
                                         uint32_t b0, uint32_t b1) {
    asm volatile(
        "mma.sync.aligned.m16n8k16.row.col.f32.bf16.bf16.f32 "
        "{%0,%1,%2,%3}, {%4,%5,%6,%7}, {%8,%9}, {%0,%1,%2,%3};"
        : "+f"(c[0]), "+f"(c[1]), "+f"(c[2]), "+f"(c[3])
        : "r"(a0), "r"(a1), "r"(a2), "r"(a3), "r"(b0), "r"(b1));
}

__device__ __forceinline__ uint32_t pack_split(float x, float y, uint32_t& lo) {
    __nv_bfloat162 h = __floats2bfloat162_rn(x, y);
    float rx = x - __bfloat162float(h.x);
    float ry = y - __bfloat162float(h.y);
    __nv_bfloat162 l = __floats2bfloat162_rn(rx, ry);
    lo = *(const uint32_t*)&l;
    return *(const uint32_t*)&h;
}

// shared mainloop: fills acc[8][4] with y1 fragments (before bias)
__device__ __forceinline__ void edge_gemm1(
    char* smem, const float* __restrict__ xu, const float* __restrict__ xv,
    const int* __restrict__ es, const int* __restrict__ ed,
    int rowBase, int t, int lane, int w, float acc[8][4]) {
    // ---- B fragments (hi/lo): 2048 u32 each, coalesced copy ----
    {
        const uint4* sH = (const uint4*)g_fragH;
        const uint4* sL = (const uint4*)g_fragL;
        uint4* dH = (uint4*)(smem + OFF_BH);
        uint4* dL = (uint4*)(smem + OFF_BL);
        dH[t] = __ldg(sH + t);
        dH[t + 256] = __ldg(sH + t + 256);
        dL[t] = __ldg(sL + t);
        dL[t + 256] = __ldg(sL + t + 256);
    }
    // ---- A: gather x_u*x_v, bf16 hi/lo split; row-major [128][64] bf16, 136B stride ----
    {
        int r = t >> 1, h = t & 1;
        int e = rowBase + r;
        char* aH = smem + OFF_AH + r * AROW + h * 64;
        char* aL = smem + OFF_AL + r * AROW + h * 64;
        if (e < ERc) {
            int s = __ldg(es + e), d = __ldg(ed + e);
            const float4* pu = (const float4*)(xu + (size_t)s * 64) + h * 8;
            const float4* pv = (const float4*)(xv + (size_t)d * 64) + h * 8;
#pragma unroll
            for (int j = 0; j < 8; j++) {
                float4 a = __ldg(pu + j), v = __ldg(pv + j);
                uint32_t lo01, lo23;
                uint32_t hi01 = pack_split(a.x * v.x, a.y * v.y, lo01);
                uint32_t hi23 = pack_split(a.z * v.z, a.w * v.w, lo23);
                *(uint2*)(aH + j * 8) = make_uint2(hi01, hi23);
                *(uint2*)(aL + j * 8) = make_uint2(lo01, lo23);
            }
        } else {
#pragma unroll
            for (int j = 0; j < 8; j++) {
                *(uint2*)(aH + j * 8) = make_uint2(0u, 0u);
                *(uint2*)(aL + j * 8) = make_uint2(0u, 0u);
            }
        }
    }
    __syncthreads();

    int g = lane >> 2, tig = lane & 3;
    int r0 = w * 16 + g;
    const char* AH = smem + OFF_AH;
    const char* AL = smem + OFF_AL;
#pragma unroll
    for (int kt = 0; kt < 4; kt++) {
        int ka = kt * 32 + tig * 4;
        uint32_t aH0 = *(const uint32_t*)(AH + r0 * AROW + ka);
        uint32_t aH1 = *(const uint32_t*)(AH + (r0 + 8) * AROW + ka);
        uint32_t aH2 = *(const uint32_t*)(AH + r0 * AROW + ka + 16);
        uint32_t aH3 = *(const uint32_t*)(AH + (r0 + 8) * AROW + ka + 16);
        uint32_t aL0 = *(const uint32_t*)(AL + r0 * AROW + ka);
        uint32_t aL1 = *(const uint32_t*)(AL + (r0 + 8) * AROW + ka);
        uint32_t aL2 = *(const uint32_t*)(AL + r0 * AROW + ka + 16);
        uint32_t aL3 = *(const uint32_t*)(AL + (r0 + 8) * AROW + ka + 16);
#pragma unroll
        for (int nt = 0; nt < 8; nt++) {
            uint32_t boff = ((kt * 8 + nt) * 64 + lane * 2) * 4;
            uint2 bH = *(const uint2*)(smem + OFF_BH + boff);
            uint2 bL = *(const uint2*)(smem + OFF_BL + boff);
            mma16816(acc[nt], aH0, aH1, aH2, aH3, bH.x, bH.y);
            mma16816(acc[nt], aH0, aH1, aH2, aH3, bL.x, bL.y);
            mma16816(acc[nt], aL0, aL1, aL2, aL3, bH.x, bH.y);
        }
    }
}

// ---- pass A: stats of y1 only (no global store) ----
__global__ __launch_bounds__(256)
void k_eA(const float* __restrict__ xu, const float* __restrict__ xv,
          const int* __restrict__ es, const int* __restrict__ ed,
          const float* __restrict__ b, double* __restrict__ stats) {
    extern __shared__ __align__(16) char smem[];
    __shared__ float ssum[64], ssq[64];
    int t = threadIdx.x, lane = t & 31, w = t >> 5;
    int rowBase = blockIdx.x * 128;
    if (t < 64) { ssum[t] = 0.f; ssq[t] = 0.f; }

    float acc[8][4] = {};
    edge_gemm1(smem, xu, xv, es, ed, rowBase, t, lane, w, acc);
    __syncthreads();

    // stage C to smem (stride-65 f32) for column-owner stat reduction
    int g = lane >> 2, tig = lane & 3;
    int r0 = w * 16 + g;
    float* stage = (float*)smem;
#pragma unroll
    for (int nt = 0; nt < 8; nt++) {
        int c = nt * 8 + tig * 2;
        stage[r0 * 65 + c] = acc[nt][0];
        stage[r0 * 65 + c + 1] = acc[nt][1];
        stage[(r0 + 8) * 65 + c] = acc[nt][2];
        stage[(r0 + 8) * 65 + c + 1] = acc[nt][3];
    }
    __syncthreads();

    int c4 = (t & 15) * 4;
    float4 bias = *(const float4*)(b + c4);
    float cs[4] = {0, 0, 0, 0}, cq[4] = {0, 0, 0, 0};
#pragma unroll
    for (int i = 0; i < 8; i++) {
        int r = (t >> 4) + 16 * i;
        int e = rowBase + r;
        if (e < ERc) {
            const float* sp = stage + r * 65 + c4;
            float v0 = sp[0] + bias.x, v1 = sp[1] + bias.y;
            float v2 = sp[2] + bias.z, v3 = sp[3] + bias.w;
            cs[0] += v0; cq[0] += v0 * v0;
            cs[1] += v1; cq[1] += v1 * v1;
            cs[2] += v2; cq[2] += v2 * v2;
            cs[3] += v3; cq[3] += v3 * v3;
        }
    }
#pragma unroll
    for (int j = 0; j < 4; j++) {
        atomicAdd(&ssum[c4 + j], cs[j]);
        atomicAdd(&ssq[c4 + j], cq[j]);
    }
    __syncthreads();
    if (t < 64) atomicAdd(&stats[t], (double)ssum[t]);
    else if (t < 128) atomicAdd(&stats[t], (double)ssq[t - 64]);
}

// ---- pass B: recompute y1, BN1+relu in fragment domain, GEMM-2 (64->16), y2 + stats2 ----
__global__ __launch_bounds__(256)
void k_eB(const float* __restrict__ xu, const float* __restrict__ xv,
          const int* __restrict__ es, const int* __restrict__ ed,
          const float* __restrict__ b1, const float* __restrict__ aff,
          const float* __restrict__ b2, float* __restrict__ y2,
          double* __restrict__ stats) {
    extern __shared__ __align__(16) char smem[];
    __shared__ float affS[128];
    __shared__ float ssum[16], ssq[16];
    int t = threadIdx.x, lane = t & 31, w = t >> 5;
    int rowBase = blockIdx.x * 128;
    if (t < 128) affS[t] = __ldg(aff + t);
    if (t < 16) { ssum[t] = 0.f; ssq[t] = 0.f; }

    float acc[8][4] = {};
    edge_gemm1(smem, xu, xv, es, ed, rowBase, t, lane, w, acc);

    int g = lane >> 2, tig = lane & 3;
    int r0 = w * 16 + g;

    // BN1 + relu in C-fragment domain, bf16-split, then GEMM-2 via mma
    float acc2[2][4] = {};
#pragma unroll
    for (int kt = 0; kt < 4; kt++) {
        // cols for this k-tile: c0 = 16kt+2tig, c1 = c0+1 (nt=2kt); c2 = c0+8, c3 = c2+1 (nt=2kt+1)
        int c0 = kt * 16 + tig * 2;
        float s0 = affS[c0], h0 = affS[64 + c0];
        float s1 = affS[c0 + 1], h1 = affS[64 + c0 + 1];
        float s2 = affS[c0 + 8], h2 = affS[64 + c0 + 8];
        float s3 = affS[c0 + 9], h3 = affS[64 + c0 + 9];
        float b00 = __ldg(b1 + c0), b01 = __ldg(b1 + c0 + 1);
        float b02 = __ldg(b1 + c0 + 8), b03 = __ldg(b1 + c0 + 9);
        float v00 = fmaxf((acc[2 * kt][0] + b00) * s0 + h0, 0.f);
        float v01 = fmaxf((acc[2 * kt][1] + b01) * s1 + h1, 0.f);
        float v10 = fmaxf((acc[2 * kt][2] + b00) * s0 + h0, 0.f);
        float v11 = fmaxf((acc[2 * kt][3] + b01) * s1 + h1, 0.f);
        float w00 = fmaxf((acc[2 * kt + 1][0] + b02) * s2 + h2, 0.f);
        float w01 = fmaxf((acc[2 * kt + 1][1] + b03) * s3 + h3, 0.f);
        float w10 = fmaxf((acc[2 * kt + 1][2] + b02) * s2 + h2, 0.f);
        float w11 = fmaxf((acc[2 * kt + 1][3] + b03) * s3 + h3, 0.f);
        uint32_t l0, l1, l2, l3;
        uint32_t a0 = pack_split(v00, v01, l0);
        uint32_t a1 = pack_split(v10, v11, l1);
        uint32_t a2 = pack_split(w00, w01, l2);
        uint32_t a3 = pack_split(w10, w11, l3);
#pragma unroll
        for (int n2 = 0; n2 < 2; n2++) {
            int fo = (kt * 2 + n2) * 64 + lane * 2;
            uint2 bH = __ldg((const uint2*)(g_frag2H + fo));
            uint2 bL = __ldg((const uint2*)(g_frag2L + fo));
            mma16816(acc2[n2], a0, a1, a2, a3, bH.x, bH.y);
            mma16816(acc2[n2], a0, a1, a2, a3, bL.x, bL.y);
            mma16816(acc2[n2], l0, l1, l2, l3, bH.x, bH.y);
        }
    }

    // epilogue: bias2, write y2 (fragment layout -> [e][16]), stats2
    int e0 = rowBase + r0, e1 = e0 + 8;
    float cs[4] = {0, 0, 0, 0}, cq[4] = {0, 0, 0, 0};
#pragma unroll
    for (int n2 = 0; n2 < 2; n2++) {
        int c = n2 * 8 + tig * 2;
        float bx = __ldg(b2 + c), by = __ldg(b2 + c + 1);
        float u0 = acc2[n2][0] + bx, u1 = acc2[n2][1] + by;
        float u2 = acc2[n2][2] + bx, u3 = acc2[n2][3] + by;
        if (e0 < ERc) {
            *(float2*)(y2 + (size_t)e0 * 16 + c) = make_float2(u0, u1);
            cs[n2 * 2] += u0; cq[n2 * 2] += u0 * u0;
            cs[n2 * 2 + 1] += u1; cq[n2 * 2 + 1] += u1 * u1;
        }
        if (e1 < ERc) {
            *(float2*)(y2 + (size_t)e1 * 16 + c) = make_float2(u2, u3);
            cs[n2 * 2] += u2; cq[n2 * 2] += u2 * u2;
            cs[n2 * 2 + 1] += u3; cq[n2 * 2 + 1] += u3 * u3;
        }
    }
#pragma unroll
    for (int n2 = 0; n2 < 2; n2++) {
#pragma unroll
        for (int j = 0; j < 2; j++) {
            int c = n2 * 8 + tig * 2 + j;
            atomicAdd(&ssum[c], cs[n2 * 2 + j]);
            atomicAdd(&ssq[c], cq[n2 * 2 + j]);
        }
    }
    __syncthreads();
    if (t < 16) atomicAdd(&stats[t], (double)ssum[t]);
    else if (t < 32) atomicAdd(&stats[t], (double)ssq[t - 16]);
}

// ---------------- edge pass 3: scores = relu(y2*a2+c2) . w3 + b3 ----------------
__global__ __launch_bounds__(256) void k_edge3(
    const float* __restrict__ y2, const float* __restrict__ aff,
    const float* __restrict__ w3, const float* __restrict__ b3,
    float* __restrict__ out) {
    int e = blockIdx.x * blockDim.x + threadIdx.x;
    if (e >= ERc) return;
    const float4* p = (const float4*)(y2 + (size_t)e * 16);
    float s = 0.f;
#pragma unroll
    for (int j = 0; j < 4; j++) {
        float4 v = __ldg(p + j);
        float4 a = *(const float4*)(aff + 4 * j);
        float4 c = *(const float4*)(aff + 16 + 4 * j);
        float4 w = *(const float4*)(w3 + 4 * j);
        s += fmaxf(v.x * a.x + c.x, 0.f) * w.x;
        s += fmaxf(v.y * a.y + c.y, 0.f) * w.y;
        s += fmaxf(v.z * a.z + c.z, 0.f) * w.z;
        s += fmaxf(v.w * a.w + c.w, 0.f) * w.w;
    }
    out[e] = s + __ldg(b3);
}

// ---------------- host ----------------
extern "C" void kernel_launch(void* const* d_in, const int* in_sizes, int n_in,
                              void* d_out, int out_size) {
    const float* u2e     = (const float*)d_in[0];
    const float* v2e     = (const float*)d_in[1];
    const float* W_self  = (const float*)d_in[2];
    const float* b_self  = (const float*)d_in[3];
    const float* W_neigh = (const float*)d_in[4];
    const float* Wur1 = (const float*)d_in[5];
    const float* bur1 = (const float*)d_in[6];
    const float* Wur2 = (const float*)d_in[7];
    const float* bur2 = (const float*)d_in[8];
    const float* Wvr1 = (const float*)d_in[9];
    const float* bvr1 = (const float*)d_in[10];
    const float* Wvr2 = (const float*)d_in[11];
    const float* bvr2 = (const float*)d_in[12];
    const float* Wuv1 = (const float*)d_in[13];
    const float* buv1 = (const float*)d_in[14];
    const float* Wuv2 = (const float*)d_in[15];
    const float* buv2 = (const float*)d_in[16];
    const float* Wuv3 = (const float*)d_in[17];
    const float* buv3 = (const float*)d_in[18];
    const float* bn_gamma  = (const float*)d_in[19];
    const float* bn_beta   = (const float*)d_in[20];
    const float* bn4_gamma = (const float*)d_in[21];
    const float* bn4_beta  = (const float*)d_in[22];
    const int* social_src = (const int*)d_in[23];
    const int* social_dst = (const int*)d_in[24];
    const int* rates_src  = (const int*)d_in[25];
    const int* rates_dst  = (const int*)d_in[26];
    float* out = (float*)d_out;

    void *p_ssoc, *p_sru, *p_srv, *p_degs, *p_degru, *p_degrv;
    void *p_hu, *p_hv, *p_tu, *p_tv, *p_xu, *p_xv, *p_y2;
    void *p_stU, *p_stV, *p_st1, *p_st2, *p_aU, *p_aV, *p_a1, *p_a2;
    cudaGetSymbolAddress(&p_ssoc, g_s_social);
    cudaGetSymbolAddress(&p_sru, g_s_ru);
    cudaGetSymbolAddress(&p_srv, g_s_rv);
    cudaGetSymbolAddress(&p_degs, g_deg_s);
    cudaGetSymbolAddress(&p_degru, g_deg_ru);
    cudaGetSymbolAddress(&p_degrv, g_deg_rv);
    cudaGetSymbolAddress(&p_hu, g_hu);
    cudaGetSymbolAddress(&p_hv, g_hv);
    cudaGetSymbolAddress(&p_tu, g_tu);
    cudaGetSymbolAddress(&p_tv, g_tv);
    cudaGetSymbolAddress(&p_xu, g_xu);
    cudaGetSymbolAddress(&p_xv, g_xv);
    cudaGetSymbolAddress(&p_y2, g_y2);
    cudaGetSymbolAddress(&p_stU, g_statU);
    cudaGetSymbolAddress(&p_stV, g_statV);
    cudaGetSymbolAddress(&p_st1, g_stat1);
    cudaGetSymbolAddress(&p_st2, g_stat2);
    cudaGetSymbolAddress(&p_aU, g_affU);
    cudaGetSymbolAddress(&p_aV, g_affV);
    cudaGetSymbolAddress(&p_a1, g_aff1);
    cudaGetSymbolAddress(&p_a2, g_aff2);

    cudaFuncSetAttribute(k_eA, cudaFuncAttributeMaxDynamicSharedMemorySize, E1_SMEM);
    cudaFuncSetAttribute(k_eB, cudaFuncAttributeMaxDynamicSharedMemorySize, E1_SMEM);

    const int NB_U = (NUc + 63) / 64;
    const int NB_V = (NVc + 63) / 64;
    const int NB_E1 = (ERc + 127) / 128;

    k_zero<<<2048, 256>>>();
    k_prepW<<<1, 256>>>(Wuv1, Wuv2);

    // segment sums: social (u->u), rated (v->u), rates (u->v); 16 lanes per edge
    k_scatter<<<ESc / 16, 256>>>(u2e, social_src, social_dst,
                                 (float*)p_ssoc, (float*)p_degs, ESc);
    k_scatter<<<ERc / 16, 256>>>(v2e, rates_dst, rates_src,
                                 (float*)p_sru, (float*)p_degru, ERc);
    k_scatter<<<ERc / 16, 256>>>(u2e, rates_src, rates_dst,
                                 (float*)p_srv, (float*)p_degrv, ERc);

    k_comb_user<<<NB_U, 256>>>(u2e, W_self, b_self, W_neigh, (float*)p_hu);
    k_comb_item<<<NB_V, 256>>>(v2e, W_self, b_self, W_neigh, (float*)p_hv);

    k_tower1<<<NB_U, 256>>>((const float*)p_hu, Wur1, bur1, (float*)p_tu, (double*)p_stU, NUc);
    k_tower1<<<NB_V, 256>>>((const float*)p_hv, Wvr1, bvr1, (float*)p_tv, (double*)p_stV, NVc);
    k_fin<<<1, 64>>>((const double*)p_stU, bn_gamma + 0, bn_beta + 0, (float*)p_aU, 64, 1.0f / NUc);
    k_fin<<<1, 64>>>((const double*)p_stV, bn_gamma + 64, bn_beta + 64, (float*)p_aV, 64, 1.0f / NVc);
    k_tower2<<<NB_U, 256>>>((const float*)p_tu, (const float*)p_aU, Wur2, bur2, (float*)p_xu, NUc);
    k_tower2<<<NB_V, 256>>>((const float*)p_tv, (const float*)p_aV, Wvr2, bvr2, (float*)p_xv, NVc);

    k_eA<<<NB_E1, 256, E1_SMEM>>>((const float*)p_xu, (const float*)p_xv,
                                  rates_src, rates_dst, buv1, (double*)p_st1);
    k_fin<<<1, 64>>>((const double*)p_st1, bn_gamma + 128, bn_beta + 128, (float*)p_a1, 64, 1.0f / ERc);
    k_eB<<<NB_E1, 256, E1_SMEM>>>((const float*)p_xu, (const float*)p_xv,
                                  rates_src, rates_dst, buv1, (const float*)p_a1,
                                  buv2, (float*)p_y2, (double*)p_st2);
    k_fin<<<1, 16>>>((const double*)p_st2, bn4_gamma, bn4_beta, (float*)p_a2, 16, 1.0f / ERc);
    k_edge3<<<(ERc + 255) / 256, 256>>>((const float*)p_y2, (const float*)p_a2, Wuv3, buv3, out);

    (void)in_sizes; (void)n_in; (void)out_size;
}

// round 10
// speedup vs baseline: 1.2281x; 1.2281x over previous
#include <cuda_runtime.h>
#include <cuda_bf16.h>
#include <cstdint>

#define NUc 50000
#define NVc 50000
#define ESc 800000
#define ERc 1000000
#define AS 68   // smem A-tile stride (floats) for FFMA GEMMs
#define WS 68

// ---------------- device scratch (no allocations allowed) ----------------
__device__ __align__(16) float g_s_social[(size_t)NUc * 64];
__device__ __align__(16) float g_s_ru[(size_t)NUc * 64];
__device__ __align__(16) float g_s_rv[(size_t)NVc * 64];
__device__ float g_deg_s[NUc];
__device__ float g_deg_ru[NUc];
__device__ float g_deg_rv[NVc];
__device__ __align__(16) float g_tu[(size_t)NUc * 64];
__device__ __align__(16) float g_tv[(size_t)NVc * 64];
__device__ __align__(16) float g_xu[(size_t)NUc * 64];
__device__ __align__(16) float g_xv[(size_t)NVc * 64];
__device__ __align__(16) float g_y1[(size_t)ERc * 64];   // 256 MB
__device__ __align__(16) float g_y2[(size_t)ERc * 16];   // 64 MB
__device__ double g_statU[128];
__device__ double g_statV[128];
__device__ double g_stat1[128];
__device__ double g_stat2[32];
__device__ __align__(16) float g_affU[128];
__device__ __align__(16) float g_affV[128];
__device__ __align__(16) float g_aff1[128];
__device__ __align__(16) float g_aff2[32];
// Wuv1 pre-packed into per-lane m16n8k16 B-fragment order (hi/lo bf16 split)
__device__ __align__(16) uint32_t g_fragH[2048];
__device__ __align__(16) uint32_t g_fragL[2048];
// Wuv2 (64x16) pre-packed the same way: (kt*2+nt)*64 + lane*2 + r
__device__ __align__(16) uint32_t g_frag2H[512];
__device__ __align__(16) uint32_t g_frag2L[512];

// ---------------- zero scratch ----------------
__global__ void k_zero() {
    size_t tid = (size_t)blockIdx.x * blockDim.x + threadIdx.x;
    size_t stride = (size_t)gridDim.x * blockDim.x;
    const size_t n4 = (size_t)NUc * 16;
    float4 z = make_float4(0.f, 0.f, 0.f, 0.f);
    for (size_t j = tid; j < n4; j += stride) {
        ((float4*)g_s_social)[j] = z;
        ((float4*)g_s_ru)[j] = z;
        ((float4*)g_s_rv)[j] = z;
    }
    for (size_t j = tid; j < NUc; j += stride) {
        g_deg_s[j] = 0.f;
        g_deg_ru[j] = 0.f;
        g_deg_rv[j] = 0.f;
    }
    if (tid < 128) { g_statU[tid] = 0.0; g_statV[tid] = 0.0; g_stat1[tid] = 0.0; }
    if (tid < 32) g_stat2[tid] = 0.0;
}

// ---------------- prep: pack Wuv1 + Wuv2 into mma B-fragment layout, bf16 hi/lo ----------------
__global__ void k_prepW(const float* __restrict__ W1, const float* __restrict__ W2) {
    int t = threadIdx.x;
    for (int idx = t; idx < 2048; idx += 256) {
        int r = idx & 1;
        int lane = (idx >> 1) & 31;
        int grp = idx >> 6;
        int kt = grp >> 3, nt = grp & 7;
        int g = lane >> 2, tig = lane & 3;
        int n = nt * 8 + g;
        int k0 = kt * 16 + 2 * tig + (r ? 8 : 0);
        float w0 = __ldg(W1 + k0 * 64 + n);
        float w1 = __ldg(W1 + (k0 + 1) * 64 + n);
        __nv_bfloat16 h0 = __float2bfloat16(w0), h1 = __float2bfloat16(w1);
        float l0 = w0 - __bfloat162float(h0);
        float l1 = w1 - __bfloat162float(h1);
        __nv_bfloat162 hh; hh.x = h0; hh.y = h1;
        __nv_bfloat162 ll; ll.x = __float2bfloat16(l0); ll.y = __float2bfloat16(l1);
        g_fragH[idx] = *(const uint32_t*)&hh;
        g_fragL[idx] = *(const uint32_t*)&ll;
    }
    for (int idx = t; idx < 512; idx += 256) {
        int r = idx & 1;
        int lane = (idx >> 1) & 31;
        int grp = idx >> 6;          // 0..7
        int kt = grp >> 1, nt = grp & 1;
        int g = lane >> 2, tig = lane & 3;
        int n = nt * 8 + g;
        int k0 = kt * 16 + 2 * tig + (r ? 8 : 0);
        float w0 = __ldg(W2 + k0 * 16 + n);
        float w1 = __ldg(W2 + (k0 + 1) * 16 + n);
        __nv_bfloat16 h0 = __float2bfloat16(w0), h1 = __float2bfloat16(w1);
        float l0 = w0 - __bfloat162float(h0);
        float l1 = w1 - __bfloat162float(h1);
        __nv_bfloat162 hh; hh.x = h0; hh.y = h1;
        __nv_bfloat162 ll; ll.x = __float2bfloat16(l0); ll.y = __float2bfloat16(l1);
        g_frag2H[idx] = *(const uint32_t*)&hh;
        g_frag2L[idx] = *(const uint32_t*)&ll;
    }
}

// ---------------- social scatter: acc[dst] += feat[src] via red.v4 ----------------
__global__ __launch_bounds__(256) void k_scatter(
    const float* __restrict__ feat, const int* __restrict__ src,
    const int* __restrict__ dst, float* __restrict__ acc,
    float* __restrict__ deg, int E) {
    int g = blockIdx.x * blockDim.x + threadIdx.x;
    int e = g >> 4;
    int q = g & 15;
    if (e >= E) return;
    int s = __ldg(src + e);
    int d = __ldg(dst + e);
    float4 v = __ldg((const float4*)feat + (size_t)s * 16 + q);
    float* p = acc + (size_t)d * 64 + q * 4;
    asm volatile("red.global.add.v4.f32 [%0], {%1, %2, %3, %4};"
                 :: "l"(p), "f"(v.x), "f"(v.y), "f"(v.z), "f"(v.w) : "memory");
    if (q == 0) atomicAdd(deg + d, 1.0f);
}

// ---------------- fused rates scatter: both directions, one index read ----------------
__global__ __launch_bounds__(256) void k_scatter2(
    const float* __restrict__ u2e, const float* __restrict__ v2e,
    const int* __restrict__ rs, const int* __restrict__ rd,
    float* __restrict__ s_rv, float* __restrict__ s_ru,
    float* __restrict__ deg_rv, float* __restrict__ deg_ru) {
    int g = blockIdx.x * blockDim.x + threadIdx.x;
    int e = g >> 4;
    int q = g & 15;
    if (e >= ERc) return;
    int s = __ldg(rs + e);
    int d = __ldg(rd + e);
    float4 a = __ldg((const float4*)u2e + (size_t)s * 16 + q);
    float4 b = __ldg((const float4*)v2e + (size_t)d * 16 + q);
    float* p1 = s_rv + (size_t)d * 64 + q * 4;
    float* p2 = s_ru + (size_t)s * 64 + q * 4;
    asm volatile("red.global.add.v4.f32 [%0], {%1, %2, %3, %4};"
                 :: "l"(p1), "f"(a.x), "f"(a.y), "f"(a.z), "f"(a.w) : "memory");
    asm volatile("red.global.add.v4.f32 [%0], {%1, %2, %3, %4};"
                 :: "l"(p2), "f"(b.x), "f"(b.y), "f"(b.z), "f"(b.w) : "memory");
    if (q == 0) {
        atomicAdd(deg_rv + d, 1.0f);
        atomicAdd(deg_ru + s, 1.0f);
    }
}

// ---------------- shared FFMA GEMM helpers (64-row block, 256 threads) ----------------
__device__ __forceinline__ void mma64(const float* __restrict__ As_,
                                      const float* __restrict__ Ws_,
                                      int ty, int tx, float acc[4][4]) {
#pragma unroll 16
    for (int k = 0; k < 64; k++) {
        float4 b = *(const float4*)(Ws_ + k * WS + tx * 4);
        float a0 = As_[(ty * 4 + 0) * AS + k];
        float a1 = As_[(ty * 4 + 1) * AS + k];
        float a2 = As_[(ty * 4 + 2) * AS + k];
        float a3 = As_[(ty * 4 + 3) * AS + k];
        acc[0][0] += a0 * b.x; acc[0][1] += a0 * b.y; acc[0][2] += a0 * b.z; acc[0][3] += a0 * b.w;
        acc[1][0] += a1 * b.x; acc[1][1] += a1 * b.y; acc[1][2] += a1 * b.z; acc[1][3] += a1 * b.w;
        acc[2][0] += a2 * b.x; acc[2][1] += a2 * b.y; acc[2][2] += a2 * b.z; acc[2][3] += a2 * b.w;
        acc[3][0] += a3 * b.x; acc[3][1] += a3 * b.y; acc[3][2] += a3 * b.z; acc[3][3] += a3 * b.w;
    }
}

__device__ __forceinline__ void loadW(const float* __restrict__ W, float* __restrict__ Ws_) {
    int t = threadIdx.x, r = t >> 2, cg = (t & 3) << 4;
#pragma unroll
    for (int j = 0; j < 16; j += 4) {
        float4 v = *(const float4*)(W + r * 64 + cg + j);
        *(float4*)(Ws_ + r * WS + cg + j) = v;
    }
}

__device__ __forceinline__ void loadWsum(const float* __restrict__ Wa, const float* __restrict__ Wb,
                                         float* __restrict__ Ws_) {
    int t = threadIdx.x, r = t >> 2, cg = (t & 3) << 4;
#pragma unroll
    for (int j = 0; j < 16; j += 4) {
        float4 a = *(const float4*)(Wa + r * 64 + cg + j);
        float4 b = *(const float4*)(Wb + r * 64 + cg + j);
        *(float4*)(Ws_ + r * WS + cg + j) = make_float4(a.x + b.x, a.y + b.y, a.z + b.z, a.w + b.w);
    }
}

__device__ __forceinline__ void loadA_plain(const float* __restrict__ src, int rowBase, int N,
                                            float* __restrict__ As_) {
    int t = threadIdx.x, r = t >> 2, cg = (t & 3) << 4;
    int row = rowBase + r;
#pragma unroll
    for (int j = 0; j < 16; j += 4) {
        float4 v = make_float4(0.f, 0.f, 0.f, 0.f);
        if (row < N) v = *(const float4*)(src + (size_t)row * 64 + cg + j);
        *(float4*)(As_ + r * AS + cg + j) = v;
    }
}

__device__ __forceinline__ void loadA_mean(const float* __restrict__ src, const float* __restrict__ deg,
                                           int rowBase, int N, float* __restrict__ As_) {
    int t = threadIdx.x, r = t >> 2, cg = (t & 3) << 4;
    int row = rowBase + r;
    float sc = 0.f;
    if (row < N) sc = 1.f / fmaxf(__ldg(deg + row), 1.f);
#pragma unroll
    for (int j = 0; j < 16; j += 4) {
        float4 v = make_float4(0.f, 0.f, 0.f, 0.f);
        if (row < N) {
            v = *(const float4*)(src + (size_t)row * 64 + cg + j);
            v.x *= sc; v.y *= sc; v.z *= sc; v.w *= sc;
        }
        *(float4*)(As_ + r * AS + cg + j) = v;
    }
}

__device__ __forceinline__ void loadA_bnrelu(const float* __restrict__ src, const float* __restrict__ aff,
                                             int rowBase, int N, float* __restrict__ As_) {
    int t = threadIdx.x, r = t >> 2, cg = (t & 3) << 4;
    int row = rowBase + r;
#pragma unroll
    for (int j = 0; j < 16; j += 4) {
        float4 v = make_float4(0.f, 0.f, 0.f, 0.f);
        if (row < N) {
            v = *(const float4*)(src + (size_t)row * 64 + cg + j);
            float4 a = *(const float4*)(aff + cg + j);
            float4 c = *(const float4*)(aff + 64 + cg + j);
            v.x = fmaxf(v.x * a.x + c.x, 0.f);
            v.y = fmaxf(v.y * a.y + c.y, 0.f);
            v.z = fmaxf(v.z * a.z + c.z, 0.f);
            v.w = fmaxf(v.w * a.w + c.w, 0.f);
        }
        *(float4*)(As_ + r * AS + cg + j) = v;
    }
}

// ---------------- fused: user combine (3 GEMMs) + tower1 GEMM + stats ----------------
__global__ __launch_bounds__(256) void k_user1(
    const float* __restrict__ u2e, const float* __restrict__ Wself,
    const float* __restrict__ bself, const float* __restrict__ Wneigh,
    const float* __restrict__ W1, const float* __restrict__ b1,
    float* __restrict__ out, double* __restrict__ stats) {
    __shared__ __align__(16) float As_[64 * AS];
    __shared__ __align__(16) float Ws_[64 * WS];
    __shared__ float ssum[64], ssq[64];
    int t = threadIdx.x, tx = t & 15, ty = t >> 4;
    if (t < 64) { ssum[t] = 0.f; ssq[t] = 0.f; }
    int rowBase = blockIdx.x * 64;
    float acc[4][4] = {};

    loadA_plain(u2e, rowBase, NUc, As_);
    loadWsum(Wself, Wself + 2 * 4096, Ws_);
    __syncthreads();
    mma64(As_, Ws_, ty, tx, acc);
    __syncthreads();

    loadA_mean(g_s_social, g_deg_s, rowBase, NUc, As_);
    loadW(Wneigh, Ws_);
    __syncthreads();
    mma64(As_, Ws_, ty, tx, acc);
    __syncthreads();

    loadA_mean(g_s_ru, g_deg_ru, rowBase, NUc, As_);
    loadW(Wneigh + 2 * 4096, Ws_);
    __syncthreads();
    mma64(As_, Ws_, ty, tx, acc);
    __syncthreads();   // all reads of As_/Ws_ done

    // h = acc + (b_self[0]+b_self[2]); stage h into As_, W1 into Ws_
    {
        float4 b0 = *(const float4*)(bself + tx * 4);
        float4 b2 = *(const float4*)(bself + 128 + tx * 4);
#pragma unroll
        for (int i = 0; i < 4; i++) {
            *(float4*)(As_ + (ty * 4 + i) * AS + tx * 4) =
                make_float4(acc[i][0] + b0.x + b2.x, acc[i][1] + b0.y + b2.y,
                            acc[i][2] + b0.z + b2.z, acc[i][3] + b0.w + b2.w);
        }
    }
    loadW(W1, Ws_);
    __syncthreads();
    float acc2[4][4] = {};
    mma64(As_, Ws_, ty, tx, acc2);

    float4 bias = *(const float4*)(b1 + tx * 4);
    float cs[4] = {0, 0, 0, 0}, cq[4] = {0, 0, 0, 0};
#pragma unroll
    for (int i = 0; i < 4; i++) {
        int row = rowBase + ty * 4 + i;
        if (row < NUc) {
            float v0 = acc2[i][0] + bias.x, v1 = acc2[i][1] + bias.y;
            float v2 = acc2[i][2] + bias.z, v3 = acc2[i][3] + bias.w;
            *(float4*)(out + (size_t)row * 64 + tx * 4) = make_float4(v0, v1, v2, v3);
            cs[0] += v0; cq[0] += v0 * v0;
            cs[1] += v1; cq[1] += v1 * v1;
            cs[2] += v2; cq[2] += v2 * v2;
            cs[3] += v3; cq[3] += v3 * v3;
        }
    }
#pragma unroll
    for (int j = 0; j < 4; j++) {
        atomicAdd(&ssum[tx * 4 + j], cs[j]);
        atomicAdd(&ssq[tx * 4 + j], cq[j]);
    }
    __syncthreads();
    if (t < 64) atomicAdd(&stats[t], (double)ssum[t]);
    else if (t < 128) atomicAdd(&stats[t], (double)ssq[t - 64]);
}

// ---------------- fused: item combine (2 GEMMs) + tower1 GEMM + stats ----------------
__global__ __launch_bounds__(256) void k_item1(
    const float* __restrict__ v2e, const float* __restrict__ Wself,
    const float* __restrict__ bself, const float* __restrict__ Wneigh,
    const float* __restrict__ W1, const float* __restrict__ b1,
    float* __restrict__ out, double* __restrict__ stats) {
    __shared__ __align__(16) float As_[64 * AS];
    __shared__ __align__(16) float Ws_[64 * WS];
    __shared__ float ssum[64], ssq[64];
    int t = threadIdx.x, tx = t & 15, ty = t >> 4;
    if (t < 64) { ssum[t] = 0.f; ssq[t] = 0.f; }
    int rowBase = blockIdx.x * 64;
    float acc[4][4] = {};

    loadA_plain(v2e, rowBase, NVc, As_);
    loadW(Wself + 4096, Ws_);
    __syncthreads();
    mma64(As_, Ws_, ty, tx, acc);
    __syncthreads();

    loadA_mean(g_s_rv, g_deg_rv, rowBase, NVc, As_);
    loadW(Wneigh + 4096, Ws_);
    __syncthreads();
    mma64(As_, Ws_, ty, tx, acc);
    __syncthreads();

    {
        float4 b1s = *(const float4*)(bself + 64 + tx * 4);
#pragma unroll
        for (int i = 0; i < 4; i++) {
            *(float4*)(As_ + (ty * 4 + i) * AS + tx * 4) =
                make_float4(acc[i][0] + b1s.x, acc[i][1] + b1s.y,
                            acc[i][2] + b1s.z, acc[i][3] + b1s.w);
        }
    }
    loadW(W1, Ws_);
    __syncthreads();
    float acc2[4][4] = {};
    mma64(As_, Ws_, ty, tx, acc2);

    float4 bias = *(const float4*)(b1 + tx * 4);
    float cs[4] = {0, 0, 0, 0}, cq[4] = {0, 0, 0, 0};
#pragma unroll
    for (int i = 0; i < 4; i++) {
        int row = rowBase + ty * 4 + i;
        if (row < NVc) {
            float v0 = acc2[i][0] + bias.x, v1 = acc2[i][1] + bias.y;
            float v2 = acc2[i][2] + bias.z, v3 = acc2[i][3] + bias.w;
            *(float4*)(out + (size_t)row * 64 + tx * 4) = make_float4(v0, v1, v2, v3);
            cs[0] += v0; cq[0] += v0 * v0;
            cs[1] += v1; cq[1] += v1 * v1;
            cs[2] += v2; cq[2] += v2 * v2;
            cs[3] += v3; cq[3] += v3 * v3;
        }
    }
#pragma unroll
    for (int j = 0; j < 4; j++) {
        atomicAdd(&ssum[tx * 4 + j], cs[j]);
        atomicAdd(&ssq[tx * 4 + j], cq[j]);
    }
    __syncthreads();
    if (t < 64) atomicAdd(&stats[t], (double)ssum[t]);
    else if (t < 128) atomicAdd(&stats[t], (double)ssq[t - 64]);
}

// ---------------- BN finalize ----------------
__global__ void k_fin(const double* __restrict__ stats, const float* __restrict__ gamma,
                      const float* __restrict__ beta, float* __restrict__ aff,
                      int C, float invN) {
    int c = threadIdx.x;
    if (c < C) {
        float mean = (float)(stats[c] * (double)invN);
        float ex2 = (float)(stats[C + c] * (double)invN);
        float var = ex2 - mean * mean;
        float a = gamma[c] * rsqrtf(var + 1e-5f);
        aff[c] = a;
        aff[C + c] = beta[c] - mean * a;
    }
}

// ---------------- tower stage 2: out = relu(in*a+c) @ W + b ----------------
__global__ __launch_bounds__(256) void k_tower2(
    const float* __restrict__ in, const float* __restrict__ aff,
    const float* __restrict__ W, const float* __restrict__ b,
    float* __restrict__ out, int N) {
    __shared__ __align__(16) float As_[64 * AS];
    __shared__ __align__(16) float Ws_[64 * WS];
    int t = threadIdx.x, tx = t & 15, ty = t >> 4;
    int rowBase = blockIdx.x * 64;

    loadA_bnrelu(in, aff, rowBase, N, As_);
    loadW(W, Ws_);
    __syncthreads();
    float acc[4][4] = {};
    mma64(As_, Ws_, ty, tx, acc);

    float4 bias = *(const float4*)(b + tx * 4);
#pragma unroll
    for (int i = 0; i < 4; i++) {
        int row = rowBase + ty * 4 + i;
        if (row < N) {
            *(float4*)(out + (size_t)row * 64 + tx * 4) =
                make_float4(acc[i][0] + bias.x, acc[i][1] + bias.y,
                            acc[i][2] + bias.z, acc[i][3] + bias.w);
        }
    }
}

// ================= mma.sync edge pass 1 =================
// y1 = (x_u[src] * x_v[dst]) @ Wuv1 + buv1 via bf16 hi/lo split HMMA
#define E1_SMEM 51200
#define OFF_AH 0
#define OFF_AL 17408
#define OFF_BH 34816
#define OFF_BL 43008
#define AROW 136   // bytes per A row (64 bf16 = 128B + 8B pad)

__device__ __forceinline__ void mma16816(float c[4], uint32_t a0, uint32_t a1,
                                         uint32_t a2, uint32_t a3,
                                         uint32_t b0, uint32_t b1) {
    asm volatile(
        "mma.sync.aligned.m16n8k16.row.col.f32.bf16.bf16.f32 "
        "{%0,%1,%2,%3}, {%4,%5,%6,%7}, {%8,%9}, {%0,%1,%2,%3};"
        : "+f"(c[0]), "+f"(c[1]), "+f"(c[2]), "+f"(c[3])
        : "r"(a0), "r"(a1), "r"(a2), "r"(a3), "r"(b0), "r"(b1));
}

__device__ __forceinline__ uint32_t pack_split(float x, float y, uint32_t& lo) {
    __nv_bfloat162 h = __floats2bfloat162_rn(x, y);
    float rx = x - __bfloat162float(h.x);
    float ry = y - __bfloat162float(h.y);
    __nv_bfloat162 l = __floats2bfloat162_rn(rx, ry);
    lo = *(const uint32_t*)&l;
    return *(const uint32_t*)&h;
}

__global__ __launch_bounds__(256)
void k_edge1_mma(const float* __restrict__ xu, const float* __restrict__ xv,
                 const int* __restrict__ es, const int* __restrict__ ed,
                 const float* __restrict__ b, float* __restrict__ out,
                 double* __restrict__ stats) {
    extern __shared__ __align__(16) char smem[];
    __shared__ float ssum[64], ssq[64];
    int t = threadIdx.x, lane = t & 31, w = t >> 5;
    int rowBase = blockIdx.x * 128;
    if (t < 64) { ssum[t] = 0.f; ssq[t] = 0.f; }

    // ---- B fragments (hi/lo): coalesced copy ----
    {
        const uint4* sH = (const uint4*)g_fragH;
        const uint4* sL = (const uint4*)g_fragL;
        uint4* dH = (uint4*)(smem + OFF_BH);
        uint4* dL = (uint4*)(smem + OFF_BL);
        dH[t] = __ldg(sH + t);
        dH[t + 256] = __ldg(sH + t + 256);
        dL[t] = __ldg(sL + t);
        dL[t + 256] = __ldg(sL + t + 256);
    }
    // ---- A: gather x_u*x_v, bf16 hi/lo split ----
    {
        int r = t >> 1, h = t & 1;
        int e = rowBase + r;
        char* aH = smem + OFF_AH + r * AROW + h * 64;
        char* aL = smem + OFF_AL + r * AROW + h * 64;
        if (e < ERc) {
            int s = __ldg(es + e), d = __ldg(ed + e);
            const float4* pu = (const float4*)(xu + (size_t)s * 64) + h * 8;
            const float4* pv = (const float4*)(xv + (size_t)d * 64) + h * 8;
#pragma unroll
            for (int j = 0; j < 8; j++) {
                float4 a = __ldg(pu + j), v = __ldg(pv + j);
                uint32_t lo01, lo23;
                uint32_t hi01 = pack_split(a.x * v.x, a.y * v.y, lo01);
                uint32_t hi23 = pack_split(a.z * v.z, a.w * v.w, lo23);
                *(uint2*)(aH + j * 8) = make_uint2(hi01, hi23);
                *(uint2*)(aL + j * 8) = make_uint2(lo01, lo23);
            }
        } else {
#pragma unroll
            for (int j = 0; j < 8; j++) {
                *(uint2*)(aH + j * 8) = make_uint2(0u, 0u);
                *(uint2*)(aL + j * 8) = make_uint2(0u, 0u);
            }
        }
    }
    __syncthreads();

    // ---- mma mainloop: D = AhiBhi + AhiBlo + AloBhi ----
    int g = lane >> 2, tig = lane & 3;
    int r0 = w * 16 + g;
    float acc[8][4] = {};
    const char* AH = smem + OFF_AH;
    const char* AL = smem + OFF_AL;
#pragma unroll
    for (int kt = 0; kt < 4; kt++) {
        int ka = kt * 32 + tig * 4;
        uint32_t aH0 = *(const uint32_t*)(AH + r0 * AROW + ka);
        uint32_t aH1 = *(const uint32_t*)(AH + (r0 + 8) * AROW + ka);
        uint32_t aH2 = *(const uint32_t*)(AH + r0 * AROW + ka + 16);
        uint32_t aH3 = *(const uint32_t*)(AH + (r0 + 8) * AROW + ka + 16);
        uint32_t aL0 = *(const uint32_t*)(AL + r0 * AROW + ka);
        uint32_t aL1 = *(const uint32_t*)(AL + (r0 + 8) * AROW + ka);
        uint32_t aL2 = *(const uint32_t*)(AL + r0 * AROW + ka + 16);
        uint32_t aL3 = *(const uint32_t*)(AL + (r0 + 8) * AROW + ka + 16);
#pragma unroll
        for (int nt = 0; nt < 8; nt++) {
            uint32_t boff = ((kt * 8 + nt) * 64 + lane * 2) * 4;
            uint2 bH = *(const uint2*)(smem + OFF_BH + boff);
            uint2 bL = *(const uint2*)(smem + OFF_BL + boff);
            mma16816(acc[nt], aH0, aH1, aH2, aH3, bH.x, bH.y);
            mma16816(acc[nt], aH0, aH1, aH2, aH3, bL.x, bL.y);
            mma16816(acc[nt], aL0, aL1, aL2, aL3, bH.x, bH.y);
        }
    }
    __syncthreads();

    // ---- stage C to smem (stride-65 f32) ----
    float* stage = (float*)smem;
#pragma unroll
    for (int nt = 0; nt < 8; nt++) {
        int c = nt * 8 + tig * 2;
        stage[r0 * 65 + c] = acc[nt][0];
        stage[r0 * 65 + c + 1] = acc[nt][1];
        stage[(r0 + 8) * 65 + c] = acc[nt][2];
        stage[(r0 + 8) * 65 + c + 1] = acc[nt][3];
    }
    __syncthreads();

    // ---- coalesced store + bias + stats ----
    int c4 = (t & 15) * 4;
    float4 bias = *(const float4*)(b + c4);
    float cs[4] = {0, 0, 0, 0}, cq[4] = {0, 0, 0, 0};
#pragma unroll
    for (int i = 0; i < 8; i++) {
        int r = (t >> 4) + 16 * i;
        int e = rowBase + r;
        if (e < ERc) {
            const float* sp = stage + r * 65 + c4;
            float v0 = sp[0] + bias.x, v1 = sp[1] + bias.y;
            float v2 = sp[2] + bias.z, v3 = sp[3] + bias.w;
            *(float4*)(out + (size_t)e * 64 + c4) = make_float4(v0, v1, v2, v3);
            cs[0] += v0; cq[0] += v0 * v0;
            cs[1] += v1; cq[1] += v1 * v1;
            cs[2] += v2; cq[2] += v2 * v2;
            cs[3] += v3; cq[3] += v3 * v3;
        }
    }
#pragma unroll
    for (int j = 0; j < 4; j++) {
        atomicAdd(&ssum[c4 + j], cs[j]);
        atomicAdd(&ssq[c4 + j], cq[j]);
    }
    __syncthreads();
    if (t < 64) atomicAdd(&stats[t], (double)ssum[t]);
    else if (t < 128) atomicAdd(&stats[t], (double)ssq[t - 64]);
}

// ================= edge pass 2 on tensor cores =================
// y2 = relu(y1*a1+c1) @ Wuv2 + buv2; y1 read directly into A-fragments.
// 128 edges/block, 8 warps; fragment-domain BN+relu+split (proven in R8's k_eB).
__global__ __launch_bounds__(256)
void k_edge2_mma(const float* __restrict__ y1, const float* __restrict__ aff,
                 const float* __restrict__ b2, float* __restrict__ y2,
                 double* __restrict__ stats) {
    __shared__ float affS[128];
    __shared__ __align__(16) uint32_t f2H[512], f2L[512];
    __shared__ float ssum[16], ssq[16];
    int t = threadIdx.x, lane = t & 31, w = t >> 5;
    int rowBase = blockIdx.x * 128;
    if (t < 128) affS[t] = __ldg(aff + t);
    if (t < 16) { ssum[t] = 0.f; ssq[t] = 0.f; }
    {   // Wuv2 fragments to smem
        ((uint2*)f2H)[t] = __ldg((const uint2*)g_frag2H + t);
        ((uint2*)f2L)[t] = __ldg((const uint2*)g_frag2L + t);
    }
    __syncthreads();

    int g = lane >> 2, tig = lane & 3;
    int r0 = w * 16 + g;
    int e0 = rowBase + r0, e1 = e0 + 8;
    bool ok0 = e0 < ERc, ok1 = e1 < ERc;

    float acc2[2][4] = {};
#pragma unroll
    for (int kt = 0; kt < 4; kt++) {
        int c0 = kt * 16 + tig * 2;
        float2 z = make_float2(0.f, 0.f);
        float2 y00 = ok0 ? *(const float2*)(y1 + (size_t)e0 * 64 + c0) : z;
        float2 y10 = ok1 ? *(const float2*)(y1 + (size_t)e1 * 64 + c0) : z;
        float2 y01 = ok0 ? *(const float2*)(y1 + (size_t)e0 * 64 + c0 + 8) : z;
        float2 y11 = ok1 ? *(const float2*)(y1 + (size_t)e1 * 64 + c0 + 8) : z;
        float s0 = affS[c0], h0 = affS[64 + c0];
        float s1 = affS[c0 + 1], h1 = affS[64 + c0 + 1];
        float s2 = affS[c0 + 8], h2 = affS[64 + c0 + 8];
        float s3 = affS[c0 + 9], h3 = affS[64 + c0 + 9];
        float v00 = fmaxf(y00.x * s0 + h0, 0.f);
        float v01 = fmaxf(y00.y * s1 + h1, 0.f);
        float v10 = fmaxf(y10.x * s0 + h0, 0.f);
        float v11 = fmaxf(y10.y * s1 + h1, 0.f);
        float w00 = fmaxf(y01.x * s2 + h2, 0.f);
        float w01 = fmaxf(y01.y * s3 + h3, 0.f);
        float w10 = fmaxf(y11.x * s2 + h2, 0.f);
        float w11 = fmaxf(y11.y * s3 + h3, 0.f);
        uint32_t l0, l1, l2, l3;
        uint32_t a0 = pack_split(v00, v01, l0);
        uint32_t a1 = pack_split(v10, v11, l1);
        uint32_t a2 = pack_split(w00, w01, l2);
        uint32_t a3 = pack_split(w10, w11, l3);
#pragma unroll
        for (int n2 = 0; n2 < 2; n2++) {
            int fo = (kt * 2 + n2) * 64 + lane * 2;
            uint2 bH = *(const uint2*)(f2H + fo);
            uint2 bL = *(const uint2*)(f2L + fo);
            mma16816(acc2[n2], a0, a1, a2, a3, bH.x, bH.y);
            mma16816(acc2[n2], a0, a1, a2, a3, bL.x, bL.y);
            mma16816(acc2[n2], l0, l1, l2, l3, bH.x, bH.y);
        }
    }

    // epilogue: bias2, write y2 (fragment layout -> [e][16]), stats2
    float cs[4] = {0, 0, 0, 0}, cq[4] = {0, 0, 0, 0};
#pragma unroll
    for (int n2 = 0; n2 < 2; n2++) {
        int c = n2 * 8 + tig * 2;
        float bx = __ldg(b2 + c), by = __ldg(b2 + c + 1);
        float u0 = acc2[n2][0] + bx, u1 = acc2[n2][1] + by;
        float u2 = acc2[n2][2] + bx, u3 = acc2[n2][3] + by;
        if (ok0) {
            *(float2*)(y2 + (size_t)e0 * 16 + c) = make_float2(u0, u1);
            cs[n2 * 2] += u0; cq[n2 * 2] += u0 * u0;
            cs[n2 * 2 + 1] += u1; cq[n2 * 2 + 1] += u1 * u1;
        }
        if (ok1) {
            *(float2*)(y2 + (size_t)e1 * 16 + c) = make_float2(u2, u3);
            cs[n2 * 2] += u2; cq[n2 * 2] += u2 * u2;
            cs[n2 * 2 + 1] += u3; cq[n2 * 2 + 1] += u3 * u3;
        }
    }
#pragma unroll
    for (int n2 = 0; n2 < 2; n2++) {
#pragma unroll
        for (int j = 0; j < 2; j++) {
            int c = n2 * 8 + tig * 2 + j;
            atomicAdd(&ssum[c], cs[n2 * 2 + j]);
            atomicAdd(&ssq[c], cq[n2 * 2 + j]);
        }
    }
    __syncthreads();
    if (t < 16) atomicAdd(&stats[t], (double)ssum[t]);
    else if (t < 32) atomicAdd(&stats[t], (double)ssq[t - 16]);
}

// ---------------- edge pass 3: scores = relu(y2*a2+c2) . w3 + b3 ----------------
__global__ __launch_bounds__(256) void k_edge3(
    const float* __restrict__ y2, const float* __restrict__ aff,
    const float* __restrict__ w3, const float* __restrict__ b3,
    float* __restrict__ out) {
    int e = blockIdx.x * blockDim.x + threadIdx.x;
    if (e >= ERc) return;
    const float4* p = (const float4*)(y2 + (size_t)e * 16);
    float s = 0.f;
#pragma unroll
    for (int j = 0; j < 4; j++) {
        float4 v = __ldg(p + j);
        float4 a = *(const float4*)(aff + 4 * j);
        float4 c = *(const float4*)(aff + 16 + 4 * j);
        float4 w = *(const float4*)(w3 + 4 * j);
        s += fmaxf(v.x * a.x + c.x, 0.f) * w.x;
        s += fmaxf(v.y * a.y + c.y, 0.f) * w.y;
        s += fmaxf(v.z * a.z + c.z, 0.f) * w.z;
        s += fmaxf(v.w * a.w + c.w, 0.f) * w.w;
    }
    out[e] = s + __ldg(b3);
}

// ---------------- host ----------------
extern "C" void kernel_launch(void* const* d_in, const int* in_sizes, int n_in,
                              void* d_out, int out_size) {
    const float* u2e     = (const float*)d_in[0];
    const float* v2e     = (const float*)d_in[1];
    const float* W_self  = (const float*)d_in[2];
    const float* b_self  = (const float*)d_in[3];
    const float* W_neigh = (const float*)d_in[4];
    const float* Wur1 = (const float*)d_in[5];
    const float* bur1 = (const float*)d_in[6];
    const float* Wur2 = (const float*)d_in[7];
    const float* bur2 = (const float*)d_in[8];
    const float* Wvr1 = (const float*)d_in[9];
    const float* bvr1 = (const float*)d_in[10];
    const float* Wvr2 = (const float*)d_in[11];
    const float* bvr2 = (const float*)d_in[12];
    const float* Wuv1 = (const float*)d_in[13];
    const float* buv1 = (const float*)d_in[14];
    const float* Wuv2 = (const float*)d_in[15];
    const float* buv2 = (const float*)d_in[16];
    const float* Wuv3 = (const float*)d_in[17];
    const float* buv3 = (const float*)d_in[18];
    const float* bn_gamma  = (const float*)d_in[19];
    const float* bn_beta   = (const float*)d_in[20];
    const float* bn4_gamma = (const float*)d_in[21];
    const float* bn4_beta  = (const float*)d_in[22];
    const int* social_src = (const int*)d_in[23];
    const int* social_dst = (const int*)d_in[24];
    const int* rates_src  = (const int*)d_in[25];
    const int* rates_dst  = (const int*)d_in[26];
    float* out = (float*)d_out;

    void *p_ssoc, *p_sru, *p_srv, *p_degs, *p_degru, *p_degrv;
    void *p_tu, *p_tv, *p_xu, *p_xv, *p_y1, *p_y2;
    void *p_stU, *p_stV, *p_st1, *p_st2, *p_aU, *p_aV, *p_a1, *p_a2;
    cudaGetSymbolAddress(&p_ssoc, g_s_social);
    cudaGetSymbolAddress(&p_sru, g_s_ru);
    cudaGetSymbolAddress(&p_srv, g_s_rv);
    cudaGetSymbolAddress(&p_degs, g_deg_s);
    cudaGetSymbolAddress(&p_degru, g_deg_ru);
    cudaGetSymbolAddress(&p_degrv, g_deg_rv);
    cudaGetSymbolAddress(&p_tu, g_tu);
    cudaGetSymbolAddress(&p_tv, g_tv);
    cudaGetSymbolAddress(&p_xu, g_xu);
    cudaGetSymbolAddress(&p_xv, g_xv);
    cudaGetSymbolAddress(&p_y1, g_y1);
    cudaGetSymbolAddress(&p_y2, g_y2);
    cudaGetSymbolAddress(&p_stU, g_statU);
    cudaGetSymbolAddress(&p_stV, g_statV);
    cudaGetSymbolAddress(&p_st1, g_stat1);
    cudaGetSymbolAddress(&p_st2, g_stat2);
    cudaGetSymbolAddress(&p_aU, g_affU);
    cudaGetSymbolAddress(&p_aV, g_affV);
    cudaGetSymbolAddress(&p_a1, g_aff1);
    cudaGetSymbolAddress(&p_a2, g_aff2);

    cudaFuncSetAttribute(k_edge1_mma, cudaFuncAttributeMaxDynamicSharedMemorySize, E1_SMEM);

    const int NB_U = (NUc + 63) / 64;
    const int NB_V = (NVc + 63) / 64;
    const int NB_E1 = (ERc + 127) / 128;

    k_zero<<<2048, 256>>>();
    k_prepW<<<1, 256>>>(Wuv1, Wuv2);

    // segment sums: social (u->u) separate; both rates directions fused
    k_scatter<<<ESc / 16, 256>>>(u2e, social_src, social_dst,
                                 (float*)p_ssoc, (float*)p_degs, ESc);
    k_scatter2<<<ERc / 16, 256>>>(u2e, v2e, rates_src, rates_dst,
                                  (float*)p_srv, (float*)p_sru,
                                  (float*)p_degrv, (float*)p_degru);

    k_user1<<<NB_U, 256>>>(u2e, W_self, b_self, W_neigh, Wur1, bur1,
                           (float*)p_tu, (double*)p_stU);
    k_item1<<<NB_V, 256>>>(v2e, W_self, b_self, W_neigh, Wvr1, bvr1,
                           (float*)p_tv, (double*)p_stV);
    k_fin<<<1, 64>>>((const double*)p_stU, bn_gamma + 0, bn_beta + 0, (float*)p_aU, 64, 1.0f / NUc);
    k_fin<<<1, 64>>>((const double*)p_stV, bn_gamma + 64, bn_beta + 64, (float*)p_aV, 64, 1.0f / NVc);
    k_tower2<<<NB_U, 256>>>((const float*)p_tu, (const float*)p_aU, Wur2, bur2, (float*)p_xu, NUc);
    k_tower2<<<NB_V, 256>>>((const float*)p_tv, (const float*)p_aV, Wvr2, bvr2, (float*)p_xv, NVc);

    k_edge1_mma<<<NB_E1, 256, E1_SMEM>>>((const float*)p_xu, (const float*)p_xv,
                                         rates_src, rates_dst, buv1,
                                         (float*)p_y1, (double*)p_st1);
    k_fin<<<1, 64>>>((const double*)p_st1, bn_gamma + 128, bn_beta + 128, (float*)p_a1, 64, 1.0f / ERc);
    k_edge2_mma<<<NB_E1, 256>>>((const float*)p_y1, (const float*)p_a1, buv2,
                                (float*)p_y2, (double*)p_st2);
    k_fin<<<1, 16>>>((const double*)p_st2, bn4_gamma, bn4_beta, (float*)p_a2, 16, 1.0f / ERc);
    k_edge3<<<(ERc + 255) / 256, 256>>>((const float*)p_y2, (const float*)p_a2, Wuv3, buv3, out);

    (void)in_sizes; (void)n_in; (void)out_size;
}

// round 11
// speedup vs baseline: 1.2814x; 1.0435x over previous
#include <cuda_runtime.h>
#include <cuda_bf16.h>
#include <cstdint>

#define NUc 50000
#define NVc 50000
#define ESc 800000
#define ERc 1000000

// ---------------- device scratch (no allocations allowed) ----------------
__device__ __align__(16) float g_s_social[(size_t)NUc * 64];
__device__ __align__(16) float g_s_ru[(size_t)NUc * 64];
__device__ __align__(16) float g_s_rv[(size_t)NVc * 64];
__device__ float g_deg_s[NUc];
__device__ float g_deg_ru[NUc];
__device__ float g_deg_rv[NVc];
__device__ __align__(16) float g_tu[(size_t)NUc * 64];
__device__ __align__(16) float g_tv[(size_t)NVc * 64];
__device__ __align__(16) float g_xu[(size_t)NUc * 64];
__device__ __align__(16) float g_xv[(size_t)NVc * 64];
__device__ __align__(16) float g_y1[(size_t)ERc * 64];   // 256 MB
__device__ __align__(16) float g_y2[(size_t)ERc * 16];   // 64 MB
__device__ double g_statU[128];
__device__ double g_statV[128];
__device__ double g_stat1[128];
__device__ double g_stat2[32];
__device__ __align__(16) float g_affU[128];
__device__ __align__(16) float g_affV[128];
__device__ __align__(16) float g_aff1[128];
__device__ __align__(16) float g_aff2[32];
// Wuv1 pre-packed into per-lane m16n8k16 B-fragment order (hi/lo bf16 split)
__device__ __align__(16) uint32_t g_fragH[2048];
__device__ __align__(16) uint32_t g_fragL[2048];
// Wuv2 (64x16): (kt*2+nt)*64 + lane*2 + r
__device__ __align__(16) uint32_t g_frag2H[512];
__device__ __align__(16) uint32_t g_frag2L[512];
// 9 node matrices (64x64 each) in B-fragment order:
// 0:Wself0+Wself2  1:Wn0  2:Wn2  3:Wur1  4:Wself1  5:Wn1  6:Wvr1  7:Wur2  8:Wvr2
__device__ __align__(16) uint32_t g_nfH[9 * 2048];
__device__ __align__(16) uint32_t g_nfL[9 * 2048];

// ---------------- common mma helpers ----------------
__device__ __forceinline__ void mma16816(float c[4], uint32_t a0, uint32_t a1,
                                         uint32_t a2, uint32_t a3,
                                         uint32_t b0, uint32_t b1) {
    asm volatile(
        "mma.sync.aligned.m16n8k16.row.col.f32.bf16.bf16.f32 "
        "{%0,%1,%2,%3}, {%4,%5,%6,%7}, {%8,%9}, {%0,%1,%2,%3};"
        : "+f"(c[0]), "+f"(c[1]), "+f"(c[2]), "+f"(c[3])
        : "r"(a0), "r"(a1), "r"(a2), "r"(a3), "r"(b0), "r"(b1));
}

__device__ __forceinline__ uint32_t pack_split(float x, float y, uint32_t& lo) {
    __nv_bfloat162 h = __floats2bfloat162_rn(x, y);
    float rx = x - __bfloat162float(h.x);
    float ry = y - __bfloat162float(h.y);
    __nv_bfloat162 l = __floats2bfloat162_rn(rx, ry);
    lo = *(const uint32_t*)&l;
    return *(const uint32_t*)&h;
}

#define AROW 136   // bytes per A row (64 bf16 = 128B + 8B pad)
#define OFF_AH 0
#define OFF_AL 17408

// stage a [128 x 64] f32 tile (optionally scaled by 1/deg) into smem as bf16 hi/lo
__device__ __forceinline__ void stageA(char* smem, const float* __restrict__ src,
                                       const float* __restrict__ deg,
                                       int rowBase, int N, int t) {
    int r = t >> 1, h = t & 1;
    int row = rowBase + r;
    char* aH = smem + OFF_AH + r * AROW + h * 64;
    char* aL = smem + OFF_AL + r * AROW + h * 64;
    if (row < N) {
        float sc = deg ? (1.f / fmaxf(__ldg(deg + row), 1.f)) : 1.f;
        const float4* pu = (const float4*)(src + (size_t)row * 64) + h * 8;
#pragma unroll
        for (int j = 0; j < 8; j++) {
            float4 a = __ldg(pu + j);
            uint32_t lo01, lo23;
            uint32_t hi01 = pack_split(a.x * sc, a.y * sc, lo01);
            uint32_t hi23 = pack_split(a.z * sc, a.w * sc, lo23);
            *(uint2*)(aH + j * 8) = make_uint2(hi01, hi23);
            *(uint2*)(aL + j * 8) = make_uint2(lo01, lo23);
        }
    } else {
#pragma unroll
        for (int j = 0; j < 8; j++) {
            *(uint2*)(aH + j * 8) = make_uint2(0u, 0u);
            *(uint2*)(aL + j * 8) = make_uint2(0u, 0u);
        }
    }
}

// acc += A(smem) @ W(frags in global, 8 n-tiles), 3-term bf16 split
__device__ __forceinline__ void mma_AB(const char* smem,
                                       const uint32_t* __restrict__ fH,
                                       const uint32_t* __restrict__ fL,
                                       int r0, int tig, int lane, float acc[8][4]) {
    const char* AH = smem + OFF_AH;
    const char* AL = smem + OFF_AL;
#pragma unroll
    for (int kt = 0; kt < 4; kt++) {
        int ka = kt * 32 + tig * 4;
        uint32_t aH0 = *(const uint32_t*)(AH + r0 * AROW + ka);
        uint32_t aH1 = *(const uint32_t*)(AH + (r0 + 8) * AROW + ka);
        uint32_t aH2 = *(const uint32_t*)(AH + r0 * AROW + ka + 16);
        uint32_t aH3 = *(const uint32_t*)(AH + (r0 + 8) * AROW + ka + 16);
        uint32_t aL0 = *(const uint32_t*)(AL + r0 * AROW + ka);
        uint32_t aL1 = *(const uint32_t*)(AL + (r0 + 8) * AROW + ka);
        uint32_t aL2 = *(const uint32_t*)(AL + r0 * AROW + ka + 16);
        uint32_t aL3 = *(const uint32_t*)(AL + (r0 + 8) * AROW + ka + 16);
#pragma unroll
        for (int nt = 0; nt < 8; nt++) {
            int fo = (kt * 8 + nt) * 64 + lane * 2;
            uint2 bH = __ldg((const uint2*)(fH + fo));
            uint2 bL = __ldg((const uint2*)(fL + fo));
            mma16816(acc[nt], aH0, aH1, aH2, aH3, bH.x, bH.y);
            mma16816(acc[nt], aH0, aH1, aH2, aH3, bL.x, bL.y);
            mma16816(acc[nt], aL0, aL1, aL2, aL3, bH.x, bH.y);
        }
    }
}

// acc2 += (acc + bias[col]) @ W(frags), with C->A fragment identity mapping
__device__ __forceinline__ void frag_gemm64(const float acc[8][4],
                                            const float* __restrict__ biasS,
                                            const uint32_t* __restrict__ fH,
                                            const uint32_t* __restrict__ fL,
                                            int tig, int lane, float acc2[8][4]) {
#pragma unroll
    for (int kt = 0; kt < 4; kt++) {
        int c0 = kt * 16 + tig * 2;
        float b00 = biasS[c0], b01 = biasS[c0 + 1];
        float b02 = biasS[c0 + 8], b03 = biasS[c0 + 9];
        uint32_t l0, l1, l2, l3;
        uint32_t a0 = pack_split(acc[2 * kt][0] + b00, acc[2 * kt][1] + b01, l0);
        uint32_t a1 = pack_split(acc[2 * kt][2] + b00, acc[2 * kt][3] + b01, l1);
        uint32_t a2 = pack_split(acc[2 * kt + 1][0] + b02, acc[2 * kt + 1][1] + b03, l2);
        uint32_t a3 = pack_split(acc[2 * kt + 1][2] + b02, acc[2 * kt + 1][3] + b03, l3);
#pragma unroll
        for (int nt = 0; nt < 8; nt++) {
            int fo = (kt * 8 + nt) * 64 + lane * 2;
            uint2 bH = __ldg((const uint2*)(fH + fo));
            uint2 bL = __ldg((const uint2*)(fL + fo));
            mma16816(acc2[nt], a0, a1, a2, a3, bH.x, bH.y);
            mma16816(acc2[nt], a0, a1, a2, a3, bL.x, bL.y);
            mma16816(acc2[nt], l0, l1, l2, l3, bH.x, bH.y);
        }
    }
}

// ---------------- zero scratch ----------------
__global__ void k_zero() {
    size_t tid = (size_t)blockIdx.x * blockDim.x + threadIdx.x;
    size_t stride = (size_t)gridDim.x * blockDim.x;
    const size_t n4 = (size_t)NUc * 16;
    float4 z = make_float4(0.f, 0.f, 0.f, 0.f);
    for (size_t j = tid; j < n4; j += stride) {
        ((float4*)g_s_social)[j] = z;
        ((float4*)g_s_ru)[j] = z;
        ((float4*)g_s_rv)[j] = z;
    }
    for (size_t j = tid; j < NUc; j += stride) {
        g_deg_s[j] = 0.f;
        g_deg_ru[j] = 0.f;
        g_deg_rv[j] = 0.f;
    }
    if (tid < 128) { g_statU[tid] = 0.0; g_statV[tid] = 0.0; g_stat1[tid] = 0.0; }
    if (tid < 32) g_stat2[tid] = 0.0;
}

// ---------------- prep: edge weight fragments (Wuv1, Wuv2) ----------------
__global__ void k_prepW(const float* __restrict__ W1, const float* __restrict__ W2) {
    int t = threadIdx.x;
    for (int idx = t; idx < 2048; idx += 256) {
        int r = idx & 1;
        int lane = (idx >> 1) & 31;
        int grp = idx >> 6;
        int kt = grp >> 3, nt = grp & 7;
        int g = lane >> 2, tig = lane & 3;
        int n = nt * 8 + g;
        int k0 = kt * 16 + 2 * tig + (r ? 8 : 0);
        uint32_t lo;
        uint32_t hi = pack_split(__ldg(W1 + k0 * 64 + n), __ldg(W1 + (k0 + 1) * 64 + n), lo);
        g_fragH[idx] = hi;
        g_fragL[idx] = lo;
    }
    for (int idx = t; idx < 512; idx += 256) {
        int r = idx & 1;
        int lane = (idx >> 1) & 31;
        int grp = idx >> 6;
        int kt = grp >> 1, nt = grp & 1;
        int g = lane >> 2, tig = lane & 3;
        int n = nt * 8 + g;
        int k0 = kt * 16 + 2 * tig + (r ? 8 : 0);
        uint32_t lo;
        uint32_t hi = pack_split(__ldg(W2 + k0 * 16 + n), __ldg(W2 + (k0 + 1) * 16 + n), lo);
        g_frag2H[idx] = hi;
        g_frag2L[idx] = lo;
    }
}

// ---------------- prep: 9 node weight matrices into fragments ----------------
__global__ void k_prepN(const float* __restrict__ Ws, const float* __restrict__ Wn,
                        const float* __restrict__ Wur1_, const float* __restrict__ Wvr1_,
                        const float* __restrict__ Wur2_, const float* __restrict__ Wvr2_) {
    int t = blockIdx.x * blockDim.x + threadIdx.x;
    if (t >= 2048) return;
    int r = t & 1;
    int lane = (t >> 1) & 31;
    int grp = t >> 6;
    int kt = grp >> 3, nt = grp & 7;
    int g = lane >> 2, tig = lane & 3;
    int n = nt * 8 + g;
    int k0 = kt * 16 + 2 * tig + (r ? 8 : 0);
    const float* base[9] = {nullptr, Wn, Wn + 2 * 4096, Wur1_, Ws + 4096,
                            Wn + 4096, Wvr1_, Wur2_, Wvr2_};
#pragma unroll
    for (int m = 0; m < 9; m++) {
        float w0, w1;
        if (m == 0) {
            w0 = __ldg(Ws + k0 * 64 + n) + __ldg(Ws + 2 * 4096 + k0 * 64 + n);
            w1 = __ldg(Ws + (k0 + 1) * 64 + n) + __ldg(Ws + 2 * 4096 + (k0 + 1) * 64 + n);
        } else {
            const float* W = base[m];
            w0 = __ldg(W + k0 * 64 + n);
            w1 = __ldg(W + (k0 + 1) * 64 + n);
        }
        uint32_t lo;
        uint32_t hi = pack_split(w0, w1, lo);
        g_nfH[m * 2048 + t] = hi;
        g_nfL[m * 2048 + t] = lo;
    }
}

// ---------------- social scatter: acc[dst] += feat[src] via red.v4 ----------------
__global__ __launch_bounds__(256) void k_scatter(
    const float* __restrict__ feat, const int* __restrict__ src,
    const int* __restrict__ dst, float* __restrict__ acc,
    float* __restrict__ deg, int E) {
    int g = blockIdx.x * blockDim.x + threadIdx.x;
    int e = g >> 4;
    int q = g & 15;
    if (e >= E) return;
    int s = __ldg(src + e);
    int d = __ldg(dst + e);
    float4 v = __ldg((const float4*)feat + (size_t)s * 16 + q);
    float* p = acc + (size_t)d * 64 + q * 4;
    asm volatile("red.global.add.v4.f32 [%0], {%1, %2, %3, %4};"
                 :: "l"(p), "f"(v.x), "f"(v.y), "f"(v.z), "f"(v.w) : "memory");
    if (q == 0) atomicAdd(deg + d, 1.0f);
}

// ---------------- fused rates scatter: both directions, one index read ----------------
__global__ __launch_bounds__(256) void k_scatter2(
    const float* __restrict__ u2e, const float* __restrict__ v2e,
    const int* __restrict__ rs, const int* __restrict__ rd,
    float* __restrict__ s_rv, float* __restrict__ s_ru,
    float* __restrict__ deg_rv, float* __restrict__ deg_ru) {
    int g = blockIdx.x * blockDim.x + threadIdx.x;
    int e = g >> 4;
    int q = g & 15;
    if (e >= ERc) return;
    int s = __ldg(rs + e);
    int d = __ldg(rd + e);
    float4 a = __ldg((const float4*)u2e + (size_t)s * 16 + q);
    float4 b = __ldg((const float4*)v2e + (size_t)d * 16 + q);
    float* p1 = s_rv + (size_t)d * 64 + q * 4;
    float* p2 = s_ru + (size_t)s * 64 + q * 4;
    asm volatile("red.global.add.v4.f32 [%0], {%1, %2, %3, %4};"
                 :: "l"(p1), "f"(a.x), "f"(a.y), "f"(a.z), "f"(a.w) : "memory");
    asm volatile("red.global.add.v4.f32 [%0], {%1, %2, %3, %4};"
                 :: "l"(p2), "f"(b.x), "f"(b.y), "f"(b.z), "f"(b.w) : "memory");
    if (q == 0) {
        atomicAdd(deg_rv + d, 1.0f);
        atomicAdd(deg_ru + s, 1.0f);
    }
}

// ---------------- fused user: combine (3 tensor GEMMs) + tower1 (frag GEMM) + stats ----------------
__global__ __launch_bounds__(256)
void k_user1_mma(const float* __restrict__ u2e, const float* __restrict__ bself,
                 const float* __restrict__ b1, float* __restrict__ out,
                 double* __restrict__ stats) {
    __shared__ __align__(16) char smem[34816];
    __shared__ float biasS[64];
    __shared__ float ssum[64], ssq[64];
    int t = threadIdx.x, lane = t & 31, w = t >> 5;
    int g = lane >> 2, tig = lane & 3;
    int r0 = w * 16 + g;
    int rowBase = blockIdx.x * 128;
    if (t < 64) {
        biasS[t] = __ldg(bself + t) + __ldg(bself + 128 + t);
        ssum[t] = 0.f;
        ssq[t] = 0.f;
    }

    float acc[8][4] = {};
    stageA(smem, u2e, nullptr, rowBase, NUc, t);
    __syncthreads();
    mma_AB(smem, g_nfH + 0 * 2048, g_nfL + 0 * 2048, r0, tig, lane, acc);
    __syncthreads();
    stageA(smem, g_s_social, g_deg_s, rowBase, NUc, t);
    __syncthreads();
    mma_AB(smem, g_nfH + 1 * 2048, g_nfL + 1 * 2048, r0, tig, lane, acc);
    __syncthreads();
    stageA(smem, g_s_ru, g_deg_ru, rowBase, NUc, t);
    __syncthreads();
    mma_AB(smem, g_nfH + 2 * 2048, g_nfL + 2 * 2048, r0, tig, lane, acc);
    __syncthreads();

    float acc2[8][4] = {};
    frag_gemm64(acc, biasS, g_nfH + 3 * 2048, g_nfL + 3 * 2048, tig, lane, acc2);

    float* stage = (float*)smem;
#pragma unroll
    for (int nt = 0; nt < 8; nt++) {
        int c = nt * 8 + tig * 2;
        stage[r0 * 65 + c] = acc2[nt][0];
        stage[r0 * 65 + c + 1] = acc2[nt][1];
        stage[(r0 + 8) * 65 + c] = acc2[nt][2];
        stage[(r0 + 8) * 65 + c + 1] = acc2[nt][3];
    }
    __syncthreads();

    int c4 = (t & 15) * 4;
    float4 bias = *(const float4*)(b1 + c4);
    float cs[4] = {0, 0, 0, 0}, cq[4] = {0, 0, 0, 0};
#pragma unroll
    for (int i = 0; i < 8; i++) {
        int r = (t >> 4) + 16 * i;
        int row = rowBase + r;
        if (row < NUc) {
            const float* sp = stage + r * 65 + c4;
            float v0 = sp[0] + bias.x, v1 = sp[1] + bias.y;
            float v2 = sp[2] + bias.z, v3 = sp[3] + bias.w;
            *(float4*)(out + (size_t)row * 64 + c4) = make_float4(v0, v1, v2, v3);
            cs[0] += v0; cq[0] += v0 * v0;
            cs[1] += v1; cq[1] += v1 * v1;
            cs[2] += v2; cq[2] += v2 * v2;
            cs[3] += v3; cq[3] += v3 * v3;
        }
    }
#pragma unroll
    for (int j = 0; j < 4; j++) {
        atomicAdd(&ssum[c4 + j], cs[j]);
        atomicAdd(&ssq[c4 + j], cq[j]);
    }
    __syncthreads();
    if (t < 64) atomicAdd(&stats[t], (double)ssum[t]);
    else if (t < 128) atomicAdd(&stats[t], (double)ssq[t - 64]);
}

// ---------------- fused item: combine (2 tensor GEMMs) + tower1 + stats ----------------
__global__ __launch_bounds__(256)
void k_item1_mma(const float* __restrict__ v2e, const float* __restrict__ bself,
                 const float* __restrict__ b1, float* __restrict__ out,
                 double* __restrict__ stats) {
    __shared__ __align__(16) char smem[34816];
    __shared__ float biasS[64];
    __shared__ float ssum[64], ssq[64];
    int t = threadIdx.x, lane = t & 31, w = t >> 5;
    int g = lane >> 2, tig = lane & 3;
    int r0 = w * 16 + g;
    int rowBase = blockIdx.x * 128;
    if (t < 64) {
        biasS[t] = __ldg(bself + 64 + t);
        ssum[t] = 0.f;
        ssq[t] = 0.f;
    }

    float acc[8][4] = {};
    stageA(smem, v2e, nullptr, rowBase, NVc, t);
    __syncthreads();
    mma_AB(smem, g_nfH + 4 * 2048, g_nfL + 4 * 2048, r0, tig, lane, acc);
    __syncthreads();
    stageA(smem, g_s_rv, g_deg_rv, rowBase, NVc, t);
    __syncthreads();
    mma_AB(smem, g_nfH + 5 * 2048, g_nfL + 5 * 2048, r0, tig, lane, acc);
    __syncthreads();

    float acc2[8][4] = {};
    frag_gemm64(acc, biasS, g_nfH + 6 * 2048, g_nfL + 6 * 2048, tig, lane, acc2);

    float* stage = (float*)smem;
#pragma unroll
    for (int nt = 0; nt < 8; nt++) {
        int c = nt * 8 + tig * 2;
        stage[r0 * 65 + c] = acc2[nt][0];
        stage[r0 * 65 + c + 1] = acc2[nt][1];
        stage[(r0 + 8) * 65 + c] = acc2[nt][2];
        stage[(r0 + 8) * 65 + c + 1] = acc2[nt][3];
    }
    __syncthreads();

    int c4 = (t & 15) * 4;
    float4 bias = *(const float4*)(b1 + c4);
    float cs[4] = {0, 0, 0, 0}, cq[4] = {0, 0, 0, 0};
#pragma unroll
    for (int i = 0; i < 8; i++) {
        int r = (t >> 4) + 16 * i;
        int row = rowBase + r;
        if (row < NVc) {
            const float* sp = stage + r * 65 + c4;
            float v0 = sp[0] + bias.x, v1 = sp[1] + bias.y;
            float v2 = sp[2] + bias.z, v3 = sp[3] + bias.w;
            *(float4*)(out + (size_t)row * 64 + c4) = make_float4(v0, v1, v2, v3);
            cs[0] += v0; cq[0] += v0 * v0;
            cs[1] += v1; cq[1] += v1 * v1;
            cs[2] += v2; cq[2] += v2 * v2;
            cs[3] += v3; cq[3] += v3 * v3;
        }
    }
#pragma unroll
    for (int j = 0; j < 4; j++) {
        atomicAdd(&ssum[c4 + j], cs[j]);
        atomicAdd(&ssq[c4 + j], cq[j]);
    }
    __syncthreads();
    if (t < 64) atomicAdd(&stats[t], (double)ssum[t]);
    else if (t < 128) atomicAdd(&stats[t], (double)ssq[t - 64]);
}

// ---------------- BN finalize ----------------
__global__ void k_fin(const double* __restrict__ stats, const float* __restrict__ gamma,
                      const float* __restrict__ beta, float* __restrict__ aff,
                      int C, float invN) {
    int c = threadIdx.x;
    if (c < C) {
        float mean = (float)(stats[c] * (double)invN);
        float ex2 = (float)(stats[C + c] * (double)invN);
        float var = ex2 - mean * mean;
        float a = gamma[c] * rsqrtf(var + 1e-5f);
        aff[c] = a;
        aff[C + c] = beta[c] - mean * a;
    }
}

// ---------------- tower2 on tensor cores: x = relu(t*a+c) @ W2 + b2 ----------------
__global__ __launch_bounds__(256)
void k_tower2_mma(const float* __restrict__ in, const float* __restrict__ aff,
                  const uint32_t* __restrict__ fH, const uint32_t* __restrict__ fL,
                  const float* __restrict__ b2, float* __restrict__ out, int N) {
    __shared__ float stage[128 * 65];
    __shared__ float affS[128];
    int t = threadIdx.x, lane = t & 31, w = t >> 5;
    int g = lane >> 2, tig = lane & 3;
    int r0 = w * 16 + g;
    int rowBase = blockIdx.x * 128;
    if (t < 128) affS[t] = __ldg(aff + t);
    __syncthreads();

    int e0 = rowBase + r0, e1 = e0 + 8;
    bool ok0 = e0 < N, ok1 = e1 < N;

    float acc2[8][4] = {};
#pragma unroll
    for (int kt = 0; kt < 4; kt++) {
        int c0 = kt * 16 + tig * 2;
        float2 z = make_float2(0.f, 0.f);
        float2 y00 = ok0 ? *(const float2*)(in + (size_t)e0 * 64 + c0) : z;       // row e0, cols c0
        float2 y10 = ok0 ? *(const float2*)(in + (size_t)e0 * 64 + c0 + 8) : z;   // row e0, cols c0+8
        float2 y01 = ok1 ? *(const float2*)(in + (size_t)e1 * 64 + c0) : z;       // row e1, cols c0
        float2 y11 = ok1 ? *(const float2*)(in + (size_t)e1 * 64 + c0 + 8) : z;   // row e1, cols c0+8
        float s0 = affS[c0], h0 = affS[64 + c0];
        float s1 = affS[c0 + 1], h1 = affS[64 + c0 + 1];
        float s2 = affS[c0 + 8], h2 = affS[64 + c0 + 8];
        float s3 = affS[c0 + 9], h3 = affS[64 + c0 + 9];
        float v00 = fmaxf(y00.x * s0 + h0, 0.f), v01 = fmaxf(y00.y * s1 + h1, 0.f);
        float v10 = fmaxf(y01.x * s0 + h0, 0.f), v11 = fmaxf(y01.y * s1 + h1, 0.f);
        float w00 = fmaxf(y10.x * s2 + h2, 0.f), w01 = fmaxf(y10.y * s3 + h3, 0.f);
        float w10 = fmaxf(y11.x * s2 + h2, 0.f), w11 = fmaxf(y11.y * s3 + h3, 0.f);
        uint32_t l0, l1, l2, l3;
        uint32_t a0 = pack_split(v00, v01, l0);
        uint32_t a1 = pack_split(v10, v11, l1);
        uint32_t a2 = pack_split(w00, w01, l2);
        uint32_t a3 = pack_split(w10, w11, l3);
#pragma unroll
        for (int nt = 0; nt < 8; nt++) {
            int fo = (kt * 8 + nt) * 64 + lane * 2;
            uint2 bH = __ldg((const uint2*)(fH + fo));
            uint2 bL = __ldg((const uint2*)(fL + fo));
            mma16816(acc2[nt], a0, a1, a2, a3, bH.x, bH.y);
            mma16816(acc2[nt], a0, a1, a2, a3, bL.x, bL.y);
            mma16816(acc2[nt], l0, l1, l2, l3, bH.x, bH.y);
        }
    }

#pragma unroll
    for (int nt = 0; nt < 8; nt++) {
        int c = nt * 8 + tig * 2;
        stage[r0 * 65 + c] = acc2[nt][0];
        stage[r0 * 65 + c + 1] = acc2[nt][1];
        stage[(r0 + 8) * 65 + c] = acc2[nt][2];
        stage[(r0 + 8) * 65 + c + 1] = acc2[nt][3];
    }
    __syncthreads();

    int c4 = (t & 15) * 4;
    float4 bias = *(const float4*)(b2 + c4);
#pragma unroll
    for (int i = 0; i < 8; i++) {
        int r = (t >> 4) + 16 * i;
        int row = rowBase + r;
        if (row < N) {
            const float* sp = stage + r * 65 + c4;
            *(float4*)(out + (size_t)row * 64 + c4) =
                make_float4(sp[0] + bias.x, sp[1] + bias.y, sp[2] + bias.z, sp[3] + bias.w);
        }
    }
}

// ================= mma.sync edge pass 1 (unchanged from 827us kernel) =================
#define E1_SMEM 51200
#define OFF_BH 34816
#define OFF_BL 43008

__global__ __launch_bounds__(256)
void k_edge1_mma(const float* __restrict__ xu, const float* __restrict__ xv,
                 const int* __restrict__ es, const int* __restrict__ ed,
                 const float* __restrict__ b, float* __restrict__ out,
                 double* __restrict__ stats) {
    extern __shared__ __align__(16) char smem[];
    __shared__ float ssum[64], ssq[64];
    int t = threadIdx.x, lane = t & 31, w = t >> 5;
    int rowBase = blockIdx.x * 128;
    if (t < 64) { ssum[t] = 0.f; ssq[t] = 0.f; }

    {
        const uint4* sH = (const uint4*)g_fragH;
        const uint4* sL = (const uint4*)g_fragL;
        uint4* dH = (uint4*)(smem + OFF_BH);
        uint4* dL = (uint4*)(smem + OFF_BL);
        dH[t] = __ldg(sH + t);
        dH[t + 256] = __ldg(sH + t + 256);
        dL[t] = __ldg(sL + t);
        dL[t + 256] = __ldg(sL + t + 256);
    }
    {
        int r = t >> 1, h = t & 1;
        int e = rowBase + r;
        char* aH = smem + OFF_AH + r * AROW + h * 64;
        char* aL = smem + OFF_AL + r * AROW + h * 64;
        if (e < ERc) {
            int s = __ldg(es + e), d = __ldg(ed + e);
            const float4* pu = (const float4*)(xu + (size_t)s * 64) + h * 8;
            const float4* pv = (const float4*)(xv + (size_t)d * 64) + h * 8;
#pragma unroll
            for (int j = 0; j < 8; j++) {
                float4 a = __ldg(pu + j), v = __ldg(pv + j);
                uint32_t lo01, lo23;
                uint32_t hi01 = pack_split(a.x * v.x, a.y * v.y, lo01);
                uint32_t hi23 = pack_split(a.z * v.z, a.w * v.w, lo23);
                *(uint2*)(aH + j * 8) = make_uint2(hi01, hi23);
                *(uint2*)(aL + j * 8) = make_uint2(lo01, lo23);
            }
        } else {
#pragma unroll
            for (int j = 0; j < 8; j++) {
                *(uint2*)(aH + j * 8) = make_uint2(0u, 0u);
                *(uint2*)(aL + j * 8) = make_uint2(0u, 0u);
            }
        }
    }
    __syncthreads();

    int g = lane >> 2, tig = lane & 3;
    int r0 = w * 16 + g;
    float acc[8][4] = {};
    const char* AH = smem + OFF_AH;
    const char* AL = smem + OFF_AL;
#pragma unroll
    for (int kt = 0; kt < 4; kt++) {
        int ka = kt * 32 + tig * 4;
        uint32_t aH0 = *(const uint32_t*)(AH + r0 * AROW + ka);
        uint32_t aH1 = *(const uint32_t*)(AH + (r0 + 8) * AROW + ka);
        uint32_t aH2 = *(const uint32_t*)(AH + r0 * AROW + ka + 16);
        uint32_t aH3 = *(const uint32_t*)(AH + (r0 + 8) * AROW + ka + 16);
        uint32_t aL0 = *(const uint32_t*)(AL + r0 * AROW + ka);
        uint32_t aL1 = *(const uint32_t*)(AL + (r0 + 8) * AROW + ka);
        uint32_t aL2 = *(const uint32_t*)(AL + r0 * AROW + ka + 16);
        uint32_t aL3 = *(const uint32_t*)(AL + (r0 + 8) * AROW + ka + 16);
#pragma unroll
        for (int nt = 0; nt < 8; nt++) {
            uint32_t boff = ((kt * 8 + nt) * 64 + lane * 2) * 4;
            uint2 bH = *(const uint2*)(smem + OFF_BH + boff);
            uint2 bL = *(const uint2*)(smem + OFF_BL + boff);
            mma16816(acc[nt], aH0, aH1, aH2, aH3, bH.x, bH.y);
            mma16816(acc[nt], aH0, aH1, aH2, aH3, bL.x, bL.y);
            mma16816(acc[nt], aL0, aL1, aL2, aL3, bH.x, bH.y);
        }
    }
    __syncthreads();

    float* stage = (float*)smem;
#pragma unroll
    for (int nt = 0; nt < 8; nt++) {
        int c = nt * 8 + tig * 2;
        stage[r0 * 65 + c] = acc[nt][0];
        stage[r0 * 65 + c + 1] = acc[nt][1];
        stage[(r0 + 8) * 65 + c] = acc[nt][2];
        stage[(r0 + 8) * 65 + c + 1] = acc[nt][3];
    }
    __syncthreads();

    int c4 = (t & 15) * 4;
    float4 bias = *(const float4*)(b + c4);
    float cs[4] = {0, 0, 0, 0}, cq[4] = {0, 0, 0, 0};
#pragma unroll
    for (int i = 0; i < 8; i++) {
        int r = (t >> 4) + 16 * i;
        int e = rowBase + r;
        if (e < ERc) {
            const float* sp = stage + r * 65 + c4;
            float v0 = sp[0] + bias.x, v1 = sp[1] + bias.y;
            float v2 = sp[2] + bias.z, v3 = sp[3] + bias.w;
            *(float4*)(out + (size_t)e * 64 + c4) = make_float4(v0, v1, v2, v3);
            cs[0] += v0; cq[0] += v0 * v0;
            cs[1] += v1; cq[1] += v1 * v1;
            cs[2] += v2; cq[2] += v2 * v2;
            cs[3] += v3; cq[3] += v3 * v3;
        }
    }
#pragma unroll
    for (int j = 0; j < 4; j++) {
        atomicAdd(&ssum[c4 + j], cs[j]);
        atomicAdd(&ssq[c4 + j], cq[j]);
    }
    __syncthreads();
    if (t < 64) atomicAdd(&stats[t], (double)ssum[t]);
    else if (t < 128) atomicAdd(&stats[t], (double)ssq[t - 64]);
}

// ================= edge pass 2 on tensor cores (unchanged) =================
__global__ __launch_bounds__(256)
void k_edge2_mma(const float* __restrict__ y1, const float* __restrict__ aff,
                 const float* __restrict__ b2, float* __restrict__ y2,
                 double* __restrict__ stats) {
    __shared__ float affS[128];
    __shared__ __align__(16) uint32_t f2H[512], f2L[512];
    __shared__ float ssum[16], ssq[16];
    int t = threadIdx.x, lane = t & 31, w = t >> 5;
    int rowBase = blockIdx.x * 128;
    if (t < 128) affS[t] = __ldg(aff + t);
    if (t < 16) { ssum[t] = 0.f; ssq[t] = 0.f; }
    {
        ((uint2*)f2H)[t] = __ldg((const uint2*)g_frag2H + t);
        ((uint2*)f2L)[t] = __ldg((const uint2*)g_frag2L + t);
    }
    __syncthreads();

    int g = lane >> 2, tig = lane & 3;
    int r0 = w * 16 + g;
    int e0 = rowBase + r0, e1 = e0 + 8;
    bool ok0 = e0 < ERc, ok1 = e1 < ERc;

    float acc2[2][4] = {};
#pragma unroll
    for (int kt = 0; kt < 4; kt++) {
        int c0 = kt * 16 + tig * 2;
        float2 z = make_float2(0.f, 0.f);
        float2 y00 = ok0 ? *(const float2*)(y1 + (size_t)e0 * 64 + c0) : z;
        float2 y10 = ok1 ? *(const float2*)(y1 + (size_t)e1 * 64 + c0) : z;
        float2 y01 = ok0 ? *(const float2*)(y1 + (size_t)e0 * 64 + c0 + 8) : z;
        float2 y11 = ok1 ? *(const float2*)(y1 + (size_t)e1 * 64 + c0 + 8) : z;
        float s0 = affS[c0], h0 = affS[64 + c0];
        float s1 = affS[c0 + 1], h1 = affS[64 + c0 + 1];
        float s2 = affS[c0 + 8], h2 = affS[64 + c0 + 8];
        float s3 = affS[c0 + 9], h3 = affS[64 + c0 + 9];
        float v00 = fmaxf(y00.x * s0 + h0, 0.f);
        float v01 = fmaxf(y00.y * s1 + h1, 0.f);
        float v10 = fmaxf(y10.x * s0 + h0, 0.f);
        float v11 = fmaxf(y10.y * s1 + h1, 0.f);
        float w00 = fmaxf(y01.x * s2 + h2, 0.f);
        float w01 = fmaxf(y01.y * s3 + h3, 0.f);
        float w10 = fmaxf(y11.x * s2 + h2, 0.f);
        float w11 = fmaxf(y11.y * s3 + h3, 0.f);
        uint32_t l0, l1, l2, l3;
        uint32_t a0 = pack_split(v00, v01, l0);
        uint32_t a1 = pack_split(v10, v11, l1);
        uint32_t a2 = pack_split(w00, w01, l2);
        uint32_t a3 = pack_split(w10, w11, l3);
#pragma unroll
        for (int n2 = 0; n2 < 2; n2++) {
            int fo = (kt * 2 + n2) * 64 + lane * 2;
            uint2 bH = *(const uint2*)(f2H + fo);
            uint2 bL = *(const uint2*)(f2L + fo);
            mma16816(acc2[n2], a0, a1, a2, a3, bH.x, bH.y);
            mma16816(acc2[n2], a0, a1, a2, a3, bL.x, bL.y);
            mma16816(acc2[n2], l0, l1, l2, l3, bH.x, bH.y);
        }
    }

    float cs[4] = {0, 0, 0, 0}, cq[4] = {0, 0, 0, 0};
#pragma unroll
    for (int n2 = 0; n2 < 2; n2++) {
        int c = n2 * 8 + tig * 2;
        float bx = __ldg(b2 + c), by = __ldg(b2 + c + 1);
        float u0 = acc2[n2][0] + bx, u1 = acc2[n2][1] + by;
        float u2 = acc2[n2][2] + bx, u3 = acc2[n2][3] + by;
        if (ok0) {
            *(float2*)(y2 + (size_t)e0 * 16 + c) = make_float2(u0, u1);
            cs[n2 * 2] += u0; cq[n2 * 2] += u0 * u0;
            cs[n2 * 2 + 1] += u1; cq[n2 * 2 + 1] += u1 * u1;
        }
        if (ok1) {
            *(float2*)(y2 + (size_t)e1 * 16 + c) = make_float2(u2, u3);
            cs[n2 * 2] += u2; cq[n2 * 2] += u2 * u2;
            cs[n2 * 2 + 1] += u3; cq[n2 * 2 + 1] += u3 * u3;
        }
    }
#pragma unroll
    for (int n2 = 0; n2 < 2; n2++) {
#pragma unroll
        for (int j = 0; j < 2; j++) {
            int c = n2 * 8 + tig * 2 + j;
            atomicAdd(&ssum[c], cs[n2 * 2 + j]);
            atomicAdd(&ssq[c], cq[n2 * 2 + j]);
        }
    }
    __syncthreads();
    if (t < 16) atomicAdd(&stats[t], (double)ssum[t]);
    else if (t < 32) atomicAdd(&stats[t], (double)ssq[t - 16]);
}

// ---------------- edge pass 3: scores = relu(y2*a2+c2) . w3 + b3 ----------------
__global__ __launch_bounds__(256) void k_edge3(
    const float* __restrict__ y2, const float* __restrict__ aff,
    const float* __restrict__ w3, const float* __restrict__ b3,
    float* __restrict__ out) {
    int e = blockIdx.x * blockDim.x + threadIdx.x;
    if (e >= ERc) return;
    const float4* p = (const float4*)(y2 + (size_t)e * 16);
    float s = 0.f;
#pragma unroll
    for (int j = 0; j < 4; j++) {
        float4 v = __ldg(p + j);
        float4 a = *(const float4*)(aff + 4 * j);
        float4 c = *(const float4*)(aff + 16 + 4 * j);
        float4 w = *(const float4*)(w3 + 4 * j);
        s += fmaxf(v.x * a.x + c.x, 0.f) * w.x;
        s += fmaxf(v.y * a.y + c.y, 0.f) * w.y;
        s += fmaxf(v.z * a.z + c.z, 0.f) * w.z;
        s += fmaxf(v.w * a.w + c.w, 0.f) * w.w;
    }
    out[e] = s + __ldg(b3);
}

// ---------------- host ----------------
extern "C" void kernel_launch(void* const* d_in, const int* in_sizes, int n_in,
                              void* d_out, int out_size) {
    const float* u2e     = (const float*)d_in[0];
    const float* v2e     = (const float*)d_in[1];
    const float* W_self  = (const float*)d_in[2];
    const float* b_self  = (const float*)d_in[3];
    const float* W_neigh = (const float*)d_in[4];
    const float* Wur1 = (const float*)d_in[5];
    const float* bur1 = (const float*)d_in[6];
    const float* Wur2 = (const float*)d_in[7];
    const float* bur2 = (const float*)d_in[8];
    const float* Wvr1 = (const float*)d_in[9];
    const float* bvr1 = (const float*)d_in[10];
    const float* Wvr2 = (const float*)d_in[11];
    const float* bvr2 = (const float*)d_in[12];
    const float* Wuv1 = (const float*)d_in[13];
    const float* buv1 = (const float*)d_in[14];
    const float* Wuv2 = (const float*)d_in[15];
    const float* buv2 = (const float*)d_in[16];
    const float* Wuv3 = (const float*)d_in[17];
    const float* buv3 = (const float*)d_in[18];
    const float* bn_gamma  = (const float*)d_in[19];
    const float* bn_beta   = (const float*)d_in[20];
    const float* bn4_gamma = (const float*)d_in[21];
    const float* bn4_beta  = (const float*)d_in[22];
    const int* social_src = (const int*)d_in[23];
    const int* social_dst = (const int*)d_in[24];
    const int* rates_src  = (const int*)d_in[25];
    const int* rates_dst  = (const int*)d_in[26];
    float* out = (float*)d_out;

    void *p_ssoc, *p_sru, *p_srv, *p_degs, *p_degru, *p_degrv;
    void *p_tu, *p_tv, *p_xu, *p_xv, *p_y1, *p_y2;
    void *p_stU, *p_stV, *p_st1, *p_st2, *p_aU, *p_aV, *p_a1, *p_a2;
    void *p_nfH, *p_nfL;
    cudaGetSymbolAddress(&p_ssoc, g_s_social);
    cudaGetSymbolAddress(&p_sru, g_s_ru);
    cudaGetSymbolAddress(&p_srv, g_s_rv);
    cudaGetSymbolAddress(&p_degs, g_deg_s);
    cudaGetSymbolAddress(&p_degru, g_deg_ru);
    cudaGetSymbolAddress(&p_degrv, g_deg_rv);
    cudaGetSymbolAddress(&p_tu, g_tu);
    cudaGetSymbolAddress(&p_tv, g_tv);
    cudaGetSymbolAddress(&p_xu, g_xu);
    cudaGetSymbolAddress(&p_xv, g_xv);
    cudaGetSymbolAddress(&p_y1, g_y1);
    cudaGetSymbolAddress(&p_y2, g_y2);
    cudaGetSymbolAddress(&p_stU, g_statU);
    cudaGetSymbolAddress(&p_stV, g_statV);
    cudaGetSymbolAddress(&p_st1, g_stat1);
    cudaGetSymbolAddress(&p_st2, g_stat2);
    cudaGetSymbolAddress(&p_aU, g_affU);
    cudaGetSymbolAddress(&p_aV, g_affV);
    cudaGetSymbolAddress(&p_a1, g_aff1);
    cudaGetSymbolAddress(&p_a2, g_aff2);
    cudaGetSymbolAddress(&p_nfH, g_nfH);
    cudaGetSymbolAddress(&p_nfL, g_nfL);

    cudaFuncSetAttribute(k_edge1_mma, cudaFuncAttributeMaxDynamicSharedMemorySize, E1_SMEM);

    const int NBn = (NUc + 127) / 128;   // 391 (NV == NU)
    const int NB_E1 = (ERc + 127) / 128;

    k_zero<<<2048, 256>>>();
    k_prepW<<<1, 256>>>(Wuv1, Wuv2);
    k_prepN<<<8, 256>>>(W_self, W_neigh, Wur1, Wvr1, Wur2, Wvr2);

    // segment sums: social (u->u) separate; both rates directions fused
    k_scatter<<<ESc / 16, 256>>>(u2e, social_src, social_dst,
                                 (float*)p_ssoc, (float*)p_degs, ESc);
    k_scatter2<<<ERc / 16, 256>>>(u2e, v2e, rates_src, rates_dst,
                                  (float*)p_srv, (float*)p_sru,
                                  (float*)p_degrv, (float*)p_degru);

    k_user1_mma<<<NBn, 256>>>(u2e, b_self, bur1, (float*)p_tu, (double*)p_stU);
    k_item1_mma<<<NBn, 256>>>(v2e, b_self, bvr1, (float*)p_tv, (double*)p_stV);
    k_fin<<<1, 64>>>((const double*)p_stU, bn_gamma + 0, bn_beta + 0, (float*)p_aU, 64, 1.0f / NUc);
    k_fin<<<1, 64>>>((const double*)p_stV, bn_gamma + 64, bn_beta + 64, (float*)p_aV, 64, 1.0f / NVc);
    k_tower2_mma<<<NBn, 256>>>((const float*)p_tu, (const float*)p_aU,
                               (const uint32_t*)p_nfH + 7 * 2048, (const uint32_t*)p_nfL + 7 * 2048,
                               bur2, (float*)p_xu, NUc);
    k_tower2_mma<<<NBn, 256>>>((const float*)p_tv, (const float*)p_aV,
                               (const uint32_t*)p_nfH + 8 * 2048, (const uint32_t*)p_nfL + 8 * 2048,
                               bvr2, (float*)p_xv, NVc);

    k_edge1_mma<<<NB_E1, 256, E1_SMEM>>>((const float*)p_xu, (const float*)p_xv,
                                         rates_src, rates_dst, buv1,
                                         (float*)p_y1, (double*)p_st1);
    k_fin<<<1, 64>>>((const double*)p_st1, bn_gamma + 128, bn_beta + 128, (float*)p_a1, 64, 1.0f / ERc);
    k_edge2_mma<<<NB_E1, 256>>>((const float*)p_y1, (const float*)p_a1, buv2,
                                (float*)p_y2, (double*)p_st2);
    k_fin<<<1, 16>>>((const double*)p_st2, bn4_gamma, bn4_beta, (float*)p_a2, 16, 1.0f / ERc);
    k_edge3<<<(ERc + 255) / 256, 256>>>((const float*)p_y2, (const float*)p_a2, Wuv3, buv3, out);

    (void)in_sizes; (void)n_in; (void)out_size;
}

// round 12
// speedup vs baseline: 1.6096x; 1.2561x over previous
#include <cuda_runtime.h>
#include <cuda_bf16.h>
#include <cuda_fp16.h>
#include <cstdint>

#define NUc 50000
#define NVc 50000
#define ESc 800000
#define ERc 1000000

// ---------------- device scratch (no allocations allowed) ----------------
__device__ __align__(16) float g_s_social[(size_t)NUc * 64];
__device__ __align__(16) float g_s_ru[(size_t)NUc * 64];
__device__ __align__(16) float g_s_rv[(size_t)NVc * 64];
__device__ float g_deg_s[NUc];
__device__ float g_deg_ru[NUc];
__device__ float g_deg_rv[NVc];
__device__ __align__(16) float g_tu[(size_t)NUc * 64];
__device__ __align__(16) float g_tv[(size_t)NVc * 64];
__device__ __align__(16) __half g_xuh[(size_t)NUc * 64];   // fp16 x tables (6.4 MB each)
__device__ __align__(16) __half g_xvh[(size_t)NVc * 64];
__device__ __align__(16) __half g_y1h[(size_t)ERc * 64];   // fp16 y1 (128 MB)
__device__ __align__(16) float g_y2[(size_t)ERc * 16];     // 64 MB
__device__ double g_statU[128];
__device__ double g_statV[128];
__device__ double g_stat1[128];
__device__ double g_stat2[32];
__device__ __align__(16) float g_affU[128];
__device__ __align__(16) float g_affV[128];
__device__ __align__(16) float g_aff1[128];
__device__ __align__(16) float g_aff2[32];
// Wuv1 pre-packed into per-lane m16n8k16 B-fragment order (hi/lo bf16 split)
__device__ __align__(16) uint32_t g_fragH[2048];
__device__ __align__(16) uint32_t g_fragL[2048];
// Wuv2 (64x16): (kt*2+nt)*64 + lane*2 + r
__device__ __align__(16) uint32_t g_frag2H[512];
__device__ __align__(16) uint32_t g_frag2L[512];
// 9 node matrices (64x64 each) in B-fragment order:
// 0:Wself0+Wself2  1:Wn0  2:Wn2  3:Wur1  4:Wself1  5:Wn1  6:Wvr1  7:Wur2  8:Wvr2
__device__ __align__(16) uint32_t g_nfH[9 * 2048];
__device__ __align__(16) uint32_t g_nfL[9 * 2048];

// ---------------- common mma helpers ----------------
__device__ __forceinline__ void mma16816(float c[4], uint32_t a0, uint32_t a1,
                                         uint32_t a2, uint32_t a3,
                                         uint32_t b0, uint32_t b1) {
    asm volatile(
        "mma.sync.aligned.m16n8k16.row.col.f32.bf16.bf16.f32 "
        "{%0,%1,%2,%3}, {%4,%5,%6,%7}, {%8,%9}, {%0,%1,%2,%3};"
        : "+f"(c[0]), "+f"(c[1]), "+f"(c[2]), "+f"(c[3])
        : "r"(a0), "r"(a1), "r"(a2), "r"(a3), "r"(b0), "r"(b1));
}

__device__ __forceinline__ uint32_t pack_split(float x, float y, uint32_t& lo) {
    __nv_bfloat162 h = __floats2bfloat162_rn(x, y);
    float rx = x - __bfloat162float(h.x);
    float ry = y - __bfloat162float(h.y);
    __nv_bfloat162 l = __floats2bfloat162_rn(rx, ry);
    lo = *(const uint32_t*)&l;
    return *(const uint32_t*)&h;
}

__device__ __forceinline__ uint32_t h2bits(__half2 h) { return *(const uint32_t*)&h; }

#define AROW 136   // bytes per A row (64 bf16 = 128B + 8B pad)
#define OFF_AH 0
#define OFF_AL 17408

// stage a [128 x 64] f32 tile (optionally scaled by 1/deg) into smem as bf16 hi/lo
__device__ __forceinline__ void stageA(char* smem, const float* __restrict__ src,
                                       const float* __restrict__ deg,
                                       int rowBase, int N, int t) {
    int r = t >> 1, h = t & 1;
    int row = rowBase + r;
    char* aH = smem + OFF_AH + r * AROW + h * 64;
    char* aL = smem + OFF_AL + r * AROW + h * 64;
    if (row < N) {
        float sc = deg ? (1.f / fmaxf(__ldg(deg + row), 1.f)) : 1.f;
        const float4* pu = (const float4*)(src + (size_t)row * 64) + h * 8;
#pragma unroll
        for (int j = 0; j < 8; j++) {
            float4 a = __ldg(pu + j);
            uint32_t lo01, lo23;
            uint32_t hi01 = pack_split(a.x * sc, a.y * sc, lo01);
            uint32_t hi23 = pack_split(a.z * sc, a.w * sc, lo23);
            *(uint2*)(aH + j * 8) = make_uint2(hi01, hi23);
            *(uint2*)(aL + j * 8) = make_uint2(lo01, lo23);
        }
    } else {
#pragma unroll
        for (int j = 0; j < 8; j++) {
            *(uint2*)(aH + j * 8) = make_uint2(0u, 0u);
            *(uint2*)(aL + j * 8) = make_uint2(0u, 0u);
        }
    }
}

// acc += A(smem) @ W(frags in global, 8 n-tiles), 3-term bf16 split
__device__ __forceinline__ void mma_AB(const char* smem,
                                       const uint32_t* __restrict__ fH,
                                       const uint32_t* __restrict__ fL,
                                       int r0, int tig, int lane, float acc[8][4]) {
    const char* AH = smem + OFF_AH;
    const char* AL = smem + OFF_AL;
#pragma unroll
    for (int kt = 0; kt < 4; kt++) {
        int ka = kt * 32 + tig * 4;
        uint32_t aH0 = *(const uint32_t*)(AH + r0 * AROW + ka);
        uint32_t aH1 = *(const uint32_t*)(AH + (r0 + 8) * AROW + ka);
        uint32_t aH2 = *(const uint32_t*)(AH + r0 * AROW + ka + 16);
        uint32_t aH3 = *(const uint32_t*)(AH + (r0 + 8) * AROW + ka + 16);
        uint32_t aL0 = *(const uint32_t*)(AL + r0 * AROW + ka);
        uint32_t aL1 = *(const uint32_t*)(AL + (r0 + 8) * AROW + ka);
        uint32_t aL2 = *(const uint32_t*)(AL + r0 * AROW + ka + 16);
        uint32_t aL3 = *(const uint32_t*)(AL + (r0 + 8) * AROW + ka + 16);
#pragma unroll
        for (int nt = 0; nt < 8; nt++) {
            int fo = (kt * 8 + nt) * 64 + lane * 2;
            uint2 bH = __ldg((const uint2*)(fH + fo));
            uint2 bL = __ldg((const uint2*)(fL + fo));
            mma16816(acc[nt], aH0, aH1, aH2, aH3, bH.x, bH.y);
            mma16816(acc[nt], aH0, aH1, aH2, aH3, bL.x, bL.y);
            mma16816(acc[nt], aL0, aL1, aL2, aL3, bH.x, bH.y);
        }
    }
}

// acc2 += (acc + bias[col]) @ W(frags), with C->A fragment identity mapping
__device__ __forceinline__ void frag_gemm64(const float acc[8][4],
                                            const float* __restrict__ biasS,
                                            const uint32_t* __restrict__ fH,
                                            const uint32_t* __restrict__ fL,
                                            int tig, int lane, float acc2[8][4]) {
#pragma unroll
    for (int kt = 0; kt < 4; kt++) {
        int c0 = kt * 16 + tig * 2;
        float b00 = biasS[c0], b01 = biasS[c0 + 1];
        float b02 = biasS[c0 + 8], b03 = biasS[c0 + 9];
        uint32_t l0, l1, l2, l3;
        uint32_t a0 = pack_split(acc[2 * kt][0] + b00, acc[2 * kt][1] + b01, l0);
        uint32_t a1 = pack_split(acc[2 * kt][2] + b00, acc[2 * kt][3] + b01, l1);
        uint32_t a2 = pack_split(acc[2 * kt + 1][0] + b02, acc[2 * kt + 1][1] + b03, l2);
        uint32_t a3 = pack_split(acc[2 * kt + 1][2] + b02, acc[2 * kt + 1][3] + b03, l3);
#pragma unroll
        for (int nt = 0; nt < 8; nt++) {
            int fo = (kt * 8 + nt) * 64 + lane * 2;
            uint2 bH = __ldg((const uint2*)(fH + fo));
            uint2 bL = __ldg((const uint2*)(fL + fo));
            mma16816(acc2[nt], a0, a1, a2, a3, bH.x, bH.y);
            mma16816(acc2[nt], a0, a1, a2, a3, bL.x, bL.y);
            mma16816(acc2[nt], l0, l1, l2, l3, bH.x, bH.y);
        }
    }
}

// ---------------- zero scratch ----------------
__global__ void k_zero() {
    size_t tid = (size_t)blockIdx.x * blockDim.x + threadIdx.x;
    size_t stride = (size_t)gridDim.x * blockDim.x;
    const size_t n4 = (size_t)NUc * 16;
    float4 z = make_float4(0.f, 0.f, 0.f, 0.f);
    for (size_t j = tid; j < n4; j += stride) {
        ((float4*)g_s_social)[j] = z;
        ((float4*)g_s_ru)[j] = z;
        ((float4*)g_s_rv)[j] = z;
    }
    for (size_t j = tid; j < NUc; j += stride) {
        g_deg_s[j] = 0.f;
        g_deg_ru[j] = 0.f;
        g_deg_rv[j] = 0.f;
    }
    if (tid < 128) { g_statU[tid] = 0.0; g_statV[tid] = 0.0; g_stat1[tid] = 0.0; }
    if (tid < 32) g_stat2[tid] = 0.0;
}

// ---------------- prep: edge weight fragments (Wuv1, Wuv2) ----------------
__global__ void k_prepW(const float* __restrict__ W1, const float* __restrict__ W2) {
    int t = threadIdx.x;
    for (int idx = t; idx < 2048; idx += 256) {
        int r = idx & 1;
        int lane = (idx >> 1) & 31;
        int grp = idx >> 6;
        int kt = grp >> 3, nt = grp & 7;
        int g = lane >> 2, tig = lane & 3;
        int n = nt * 8 + g;
        int k0 = kt * 16 + 2 * tig + (r ? 8 : 0);
        uint32_t lo;
        uint32_t hi = pack_split(__ldg(W1 + k0 * 64 + n), __ldg(W1 + (k0 + 1) * 64 + n), lo);
        g_fragH[idx] = hi;
        g_fragL[idx] = lo;
    }
    for (int idx = t; idx < 512; idx += 256) {
        int r = idx & 1;
        int lane = (idx >> 1) & 31;
        int grp = idx >> 6;
        int kt = grp >> 1, nt = grp & 1;
        int g = lane >> 2, tig = lane & 3;
        int n = nt * 8 + g;
        int k0 = kt * 16 + 2 * tig + (r ? 8 : 0);
        uint32_t lo;
        uint32_t hi = pack_split(__ldg(W2 + k0 * 16 + n), __ldg(W2 + (k0 + 1) * 16 + n), lo);
        g_frag2H[idx] = hi;
        g_frag2L[idx] = lo;
    }
}

// ---------------- prep: 9 node weight matrices into fragments ----------------
__global__ void k_prepN(const float* __restrict__ Ws, const float* __restrict__ Wn,
                        const float* __restrict__ Wur1_, const float* __restrict__ Wvr1_,
                        const float* __restrict__ Wur2_, const float* __restrict__ Wvr2_) {
    int t = blockIdx.x * blockDim.x + threadIdx.x;
    if (t >= 2048) return;
    int r = t & 1;
    int lane = (t >> 1) & 31;
    int grp = t >> 6;
    int kt = grp >> 3, nt = grp & 7;
    int g = lane >> 2, tig = lane & 3;
    int n = nt * 8 + g;
    int k0 = kt * 16 + 2 * tig + (r ? 8 : 0);
    const float* base[9] = {nullptr, Wn, Wn + 2 * 4096, Wur1_, Ws + 4096,
                            Wn + 4096, Wvr1_, Wur2_, Wvr2_};
#pragma unroll
    for (int m = 0; m < 9; m++) {
        float w0, w1;
        if (m == 0) {
            w0 = __ldg(Ws + k0 * 64 + n) + __ldg(Ws + 2 * 4096 + k0 * 64 + n);
            w1 = __ldg(Ws + (k0 + 1) * 64 + n) + __ldg(Ws + 2 * 4096 + (k0 + 1) * 64 + n);
        } else {
            const float* W = base[m];
            w0 = __ldg(W + k0 * 64 + n);
            w1 = __ldg(W + (k0 + 1) * 64 + n);
        }
        uint32_t lo;
        uint32_t hi = pack_split(w0, w1, lo);
        g_nfH[m * 2048 + t] = hi;
        g_nfL[m * 2048 + t] = lo;
    }
}

// ---------------- social scatter: acc[dst] += feat[src] via red.v4 ----------------
__global__ __launch_bounds__(256) void k_scatter(
    const float* __restrict__ feat, const int* __restrict__ src,
    const int* __restrict__ dst, float* __restrict__ acc,
    float* __restrict__ deg, int E) {
    int g = blockIdx.x * blockDim.x + threadIdx.x;
    int e = g >> 4;
    int q = g & 15;
    if (e >= E) return;
    int s = __ldg(src + e);
    int d = __ldg(dst + e);
    float4 v = __ldg((const float4*)feat + (size_t)s * 16 + q);
    float* p = acc + (size_t)d * 64 + q * 4;
    asm volatile("red.global.add.v4.f32 [%0], {%1, %2, %3, %4};"
                 :: "l"(p), "f"(v.x), "f"(v.y), "f"(v.z), "f"(v.w) : "memory");
    if (q == 0) atomicAdd(deg + d, 1.0f);
}

// ---------------- fused rates scatter: both directions, one index read ----------------
__global__ __launch_bounds__(256) void k_scatter2(
    const float* __restrict__ u2e, const float* __restrict__ v2e,
    const int* __restrict__ rs, const int* __restrict__ rd,
    float* __restrict__ s_rv, float* __restrict__ s_ru,
    float* __restrict__ deg_rv, float* __restrict__ deg_ru) {
    int g = blockIdx.x * blockDim.x + threadIdx.x;
    int e = g >> 4;
    int q = g & 15;
    if (e >= ERc) return;
    int s = __ldg(rs + e);
    int d = __ldg(rd + e);
    float4 a = __ldg((const float4*)u2e + (size_t)s * 16 + q);
    float4 b = __ldg((const float4*)v2e + (size_t)d * 16 + q);
    float* p1 = s_rv + (size_t)d * 64 + q * 4;
    float* p2 = s_ru + (size_t)s * 64 + q * 4;
    asm volatile("red.global.add.v4.f32 [%0], {%1, %2, %3, %4};"
                 :: "l"(p1), "f"(a.x), "f"(a.y), "f"(a.z), "f"(a.w) : "memory");
    asm volatile("red.global.add.v4.f32 [%0], {%1, %2, %3, %4};"
                 :: "l"(p2), "f"(b.x), "f"(b.y), "f"(b.z), "f"(b.w) : "memory");
    if (q == 0) {
        atomicAdd(deg_rv + d, 1.0f);
        atomicAdd(deg_ru + s, 1.0f);
    }
}

// ---------------- fused user: combine (3 tensor GEMMs) + tower1 (frag GEMM) + stats ----------------
__global__ __launch_bounds__(256)
void k_user1_mma(const float* __restrict__ u2e, const float* __restrict__ bself,
                 const float* __restrict__ b1, float* __restrict__ out,
                 double* __restrict__ stats) {
    __shared__ __align__(16) char smem[34816];
    __shared__ float biasS[64];
    __shared__ float ssum[64], ssq[64];
    int t = threadIdx.x, lane = t & 31, w = t >> 5;
    int g = lane >> 2, tig = lane & 3;
    int r0 = w * 16 + g;
    int rowBase = blockIdx.x * 128;
    if (t < 64) {
        biasS[t] = __ldg(bself + t) + __ldg(bself + 128 + t);
        ssum[t] = 0.f;
        ssq[t] = 0.f;
    }

    float acc[8][4] = {};
    stageA(smem, u2e, nullptr, rowBase, NUc, t);
    __syncthreads();
    mma_AB(smem, g_nfH + 0 * 2048, g_nfL + 0 * 2048, r0, tig, lane, acc);
    __syncthreads();
    stageA(smem, g_s_social, g_deg_s, rowBase, NUc, t);
    __syncthreads();
    mma_AB(smem, g_nfH + 1 * 2048, g_nfL + 1 * 2048, r0, tig, lane, acc);
    __syncthreads();
    stageA(smem, g_s_ru, g_deg_ru, rowBase, NUc, t);
    __syncthreads();
    mma_AB(smem, g_nfH + 2 * 2048, g_nfL + 2 * 2048, r0, tig, lane, acc);
    __syncthreads();

    float acc2[8][4] = {};
    frag_gemm64(acc, biasS, g_nfH + 3 * 2048, g_nfL + 3 * 2048, tig, lane, acc2);

    float* stage = (float*)smem;
#pragma unroll
    for (int nt = 0; nt < 8; nt++) {
        int c = nt * 8 + tig * 2;
        stage[r0 * 65 + c] = acc2[nt][0];
        stage[r0 * 65 + c + 1] = acc2[nt][1];
        stage[(r0 + 8) * 65 + c] = acc2[nt][2];
        stage[(r0 + 8) * 65 + c + 1] = acc2[nt][3];
    }
    __syncthreads();

    int c4 = (t & 15) * 4;
    float4 bias = *(const float4*)(b1 + c4);
    float cs[4] = {0, 0, 0, 0}, cq[4] = {0, 0, 0, 0};
#pragma unroll
    for (int i = 0; i < 8; i++) {
        int r = (t >> 4) + 16 * i;
        int row = rowBase + r;
        if (row < NUc) {
            const float* sp = stage + r * 65 + c4;
            float v0 = sp[0] + bias.x, v1 = sp[1] + bias.y;
            float v2 = sp[2] + bias.z, v3 = sp[3] + bias.w;
            *(float4*)(out + (size_t)row * 64 + c4) = make_float4(v0, v1, v2, v3);
            cs[0] += v0; cq[0] += v0 * v0;
            cs[1] += v1; cq[1] += v1 * v1;
            cs[2] += v2; cq[2] += v2 * v2;
            cs[3] += v3; cq[3] += v3 * v3;
        }
    }
#pragma unroll
    for (int j = 0; j < 4; j++) {
        atomicAdd(&ssum[c4 + j], cs[j]);
        atomicAdd(&ssq[c4 + j], cq[j]);
    }
    __syncthreads();
    if (t < 64) atomicAdd(&stats[t], (double)ssum[t]);
    else if (t < 128) atomicAdd(&stats[t], (double)ssq[t - 64]);
}

// ---------------- fused item: combine (2 tensor GEMMs) + tower1 + stats ----------------
__global__ __launch_bounds__(256)
void k_item1_mma(const float* __restrict__ v2e, const float* __restrict__ bself,
                 const float* __restrict__ b1, float* __restrict__ out,
                 double* __restrict__ stats) {
    __shared__ __align__(16) char smem[34816];
    __shared__ float biasS[64];
    __shared__ float ssum[64], ssq[64];
    int t = threadIdx.x, lane = t & 31, w = t >> 5;
    int g = lane >> 2, tig = lane & 3;
    int r0 = w * 16 + g;
    int rowBase = blockIdx.x * 128;
    if (t < 64) {
        biasS[t] = __ldg(bself + 64 + t);
        ssum[t] = 0.f;
        ssq[t] = 0.f;
    }

    float acc[8][4] = {};
    stageA(smem, v2e, nullptr, rowBase, NVc, t);
    __syncthreads();
    mma_AB(smem, g_nfH + 4 * 2048, g_nfL + 4 * 2048, r0, tig, lane, acc);
    __syncthreads();
    stageA(smem, g_s_rv, g_deg_rv, rowBase, NVc, t);
    __syncthreads();
    mma_AB(smem, g_nfH + 5 * 2048, g_nfL + 5 * 2048, r0, tig, lane, acc);
    __syncthreads();

    float acc2[8][4] = {};
    frag_gemm64(acc, biasS, g_nfH + 6 * 2048, g_nfL + 6 * 2048, tig, lane, acc2);

    float* stage = (float*)smem;
#pragma unroll
    for (int nt = 0; nt < 8; nt++) {
        int c = nt * 8 + tig * 2;
        stage[r0 * 65 + c] = acc2[nt][0];
        stage[r0 * 65 + c + 1] = acc2[nt][1];
        stage[(r0 + 8) * 65 + c] = acc2[nt][2];
        stage[(r0 + 8) * 65 + c + 1] = acc2[nt][3];
    }
    __syncthreads();

    int c4 = (t & 15) * 4;
    float4 bias = *(const float4*)(b1 + c4);
    float cs[4] = {0, 0, 0, 0}, cq[4] = {0, 0, 0, 0};
#pragma unroll
    for (int i = 0; i < 8; i++) {
        int r = (t >> 4) + 16 * i;
        int row = rowBase + r;
        if (row < NVc) {
            const float* sp = stage + r * 65 + c4;
            float v0 = sp[0] + bias.x, v1 = sp[1] + bias.y;
            float v2 = sp[2] + bias.z, v3 = sp[3] + bias.w;
            *(float4*)(out + (size_t)row * 64 + c4) = make_float4(v0, v1, v2, v3);
            cs[0] += v0; cq[0] += v0 * v0;
            cs[1] += v1; cq[1] += v1 * v1;
            cs[2] += v2; cq[2] += v2 * v2;
            cs[3] += v3; cq[3] += v3 * v3;
        }
    }
#pragma unroll
    for (int j = 0; j < 4; j++) {
        atomicAdd(&ssum[c4 + j], cs[j]);
        atomicAdd(&ssq[c4 + j], cq[j]);
    }
    __syncthreads();
    if (t < 64) atomicAdd(&stats[t], (double)ssum[t]);
    else if (t < 128) atomicAdd(&stats[t], (double)ssq[t - 64]);
}

// ---------------- BN finalize ----------------
__global__ void k_fin(const double* __restrict__ stats, const float* __restrict__ gamma,
                      const float* __restrict__ beta, float* __restrict__ aff,
                      int C, float invN) {
    int c = threadIdx.x;
    if (c < C) {
        float mean = (float)(stats[c] * (double)invN);
        float ex2 = (float)(stats[C + c] * (double)invN);
        float var = ex2 - mean * mean;
        float a = gamma[c] * rsqrtf(var + 1e-5f);
        aff[c] = a;
        aff[C + c] = beta[c] - mean * a;
    }
}

// ---------------- tower2 on tensor cores: x = relu(t*a+c) @ W2 + b2 -> fp16 out ----------------
__global__ __launch_bounds__(256)
void k_tower2_mma(const float* __restrict__ in, const float* __restrict__ aff,
                  const uint32_t* __restrict__ fH, const uint32_t* __restrict__ fL,
                  const float* __restrict__ b2, __half* __restrict__ out, int N) {
    __shared__ float stage[128 * 65];
    __shared__ float affS[128];
    int t = threadIdx.x, lane = t & 31, w = t >> 5;
    int g = lane >> 2, tig = lane & 3;
    int r0 = w * 16 + g;
    int rowBase = blockIdx.x * 128;
    if (t < 128) affS[t] = __ldg(aff + t);
    __syncthreads();

    int e0 = rowBase + r0, e1 = e0 + 8;
    bool ok0 = e0 < N, ok1 = e1 < N;

    float acc2[8][4] = {};
#pragma unroll
    for (int kt = 0; kt < 4; kt++) {
        int c0 = kt * 16 + tig * 2;
        float2 z = make_float2(0.f, 0.f);
        float2 y00 = ok0 ? *(const float2*)(in + (size_t)e0 * 64 + c0) : z;
        float2 y10 = ok0 ? *(const float2*)(in + (size_t)e0 * 64 + c0 + 8) : z;
        float2 y01 = ok1 ? *(const float2*)(in + (size_t)e1 * 64 + c0) : z;
        float2 y11 = ok1 ? *(const float2*)(in + (size_t)e1 * 64 + c0 + 8) : z;
        float s0 = affS[c0], h0 = affS[64 + c0];
        float s1 = affS[c0 + 1], h1 = affS[64 + c0 + 1];
        float s2 = affS[c0 + 8], h2 = affS[64 + c0 + 8];
        float s3 = affS[c0 + 9], h3 = affS[64 + c0 + 9];
        float v00 = fmaxf(y00.x * s0 + h0, 0.f), v01 = fmaxf(y00.y * s1 + h1, 0.f);
        float v10 = fmaxf(y01.x * s0 + h0, 0.f), v11 = fmaxf(y01.y * s1 + h1, 0.f);
        float w00 = fmaxf(y10.x * s2 + h2, 0.f), w01 = fmaxf(y10.y * s3 + h3, 0.f);
        float w10 = fmaxf(y11.x * s2 + h2, 0.f), w11 = fmaxf(y11.y * s3 + h3, 0.f);
        uint32_t l0, l1, l2, l3;
        uint32_t a0 = pack_split(v00, v01, l0);
        uint32_t a1 = pack_split(v10, v11, l1);
        uint32_t a2 = pack_split(w00, w01, l2);
        uint32_t a3 = pack_split(w10, w11, l3);
#pragma unroll
        for (int nt = 0; nt < 8; nt++) {
            int fo = (kt * 8 + nt) * 64 + lane * 2;
            uint2 bH = __ldg((const uint2*)(fH + fo));
            uint2 bL = __ldg((const uint2*)(fL + fo));
            mma16816(acc2[nt], a0, a1, a2, a3, bH.x, bH.y);
            mma16816(acc2[nt], a0, a1, a2, a3, bL.x, bL.y);
            mma16816(acc2[nt], l0, l1, l2, l3, bH.x, bH.y);
        }
    }

#pragma unroll
    for (int nt = 0; nt < 8; nt++) {
        int c = nt * 8 + tig * 2;
        stage[r0 * 65 + c] = acc2[nt][0];
        stage[r0 * 65 + c + 1] = acc2[nt][1];
        stage[(r0 + 8) * 65 + c] = acc2[nt][2];
        stage[(r0 + 8) * 65 + c + 1] = acc2[nt][3];
    }
    __syncthreads();

    int c4 = (t & 15) * 4;
    float4 bias = *(const float4*)(b2 + c4);
#pragma unroll
    for (int i = 0; i < 8; i++) {
        int r = (t >> 4) + 16 * i;
        int row = rowBase + r;
        if (row < N) {
            const float* sp = stage + r * 65 + c4;
            __half2 ha = __floats2half2_rn(sp[0] + bias.x, sp[1] + bias.y);
            __half2 hb = __floats2half2_rn(sp[2] + bias.z, sp[3] + bias.w);
            *(uint2*)(out + (size_t)row * 64 + c4) = make_uint2(h2bits(ha), h2bits(hb));
        }
    }
}

// ================= mma.sync edge pass 1: fp16 gather -> fp16 y1 =================
#define E1_SMEM 51200
#define OFF_BH 34816
#define OFF_BL 43008

__global__ __launch_bounds__(256)
void k_edge1_mma(const __half* __restrict__ xu, const __half* __restrict__ xv,
                 const int* __restrict__ es, const int* __restrict__ ed,
                 const float* __restrict__ b, __half* __restrict__ out,
                 double* __restrict__ stats) {
    extern __shared__ __align__(16) char smem[];
    __shared__ float ssum[64], ssq[64];
    int t = threadIdx.x, lane = t & 31, w = t >> 5;
    int rowBase = blockIdx.x * 128;
    if (t < 64) { ssum[t] = 0.f; ssq[t] = 0.f; }

    {
        const uint4* sH = (const uint4*)g_fragH;
        const uint4* sL = (const uint4*)g_fragL;
        uint4* dH = (uint4*)(smem + OFF_BH);
        uint4* dL = (uint4*)(smem + OFF_BL);
        dH[t] = __ldg(sH + t);
        dH[t + 256] = __ldg(sH + t + 256);
        dL[t] = __ldg(sL + t);
        dL[t + 256] = __ldg(sL + t + 256);
    }
    {
        int r = t >> 1, h = t & 1;
        int e = rowBase + r;
        char* aH = smem + OFF_AH + r * AROW + h * 64;
        char* aL = smem + OFF_AL + r * AROW + h * 64;
        if (e < ERc) {
            int s = __ldg(es + e), d = __ldg(ed + e);
            const uint4* pu = (const uint4*)(xu + (size_t)s * 64) + h * 4;   // 8 halves per uint4
            const uint4* pv = (const uint4*)(xv + (size_t)d * 64) + h * 4;
#pragma unroll
            for (int j = 0; j < 4; j++) {
                uint4 A = __ldg(pu + j), V = __ldg(pv + j);
                float2 a0 = __half22float2(*(const __half2*)&A.x);
                float2 a1 = __half22float2(*(const __half2*)&A.y);
                float2 a2 = __half22float2(*(const __half2*)&A.z);
                float2 a3 = __half22float2(*(const __half2*)&A.w);
                float2 v0 = __half22float2(*(const __half2*)&V.x);
                float2 v1 = __half22float2(*(const __half2*)&V.y);
                float2 v2 = __half22float2(*(const __half2*)&V.z);
                float2 v3 = __half22float2(*(const __half2*)&V.w);
                uint32_t lo01, lo23, lo45, lo67;
                uint32_t hi01 = pack_split(a0.x * v0.x, a0.y * v0.y, lo01);
                uint32_t hi23 = pack_split(a1.x * v1.x, a1.y * v1.y, lo23);
                uint32_t hi45 = pack_split(a2.x * v2.x, a2.y * v2.y, lo45);
                uint32_t hi67 = pack_split(a3.x * v3.x, a3.y * v3.y, lo67);
                *(uint2*)(aH + j * 16) = make_uint2(hi01, hi23);
                *(uint2*)(aH + j * 16 + 8) = make_uint2(hi45, hi67);
                *(uint2*)(aL + j * 16) = make_uint2(lo01, lo23);
                *(uint2*)(aL + j * 16 + 8) = make_uint2(lo45, lo67);
            }
        } else {
#pragma unroll
            for (int j = 0; j < 8; j++) {
                *(uint2*)(aH + j * 8) = make_uint2(0u, 0u);
                *(uint2*)(aL + j * 8) = make_uint2(0u, 0u);
            }
        }
    }
    __syncthreads();

    int g = lane >> 2, tig = lane & 3;
    int r0 = w * 16 + g;
    float acc[8][4] = {};
    const char* AH = smem + OFF_AH;
    const char* AL = smem + OFF_AL;
#pragma unroll
    for (int kt = 0; kt < 4; kt++) {
        int ka = kt * 32 + tig * 4;
        uint32_t aH0 = *(const uint32_t*)(AH + r0 * AROW + ka);
        uint32_t aH1 = *(const uint32_t*)(AH + (r0 + 8) * AROW + ka);
        uint32_t aH2 = *(const uint32_t*)(AH + r0 * AROW + ka + 16);
        uint32_t aH3 = *(const uint32_t*)(AH + (r0 + 8) * AROW + ka + 16);
        uint32_t aL0 = *(const uint32_t*)(AL + r0 * AROW + ka);
        uint32_t aL1 = *(const uint32_t*)(AL + (r0 + 8) * AROW + ka);
        uint32_t aL2 = *(const uint32_t*)(AL + r0 * AROW + ka + 16);
        uint32_t aL3 = *(const uint32_t*)(AL + (r0 + 8) * AROW + ka + 16);
#pragma unroll
        for (int nt = 0; nt < 8; nt++) {
            uint32_t boff = ((kt * 8 + nt) * 64 + lane * 2) * 4;
            uint2 bH = *(const uint2*)(smem + OFF_BH + boff);
            uint2 bL = *(const uint2*)(smem + OFF_BL + boff);
            mma16816(acc[nt], aH0, aH1, aH2, aH3, bH.x, bH.y);
            mma16816(acc[nt], aH0, aH1, aH2, aH3, bL.x, bL.y);
            mma16816(acc[nt], aL0, aL1, aL2, aL3, bH.x, bH.y);
        }
    }
    __syncthreads();

    float* stage = (float*)smem;
#pragma unroll
    for (int nt = 0; nt < 8; nt++) {
        int c = nt * 8 + tig * 2;
        stage[r0 * 65 + c] = acc[nt][0];
        stage[r0 * 65 + c + 1] = acc[nt][1];
        stage[(r0 + 8) * 65 + c] = acc[nt][2];
        stage[(r0 + 8) * 65 + c + 1] = acc[nt][3];
    }
    __syncthreads();

    int c4 = (t & 15) * 4;
    float4 bias = *(const float4*)(b + c4);
    float cs[4] = {0, 0, 0, 0}, cq[4] = {0, 0, 0, 0};
#pragma unroll
    for (int i = 0; i < 8; i++) {
        int r = (t >> 4) + 16 * i;
        int e = rowBase + r;
        if (e < ERc) {
            const float* sp = stage + r * 65 + c4;
            float v0 = sp[0] + bias.x, v1 = sp[1] + bias.y;
            float v2 = sp[2] + bias.z, v3 = sp[3] + bias.w;
            __half2 ha = __floats2half2_rn(v0, v1);
            __half2 hb = __floats2half2_rn(v2, v3);
            *(uint2*)(out + (size_t)e * 64 + c4) = make_uint2(h2bits(ha), h2bits(hb));
            cs[0] += v0; cq[0] += v0 * v0;
            cs[1] += v1; cq[1] += v1 * v1;
            cs[2] += v2; cq[2] += v2 * v2;
            cs[3] += v3; cq[3] += v3 * v3;
        }
    }
#pragma unroll
    for (int j = 0; j < 4; j++) {
        atomicAdd(&ssum[c4 + j], cs[j]);
        atomicAdd(&ssq[c4 + j], cq[j]);
    }
    __syncthreads();
    if (t < 64) atomicAdd(&stats[t], (double)ssum[t]);
    else if (t < 128) atomicAdd(&stats[t], (double)ssq[t - 64]);
}

// ================= edge pass 2 on tensor cores: fp16 y1 in =================
__global__ __launch_bounds__(256)
void k_edge2_mma(const __half* __restrict__ y1, const float* __restrict__ aff,
                 const float* __restrict__ b2, float* __restrict__ y2,
                 double* __restrict__ stats) {
    __shared__ float affS[128];
    __shared__ __align__(16) uint32_t f2H[512], f2L[512];
    __shared__ float ssum[16], ssq[16];
    int t = threadIdx.x, lane = t & 31, w = t >> 5;
    int rowBase = blockIdx.x * 128;
    if (t < 128) affS[t] = __ldg(aff + t);
    if (t < 16) { ssum[t] = 0.f; ssq[t] = 0.f; }
    {
        ((uint2*)f2H)[t] = __ldg((const uint2*)g_frag2H + t);
        ((uint2*)f2L)[t] = __ldg((const uint2*)g_frag2L + t);
    }
    __syncthreads();

    int g = lane >> 2, tig = lane & 3;
    int r0 = w * 16 + g;
    int e0 = rowBase + r0, e1 = e0 + 8;
    bool ok0 = e0 < ERc, ok1 = e1 < ERc;

    float acc2[2][4] = {};
#pragma unroll
    for (int kt = 0; kt < 4; kt++) {
        int c0 = kt * 16 + tig * 2;
        float2 z = make_float2(0.f, 0.f);
        float2 y00 = ok0 ? __half22float2(*(const __half2*)(y1 + (size_t)e0 * 64 + c0)) : z;
        float2 y10 = ok1 ? __half22float2(*(const __half2*)(y1 + (size_t)e1 * 64 + c0)) : z;
        float2 y01 = ok0 ? __half22float2(*(const __half2*)(y1 + (size_t)e0 * 64 + c0 + 8)) : z;
        float2 y11 = ok1 ? __half22float2(*(const __half2*)(y1 + (size_t)e1 * 64 + c0 + 8)) : z;
        float s0 = affS[c0], h0 = affS[64 + c0];
        float s1 = affS[c0 + 1], h1 = affS[64 + c0 + 1];
        float s2 = affS[c0 + 8], h2 = affS[64 + c0 + 8];
        float s3 = affS[c0 + 9], h3 = affS[64 + c0 + 9];
        float v00 = fmaxf(y00.x * s0 + h0, 0.f);
        float v01 = fmaxf(y00.y * s1 + h1, 0.f);
        float v10 = fmaxf(y10.x * s0 + h0, 0.f);
        float v11 = fmaxf(y10.y * s1 + h1, 0.f);
        float w00 = fmaxf(y01.x * s2 + h2, 0.f);
        float w01 = fmaxf(y01.y * s3 + h3, 0.f);
        float w10 = fmaxf(y11.x * s2 + h2, 0.f);
        float w11 = fmaxf(y11.y * s3 + h3, 0.f);
        uint32_t l0, l1, l2, l3;
        uint32_t a0 = pack_split(v00, v01, l0);
        uint32_t a1 = pack_split(v10, v11, l1);
        uint32_t a2 = pack_split(w00, w01, l2);
        uint32_t a3 = pack_split(w10, w11, l3);
#pragma unroll
        for (int n2 = 0; n2 < 2; n2++) {
            int fo = (kt * 2 + n2) * 64 + lane * 2;
            uint2 bH = *(const uint2*)(f2H + fo);
            uint2 bL = *(const uint2*)(f2L + fo);
            mma16816(acc2[n2], a0, a1, a2, a3, bH.x, bH.y);
            mma16816(acc2[n2], a0, a1, a2, a3, bL.x, bL.y);
            mma16816(acc2[n2], l0, l1, l2, l3, bH.x, bH.y);
        }
    }

    float cs[4] = {0, 0, 0, 0}, cq[4] = {0, 0, 0, 0};
#pragma unroll
    for (int n2 = 0; n2 < 2; n2++) {
        int c = n2 * 8 + tig * 2;
        float bx = __ldg(b2 + c), by = __ldg(b2 + c + 1);
        float u0 = acc2[n2][0] + bx, u1 = acc2[n2][1] + by;
        float u2 = acc2[n2][2] + bx, u3 = acc2[n2][3] + by;
        if (ok0) {
            *(float2*)(y2 + (size_t)e0 * 16 + c) = make_float2(u0, u1);
            cs[n2 * 2] += u0; cq[n2 * 2] += u0 * u0;
            cs[n2 * 2 + 1] += u1; cq[n2 * 2 + 1] += u1 * u1;
        }
        if (ok1) {
            *(float2*)(y2 + (size_t)e1 * 16 + c) = make_float2(u2, u3);
            cs[n2 * 2] += u2; cq[n2 * 2] += u2 * u2;
            cs[n2 * 2 + 1] += u3; cq[n2 * 2 + 1] += u3 * u3;
        }
    }
#pragma unroll
    for (int n2 = 0; n2 < 2; n2++) {
#pragma unroll
        for (int j = 0; j < 2; j++) {
            int c = n2 * 8 + tig * 2 + j;
            atomicAdd(&ssum[c], cs[n2 * 2 + j]);
            atomicAdd(&ssq[c], cq[n2 * 2 + j]);
        }
    }
    __syncthreads();
    if (t < 16) atomicAdd(&stats[t], (double)ssum[t]);
    else if (t < 32) atomicAdd(&stats[t], (double)ssq[t - 16]);
}

// ---------------- edge pass 3: scores = relu(y2*a2+c2) . w3 + b3 ----------------
__global__ __launch_bounds__(256) void k_edge3(
    const float* __restrict__ y2, const float* __restrict__ aff,
    const float* __restrict__ w3, const float* __restrict__ b3,
    float* __restrict__ out) {
    int e = blockIdx.x * blockDim.x + threadIdx.x;
    if (e >= ERc) return;
    const float4* p = (const float4*)(y2 + (size_t)e * 16);
    float s = 0.f;
#pragma unroll
    for (int j = 0; j < 4; j++) {
        float4 v = __ldg(p + j);
        float4 a = *(const float4*)(aff + 4 * j);
        float4 c = *(const float4*)(aff + 16 + 4 * j);
        float4 w = *(const float4*)(w3 + 4 * j);
        s += fmaxf(v.x * a.x + c.x, 0.f) * w.x;
        s += fmaxf(v.y * a.y + c.y, 0.f) * w.y;
        s += fmaxf(v.z * a.z + c.z, 0.f) * w.z;
        s += fmaxf(v.w * a.w + c.w, 0.f) * w.w;
    }
    out[e] = s + __ldg(b3);
}

// ---------------- host ----------------
extern "C" void kernel_launch(void* const* d_in, const int* in_sizes, int n_in,
                              void* d_out, int out_size) {
    const float* u2e     = (const float*)d_in[0];
    const float* v2e     = (const float*)d_in[1];
    const float* W_self  = (const float*)d_in[2];
    const float* b_self  = (const float*)d_in[3];
    const float* W_neigh = (const float*)d_in[4];
    const float* Wur1 = (const float*)d_in[5];
    const float* bur1 = (const float*)d_in[6];
    const float* Wur2 = (const float*)d_in[7];
    const float* bur2 = (const float*)d_in[8];
    const float* Wvr1 = (const float*)d_in[9];
    const float* bvr1 = (const float*)d_in[10];
    const float* Wvr2 = (const float*)d_in[11];
    const float* bvr2 = (const float*)d_in[12];
    const float* Wuv1 = (const float*)d_in[13];
    const float* buv1 = (const float*)d_in[14];
    const float* Wuv2 = (const float*)d_in[15];
    const float* buv2 = (const float*)d_in[16];
    const float* Wuv3 = (const float*)d_in[17];
    const float* buv3 = (const float*)d_in[18];
    const float* bn_gamma  = (const float*)d_in[19];
    const float* bn_beta   = (const float*)d_in[20];
    const float* bn4_gamma = (const float*)d_in[21];
    const float* bn4_beta  = (const float*)d_in[22];
    const int* social_src = (const int*)d_in[23];
    const int* social_dst = (const int*)d_in[24];
    const int* rates_src  = (const int*)d_in[25];
    const int* rates_dst  = (const int*)d_in[26];
    float* out = (float*)d_out;

    void *p_ssoc, *p_sru, *p_srv, *p_degs, *p_degru, *p_degrv;
    void *p_tu, *p_tv, *p_xu, *p_xv, *p_y1, *p_y2;
    void *p_stU, *p_stV, *p_st1, *p_st2, *p_aU, *p_aV, *p_a1, *p_a2;
    void *p_nfH, *p_nfL;
    cudaGetSymbolAddress(&p_ssoc, g_s_social);
    cudaGetSymbolAddress(&p_sru, g_s_ru);
    cudaGetSymbolAddress(&p_srv, g_s_rv);
    cudaGetSymbolAddress(&p_degs, g_deg_s);
    cudaGetSymbolAddress(&p_degru, g_deg_ru);
    cudaGetSymbolAddress(&p_degrv, g_deg_rv);
    cudaGetSymbolAddress(&p_tu, g_tu);
    cudaGetSymbolAddress(&p_tv, g_tv);
    cudaGetSymbolAddress(&p_xu, g_xuh);
    cudaGetSymbolAddress(&p_xv, g_xvh);
    cudaGetSymbolAddress(&p_y1, g_y1h);
    cudaGetSymbolAddress(&p_y2, g_y2);
    cudaGetSymbolAddress(&p_stU, g_statU);
    cudaGetSymbolAddress(&p_stV, g_statV);
    cudaGetSymbolAddress(&p_st1, g_stat1);
    cudaGetSymbolAddress(&p_st2, g_stat2);
    cudaGetSymbolAddress(&p_aU, g_affU);
    cudaGetSymbolAddress(&p_aV, g_affV);
    cudaGetSymbolAddress(&p_a1, g_aff1);
    cudaGetSymbolAddress(&p_a2, g_aff2);
    cudaGetSymbolAddress(&p_nfH, g_nfH);
    cudaGetSymbolAddress(&p_nfL, g_nfL);

    cudaFuncSetAttribute(k_edge1_mma, cudaFuncAttributeMaxDynamicSharedMemorySize, E1_SMEM);

    const int NBn = (NUc + 127) / 128;   // 391 (NV == NU)
    const int NB_E1 = (ERc + 127) / 128;

    k_zero<<<2048, 256>>>();
    k_prepW<<<1, 256>>>(Wuv1, Wuv2);
    k_prepN<<<8, 256>>>(W_self, W_neigh, Wur1, Wvr1, Wur2, Wvr2);

    // segment sums: social (u->u) separate; both rates directions fused
    k_scatter<<<ESc / 16, 256>>>(u2e, social_src, social_dst,
                                 (float*)p_ssoc, (float*)p_degs, ESc);
    k_scatter2<<<ERc / 16, 256>>>(u2e, v2e, rates_src, rates_dst,
                                  (float*)p_srv, (float*)p_sru,
                                  (float*)p_degrv, (float*)p_degru);

    k_user1_mma<<<NBn, 256>>>(u2e, b_self, bur1, (float*)p_tu, (double*)p_stU);
    k_item1_mma<<<NBn, 256>>>(v2e, b_self, bvr1, (float*)p_tv, (double*)p_stV);
    k_fin<<<1, 64>>>((const double*)p_stU, bn_gamma + 0, bn_beta + 0, (float*)p_aU, 64, 1.0f / NUc);
    k_fin<<<1, 64>>>((const double*)p_stV, bn_gamma + 64, bn_beta + 64, (float*)p_aV, 64, 1.0f / NVc);
    k_tower2_mma<<<NBn, 256>>>((const float*)p_tu, (const float*)p_aU,
                               (const uint32_t*)p_nfH + 7 * 2048, (const uint32_t*)p_nfL + 7 * 2048,
                               bur2, (__half*)p_xu, NUc);
    k_tower2_mma<<<NBn, 256>>>((const float*)p_tv, (const float*)p_aV,
                               (const uint32_t*)p_nfH + 8 * 2048, (const uint32_t*)p_nfL + 8 * 2048,
                               bvr2, (__half*)p_xv, NVc);

    k_edge1_mma<<<NB_E1, 256, E1_SMEM>>>((const __half*)p_xu, (const __half*)p_xv,
                                         rates_src, rates_dst, buv1,
                                         (__half*)p_y1, (double*)p_st1);
    k_fin<<<1, 64>>>((const double*)p_st1, bn_gamma + 128, bn_beta + 128, (float*)p_a1, 64, 1.0f / ERc);
    k_edge2_mma<<<NB_E1, 256>>>((const __half*)p_y1, (const float*)p_a1, buv2,
                                (float*)p_y2, (double*)p_st2);
    k_fin<<<1, 16>>>((const double*)p_st2, bn4_gamma, bn4_beta, (float*)p_a2, 16, 1.0f / ERc);
    k_edge3<<<(ERc + 255) / 256, 256>>>((const float*)p_y2, (const float*)p_a2, Wuv3, buv3, out);

    (void)in_sizes; (void)n_in; (void)out_size;
}

// round 14
// speedup vs baseline: 1.6923x; 1.0514x over previous
#include <cuda_runtime.h>
#include <cuda_bf16.h>
#include <cuda_fp16.h>
#include <cstdint>

#define NUc 50000
#define NVc 50000
#define ESc 800000
#define ERc 1000000

// ---------------- device scratch (no allocations allowed) ----------------
__device__ __align__(16) float g_s_social[(size_t)NUc * 64];
__device__ __align__(16) float g_s_ru[(size_t)NUc * 64];
__device__ __align__(16) float g_s_rv[(size_t)NVc * 64];
__device__ float g_deg_s[NUc];
__device__ float g_deg_ru[NUc];
__device__ float g_deg_rv[NVc];
__device__ __align__(16) float g_tu[(size_t)NUc * 64];
__device__ __align__(16) float g_tv[(size_t)NVc * 64];
__device__ __align__(16) __half g_xuh[(size_t)NUc * 64];   // fp16 x tables
__device__ __align__(16) __half g_xvh[(size_t)NVc * 64];
__device__ __align__(16) __half g_y1h[(size_t)ERc * 64];   // fp16 y1 (128 MB)
__device__ __align__(16) float g_y2[(size_t)ERc * 16];     // 64 MB
__device__ double g_statU[128];
__device__ double g_statV[128];
__device__ double g_stat1[128];
__device__ double g_stat2[32];
__device__ __align__(16) float g_affU[128];
__device__ __align__(16) float g_affV[128];
__device__ __align__(16) float g_aff1[128];
__device__ __align__(16) float g_aff2[32];
// Wuv1 pre-packed per-lane m16n8k16 B-fragment order, fp16 hi/lo split
__device__ __align__(16) uint32_t g_fragH[2048];
__device__ __align__(16) uint32_t g_fragL[2048];
// Wuv2 (64x16) fp16 hi/lo: (kt*2+nt)*64 + lane*2 + r
__device__ __align__(16) uint32_t g_frag2H[512];
__device__ __align__(16) uint32_t g_frag2L[512];
// 9 node matrices (64x64 each) in bf16 hi/lo B-fragment order:
// 0:Wself0+Wself2  1:Wn0  2:Wn2  3:Wur1  4:Wself1  5:Wn1  6:Wvr1  7:Wur2  8:Wvr2
__device__ __align__(16) uint32_t g_nfH[9 * 2048];
__device__ __align__(16) uint32_t g_nfL[9 * 2048];

// ---------------- common mma helpers ----------------
__device__ __forceinline__ void mma16816(float c[4], uint32_t a0, uint32_t a1,
                                         uint32_t a2, uint32_t a3,
                                         uint32_t b0, uint32_t b1) {
    asm volatile(
        "mma.sync.aligned.m16n8k16.row.col.f32.bf16.bf16.f32 "
        "{%0,%1,%2,%3}, {%4,%5,%6,%7}, {%8,%9}, {%0,%1,%2,%3};"
        : "+f"(c[0]), "+f"(c[1]), "+f"(c[2]), "+f"(c[3])
        : "r"(a0), "r"(a1), "r"(a2), "r"(a3), "r"(b0), "r"(b1));
}

__device__ __forceinline__ void mma16816h(float c[4], uint32_t a0, uint32_t a1,
                                          uint32_t a2, uint32_t a3,
                                          uint32_t b0, uint32_t b1) {
    asm volatile(
        "mma.sync.aligned.m16n8k16.row.col.f32.f16.f16.f32 "
        "{%0,%1,%2,%3}, {%4,%5,%6,%7}, {%8,%9}, {%0,%1,%2,%3};"
        : "+f"(c[0]), "+f"(c[1]), "+f"(c[2]), "+f"(c[3])
        : "r"(a0), "r"(a1), "r"(a2), "r"(a3), "r"(b0), "r"(b1));
}

__device__ __forceinline__ uint32_t pack_split(float x, float y, uint32_t& lo) {
    __nv_bfloat162 h = __floats2bfloat162_rn(x, y);
    float rx = x - __bfloat162float(h.x);
    float ry = y - __bfloat162float(h.y);
    __nv_bfloat162 l = __floats2bfloat162_rn(rx, ry);
    lo = *(const uint32_t*)&l;
    return *(const uint32_t*)&h;
}

__device__ __forceinline__ uint32_t h2bits(__half2 h) { return *(const uint32_t*)&h; }

// fp16 hi/lo split (W to ~2^-22)
__device__ __forceinline__ uint32_t pack_splith(float x, float y, uint32_t& lo) {
    __half2 h = __floats2half2_rn(x, y);
    float2 hf = __half22float2(h);
    __half2 l = __floats2half2_rn(x - hf.x, y - hf.y);
    lo = h2bits(l);
    return h2bits(h);
}

#define AROW 136   // bytes per A row (64 x 16-bit = 128B + 8B pad); 8B-aligned only!
#define OFF_AH 0
#define OFF_AL 17408

// stage a [128 x 64] f32 tile (optionally scaled by 1/deg) into smem as bf16 hi/lo
__device__ __forceinline__ void stageA(char* smem, const float* __restrict__ src,
                                       const float* __restrict__ deg,
                                       int rowBase, int N, int t) {
    int r = t >> 1, h = t & 1;
    int row = rowBase + r;
    char* aH = smem + OFF_AH + r * AROW + h * 64;
    char* aL = smem + OFF_AL + r * AROW + h * 64;
    if (row < N) {
        float sc = deg ? (1.f / fmaxf(__ldg(deg + row), 1.f)) : 1.f;
        const float4* pu = (const float4*)(src + (size_t)row * 64) + h * 8;
#pragma unroll
        for (int j = 0; j < 8; j++) {
            float4 a = __ldg(pu + j);
            uint32_t lo01, lo23;
            uint32_t hi01 = pack_split(a.x * sc, a.y * sc, lo01);
            uint32_t hi23 = pack_split(a.z * sc, a.w * sc, lo23);
            *(uint2*)(aH + j * 8) = make_uint2(hi01, hi23);
            *(uint2*)(aL + j * 8) = make_uint2(lo01, lo23);
        }
    } else {
#pragma unroll
        for (int j = 0; j < 8; j++) {
            *(uint2*)(aH + j * 8) = make_uint2(0u, 0u);
            *(uint2*)(aL + j * 8) = make_uint2(0u, 0u);
        }
    }
}

// acc += A(smem) @ W(frags in global, 8 n-tiles), 3-term bf16 split
__device__ __forceinline__ void mma_AB(const char* smem,
                                       const uint32_t* __restrict__ fH,
                                       const uint32_t* __restrict__ fL,
                                       int r0, int tig, int lane, float acc[8][4]) {
    const char* AH = smem + OFF_AH;
    const char* AL = smem + OFF_AL;
#pragma unroll
    for (int kt = 0; kt < 4; kt++) {
        int ka = kt * 32 + tig * 4;
        uint32_t aH0 = *(const uint32_t*)(AH + r0 * AROW + ka);
        uint32_t aH1 = *(const uint32_t*)(AH + (r0 + 8) * AROW + ka);
        uint32_t aH2 = *(const uint32_t*)(AH + r0 * AROW + ka + 16);
        uint32_t aH3 = *(const uint32_t*)(AH + (r0 + 8) * AROW + ka + 16);
        uint32_t aL0 = *(const uint32_t*)(AL + r0 * AROW + ka);
        uint32_t aL1 = *(const uint32_t*)(AL + (r0 + 8) * AROW + ka);
        uint32_t aL2 = *(const uint32_t*)(AL + r0 * AROW + ka + 16);
        uint32_t aL3 = *(const uint32_t*)(AL + (r0 + 8) * AROW + ka + 16);
#pragma unroll
        for (int nt = 0; nt < 8; nt++) {
            int fo = (kt * 8 + nt) * 64 + lane * 2;
            uint2 bH = __ldg((const uint2*)(fH + fo));
            uint2 bL = __ldg((const uint2*)(fL + fo));
            mma16816(acc[nt], aH0, aH1, aH2, aH3, bH.x, bH.y);
            mma16816(acc[nt], aH0, aH1, aH2, aH3, bL.x, bL.y);
            mma16816(acc[nt], aL0, aL1, aL2, aL3, bH.x, bH.y);
        }
    }
}

// acc2 += (acc + bias[col]) @ W(frags), with C->A fragment identity mapping
__device__ __forceinline__ void frag_gemm64(const float acc[8][4],
                                            const float* __restrict__ biasS,
                                            const uint32_t* __restrict__ fH,
                                            const uint32_t* __restrict__ fL,
                                            int tig, int lane, float acc2[8][4]) {
#pragma unroll
    for (int kt = 0; kt < 4; kt++) {
        int c0 = kt * 16 + tig * 2;
        float b00 = biasS[c0], b01 = biasS[c0 + 1];
        float b02 = biasS[c0 + 8], b03 = biasS[c0 + 9];
        uint32_t l0, l1, l2, l3;
        uint32_t a0 = pack_split(acc[2 * kt][0] + b00, acc[2 * kt][1] + b01, l0);
        uint32_t a1 = pack_split(acc[2 * kt][2] + b00, acc[2 * kt][3] + b01, l1);
        uint32_t a2 = pack_split(acc[2 * kt + 1][0] + b02, acc[2 * kt + 1][1] + b03, l2);
        uint32_t a3 = pack_split(acc[2 * kt + 1][2] + b02, acc[2 * kt + 1][3] + b03, l3);
#pragma unroll
        for (int nt = 0; nt < 8; nt++) {
            int fo = (kt * 8 + nt) * 64 + lane * 2;
            uint2 bH = __ldg((const uint2*)(fH + fo));
            uint2 bL = __ldg((const uint2*)(fL + fo));
            mma16816(acc2[nt], a0, a1, a2, a3, bH.x, bH.y);
            mma16816(acc2[nt], a0, a1, a2, a3, bL.x, bL.y);
            mma16816(acc2[nt], l0, l1, l2, l3, bH.x, bH.y);
        }
    }
}

// ---------------- zero scratch ----------------
__global__ void k_zero() {
    size_t tid = (size_t)blockIdx.x * blockDim.x + threadIdx.x;
    size_t stride = (size_t)gridDim.x * blockDim.x;
    const size_t n4 = (size_t)NUc * 16;
    float4 z = make_float4(0.f, 0.f, 0.f, 0.f);
    for (size_t j = tid; j < n4; j += stride) {
        ((float4*)g_s_social)[j] = z;
        ((float4*)g_s_ru)[j] = z;
        ((float4*)g_s_rv)[j] = z;
    }
    for (size_t j = tid; j < NUc; j += stride) {
        g_deg_s[j] = 0.f;
        g_deg_ru[j] = 0.f;
        g_deg_rv[j] = 0.f;
    }
    if (tid < 128) { g_statU[tid] = 0.0; g_statV[tid] = 0.0; g_stat1[tid] = 0.0; }
    if (tid < 32) g_stat2[tid] = 0.0;
}

// ---------------- prep: edge weight fragments (Wuv1, Wuv2) fp16 hi/lo ----------------
__global__ void k_prepW(const float* __restrict__ W1, const float* __restrict__ W2) {
    int t = threadIdx.x;
    for (int idx = t; idx < 2048; idx += 256) {
        int r = idx & 1;
        int lane = (idx >> 1) & 31;
        int grp = idx >> 6;
        int kt = grp >> 3, nt = grp & 7;
        int g = lane >> 2, tig = lane & 3;
        int n = nt * 8 + g;
        int k0 = kt * 16 + 2 * tig + (r ? 8 : 0);
        uint32_t lo;
        uint32_t hi = pack_splith(__ldg(W1 + k0 * 64 + n), __ldg(W1 + (k0 + 1) * 64 + n), lo);
        g_fragH[idx] = hi;
        g_fragL[idx] = lo;
    }
    for (int idx = t; idx < 512; idx += 256) {
        int r = idx & 1;
        int lane = (idx >> 1) & 31;
        int grp = idx >> 6;
        int kt = grp >> 1, nt = grp & 1;
        int g = lane >> 2, tig = lane & 3;
        int n = nt * 8 + g;
        int k0 = kt * 16 + 2 * tig + (r ? 8 : 0);
        uint32_t lo;
        uint32_t hi = pack_splith(__ldg(W2 + k0 * 16 + n), __ldg(W2 + (k0 + 1) * 16 + n), lo);
        g_frag2H[idx] = hi;
        g_frag2L[idx] = lo;
    }
}

// ---------------- prep: 9 node weight matrices into bf16 fragments ----------------
__global__ void k_prepN(const float* __restrict__ Ws, const float* __restrict__ Wn,
                        const float* __restrict__ Wur1_, const float* __restrict__ Wvr1_,
                        const float* __restrict__ Wur2_, const float* __restrict__ Wvr2_) {
    int t = blockIdx.x * blockDim.x + threadIdx.x;
    if (t >= 2048) return;
    int r = t & 1;
    int lane = (t >> 1) & 31;
    int grp = t >> 6;
    int kt = grp >> 3, nt = grp & 7;
    int g = lane >> 2, tig = lane & 3;
    int n = nt * 8 + g;
    int k0 = kt * 16 + 2 * tig + (r ? 8 : 0);
    const float* base[9] = {nullptr, Wn, Wn + 2 * 4096, Wur1_, Ws + 4096,
                            Wn + 4096, Wvr1_, Wur2_, Wvr2_};
#pragma unroll
    for (int m = 0; m < 9; m++) {
        float w0, w1;
        if (m == 0) {
            w0 = __ldg(Ws + k0 * 64 + n) + __ldg(Ws + 2 * 4096 + k0 * 64 + n);
            w1 = __ldg(Ws + (k0 + 1) * 64 + n) + __ldg(Ws + 2 * 4096 + (k0 + 1) * 64 + n);
        } else {
            const float* W = base[m];
            w0 = __ldg(W + k0 * 64 + n);
            w1 = __ldg(W + (k0 + 1) * 64 + n);
        }
        uint32_t lo;
        uint32_t hi = pack_split(w0, w1, lo);
        g_nfH[m * 2048 + t] = hi;
        g_nfL[m * 2048 + t] = lo;
    }
}

// ---------------- social scatter: acc[dst] += feat[src] via red.v4 ----------------
__global__ __launch_bounds__(256) void k_scatter(
    const float* __restrict__ feat, const int* __restrict__ src,
    const int* __restrict__ dst, float* __restrict__ acc,
    float* __restrict__ deg, int E) {
    int g = blockIdx.x * blockDim.x + threadIdx.x;
    int e = g >> 4;
    int q = g & 15;
    if (e >= E) return;
    int s = __ldg(src + e);
    int d = __ldg(dst + e);
    float4 v = __ldg((const float4*)feat + (size_t)s * 16 + q);
    float* p = acc + (size_t)d * 64 + q * 4;
    asm volatile("red.global.add.v4.f32 [%0], {%1, %2, %3, %4};"
                 :: "l"(p), "f"(v.x), "f"(v.y), "f"(v.z), "f"(v.w) : "memory");
    if (q == 0) atomicAdd(deg + d, 1.0f);
}

// ---------------- fused rates scatter: both directions, one index read ----------------
__global__ __launch_bounds__(256) void k_scatter2(
    const float* __restrict__ u2e, const float* __restrict__ v2e,
    const int* __restrict__ rs, const int* __restrict__ rd,
    float* __restrict__ s_rv, float* __restrict__ s_ru,
    float* __restrict__ deg_rv, float* __restrict__ deg_ru) {
    int g = blockIdx.x * blockDim.x + threadIdx.x;
    int e = g >> 4;
    int q = g & 15;
    if (e >= ERc) return;
    int s = __ldg(rs + e);
    int d = __ldg(rd + e);
    float4 a = __ldg((const float4*)u2e + (size_t)s * 16 + q);
    float4 b = __ldg((const float4*)v2e + (size_t)d * 16 + q);
    float* p1 = s_rv + (size_t)d * 64 + q * 4;
    float* p2 = s_ru + (size_t)s * 64 + q * 4;
    asm volatile("red.global.add.v4.f32 [%0], {%1, %2, %3, %4};"
                 :: "l"(p1), "f"(a.x), "f"(a.y), "f"(a.z), "f"(a.w) : "memory");
    asm volatile("red.global.add.v4.f32 [%0], {%1, %2, %3, %4};"
                 :: "l"(p2), "f"(b.x), "f"(b.y), "f"(b.z), "f"(b.w) : "memory");
    if (q == 0) {
        atomicAdd(deg_rv + d, 1.0f);
        atomicAdd(deg_ru + s, 1.0f);
    }
}

// ---------------- fused user: combine (3 tensor GEMMs) + tower1 (frag GEMM) + stats ----------------
__global__ __launch_bounds__(256)
void k_user1_mma(const float* __restrict__ u2e, const float* __restrict__ bself,
                 const float* __restrict__ b1, float* __restrict__ out,
                 double* __restrict__ stats) {
    __shared__ __align__(16) char smem[34816];
    __shared__ float biasS[64];
    __shared__ float ssum[64], ssq[64];
    int t = threadIdx.x, lane = t & 31, w = t >> 5;
    int g = lane >> 2, tig = lane & 3;
    int r0 = w * 16 + g;
    int rowBase = blockIdx.x * 128;
    if (t < 64) {
        biasS[t] = __ldg(bself + t) + __ldg(bself + 128 + t);
        ssum[t] = 0.f;
        ssq[t] = 0.f;
    }

    float acc[8][4] = {};
    stageA(smem, u2e, nullptr, rowBase, NUc, t);
    __syncthreads();
    mma_AB(smem, g_nfH + 0 * 2048, g_nfL + 0 * 2048, r0, tig, lane, acc);
    __syncthreads();
    stageA(smem, g_s_social, g_deg_s, rowBase, NUc, t);
    __syncthreads();
    mma_AB(smem, g_nfH + 1 * 2048, g_nfL + 1 * 2048, r0, tig, lane, acc);
    __syncthreads();
    stageA(smem, g_s_ru, g_deg_ru, rowBase, NUc, t);
    __syncthreads();
    mma_AB(smem, g_nfH + 2 * 2048, g_nfL + 2 * 2048, r0, tig, lane, acc);
    __syncthreads();

    float acc2[8][4] = {};
    frag_gemm64(acc, biasS, g_nfH + 3 * 2048, g_nfL + 3 * 2048, tig, lane, acc2);

    float* stage = (float*)smem;
#pragma unroll
    for (int nt = 0; nt < 8; nt++) {
        int c = nt * 8 + tig * 2;
        stage[r0 * 65 + c] = acc2[nt][0];
        stage[r0 * 65 + c + 1] = acc2[nt][1];
        stage[(r0 + 8) * 65 + c] = acc2[nt][2];
        stage[(r0 + 8) * 65 + c + 1] = acc2[nt][3];
    }
    __syncthreads();

    int c4 = (t & 15) * 4;
    float4 bias = *(const float4*)(b1 + c4);
    float cs[4] = {0, 0, 0, 0}, cq[4] = {0, 0, 0, 0};
#pragma unroll
    for (int i = 0; i < 8; i++) {
        int r = (t >> 4) + 16 * i;
        int row = rowBase + r;
        if (row < NUc) {
            const float* sp = stage + r * 65 + c4;
            float v0 = sp[0] + bias.x, v1 = sp[1] + bias.y;
            float v2 = sp[2] + bias.z, v3 = sp[3] + bias.w;
            *(float4*)(out + (size_t)row * 64 + c4) = make_float4(v0, v1, v2, v3);
            cs[0] += v0; cq[0] += v0 * v0;
            cs[1] += v1; cq[1] += v1 * v1;
            cs[2] += v2; cq[2] += v2 * v2;
            cs[3] += v3; cq[3] += v3 * v3;
        }
    }
#pragma unroll
    for (int j = 0; j < 4; j++) {
        atomicAdd(&ssum[c4 + j], cs[j]);
        atomicAdd(&ssq[c4 + j], cq[j]);
    }
    __syncthreads();
    if (t < 64) atomicAdd(&stats[t], (double)ssum[t]);
    else if (t < 128) atomicAdd(&stats[t], (double)ssq[t - 64]);
}

// ---------------- fused item: combine (2 tensor GEMMs) + tower1 + stats ----------------
__global__ __launch_bounds__(256)
void k_item1_mma(const float* __restrict__ v2e, const float* __restrict__ bself,
                 const float* __restrict__ b1, float* __restrict__ out,
                 double* __restrict__ stats) {
    __shared__ __align__(16) char smem[34816];
    __shared__ float biasS[64];
    __shared__ float ssum[64], ssq[64];
    int t = threadIdx.x, lane = t & 31, w = t >> 5;
    int g = lane >> 2, tig = lane & 3;
    int r0 = w * 16 + g;
    int rowBase = blockIdx.x * 128;
    if (t < 64) {
        biasS[t] = __ldg(bself + 64 + t);
        ssum[t] = 0.f;
        ssq[t] = 0.f;
    }

    float acc[8][4] = {};
    stageA(smem, v2e, nullptr, rowBase, NVc, t);
    __syncthreads();
    mma_AB(smem, g_nfH + 4 * 2048, g_nfL + 4 * 2048, r0, tig, lane, acc);
    __syncthreads();
    stageA(smem, g_s_rv, g_deg_rv, rowBase, NVc, t);
    __syncthreads();
    mma_AB(smem, g_nfH + 5 * 2048, g_nfL + 5 * 2048, r0, tig, lane, acc);
    __syncthreads();

    float acc2[8][4] = {};
    frag_gemm64(acc, biasS, g_nfH + 6 * 2048, g_nfL + 6 * 2048, tig, lane, acc2);

    float* stage = (float*)smem;
#pragma unroll
    for (int nt = 0; nt < 8; nt++) {
        int c = nt * 8 + tig * 2;
        stage[r0 * 65 + c] = acc2[nt][0];
        stage[r0 * 65 + c + 1] = acc2[nt][1];
        stage[(r0 + 8) * 65 + c] = acc2[nt][2];
        stage[(r0 + 8) * 65 + c + 1] = acc2[nt][3];
    }
    __syncthreads();

    int c4 = (t & 15) * 4;
    float4 bias = *(const float4*)(b1 + c4);
    float cs[4] = {0, 0, 0, 0}, cq[4] = {0, 0, 0, 0};
#pragma unroll
    for (int i = 0; i < 8; i++) {
        int r = (t >> 4) + 16 * i;
        int row = rowBase + r;
        if (row < NVc) {
            const float* sp = stage + r * 65 + c4;
            float v0 = sp[0] + bias.x, v1 = sp[1] + bias.y;
            float v2 = sp[2] + bias.z, v3 = sp[3] + bias.w;
            *(float4*)(out + (size_t)row * 64 + c4) = make_float4(v0, v1, v2, v3);
            cs[0] += v0; cq[0] += v0 * v0;
            cs[1] += v1; cq[1] += v1 * v1;
            cs[2] += v2; cq[2] += v2 * v2;
            cs[3] += v3; cq[3] += v3 * v3;
        }
    }
#pragma unroll
    for (int j = 0; j < 4; j++) {
        atomicAdd(&ssum[c4 + j], cs[j]);
        atomicAdd(&ssq[c4 + j], cq[j]);
    }
    __syncthreads();
    if (t < 64) atomicAdd(&stats[t], (double)ssum[t]);
    else if (t < 128) atomicAdd(&stats[t], (double)ssq[t - 64]);
}

// ---------------- BN finalize ----------------
__global__ void k_fin(const double* __restrict__ stats, const float* __restrict__ gamma,
                      const float* __restrict__ beta, float* __restrict__ aff,
                      int C, float invN) {
    int c = threadIdx.x;
    if (c < C) {
        float mean = (float)(stats[c] * (double)invN);
        float ex2 = (float)(stats[C + c] * (double)invN);
        float var = ex2 - mean * mean;
        float a = gamma[c] * rsqrtf(var + 1e-5f);
        aff[c] = a;
        aff[C + c] = beta[c] - mean * a;
    }
}

// ---------------- tower2 on tensor cores: x = relu(t*a+c) @ W2 + b2 -> fp16 out ----------------
__global__ __launch_bounds__(256)
void k_tower2_mma(const float* __restrict__ in, const float* __restrict__ aff,
                  const uint32_t* __restrict__ fH, const uint32_t* __restrict__ fL,
                  const float* __restrict__ b2, __half* __restrict__ out, int N) {
    __shared__ float stage[128 * 65];
    __shared__ float affS[128];
    int t = threadIdx.x, lane = t & 31, w = t >> 5;
    int g = lane >> 2, tig = lane & 3;
    int r0 = w * 16 + g;
    int rowBase = blockIdx.x * 128;
    if (t < 128) affS[t] = __ldg(aff + t);
    __syncthreads();

    int e0 = rowBase + r0, e1 = e0 + 8;
    bool ok0 = e0 < N, ok1 = e1 < N;

    float acc2[8][4] = {};
#pragma unroll
    for (int kt = 0; kt < 4; kt++) {
        int c0 = kt * 16 + tig * 2;
        float2 z = make_float2(0.f, 0.f);
        float2 y00 = ok0 ? *(const float2*)(in + (size_t)e0 * 64 + c0) : z;
        float2 y10 = ok0 ? *(const float2*)(in + (size_t)e0 * 64 + c0 + 8) : z;
        float2 y01 = ok1 ? *(const float2*)(in + (size_t)e1 * 64 + c0) : z;
        float2 y11 = ok1 ? *(const float2*)(in + (size_t)e1 * 64 + c0 + 8) : z;
        float s0 = affS[c0], h0 = affS[64 + c0];
        float s1 = affS[c0 + 1], h1 = affS[64 + c0 + 1];
        float s2 = affS[c0 + 8], h2 = affS[64 + c0 + 8];
        float s3 = affS[c0 + 9], h3 = affS[64 + c0 + 9];
        float v00 = fmaxf(y00.x * s0 + h0, 0.f), v01 = fmaxf(y00.y * s1 + h1, 0.f);
        float v10 = fmaxf(y01.x * s0 + h0, 0.f), v11 = fmaxf(y01.y * s1 + h1, 0.f);
        float w00 = fmaxf(y10.x * s2 + h2, 0.f), w01 = fmaxf(y10.y * s3 + h3, 0.f);
        float w10 = fmaxf(y11.x * s2 + h2, 0.f), w11 = fmaxf(y11.y * s3 + h3, 0.f);
        uint32_t l0, l1, l2, l3;
        uint32_t a0 = pack_split(v00, v01, l0);
        uint32_t a1 = pack_split(v10, v11, l1);
        uint32_t a2 = pack_split(w00, w01, l2);
        uint32_t a3 = pack_split(w10, w11, l3);
#pragma unroll
        for (int nt = 0; nt < 8; nt++) {
            int fo = (kt * 8 + nt) * 64 + lane * 2;
            uint2 bH = __ldg((const uint2*)(fH + fo));
            uint2 bL = __ldg((const uint2*)(fL + fo));
            mma16816(acc2[nt], a0, a1, a2, a3, bH.x, bH.y);
            mma16816(acc2[nt], a0, a1, a2, a3, bL.x, bL.y);
            mma16816(acc2[nt], l0, l1, l2, l3, bH.x, bH.y);
        }
    }

#pragma unroll
    for (int nt = 0; nt < 8; nt++) {
        int c = nt * 8 + tig * 2;
        stage[r0 * 65 + c] = acc2[nt][0];
        stage[r0 * 65 + c + 1] = acc2[nt][1];
        stage[(r0 + 8) * 65 + c] = acc2[nt][2];
        stage[(r0 + 8) * 65 + c + 1] = acc2[nt][3];
    }
    __syncthreads();

    int c4 = (t & 15) * 4;
    float4 bias = *(const float4*)(b2 + c4);
#pragma unroll
    for (int i = 0; i < 8; i++) {
        int r = (t >> 4) + 16 * i;
        int row = rowBase + r;
        if (row < N) {
            const float* sp = stage + r * 65 + c4;
            __half2 ha = __floats2half2_rn(sp[0] + bias.x, sp[1] + bias.y);
            __half2 hb = __floats2half2_rn(sp[2] + bias.z, sp[3] + bias.w);
            *(uint2*)(out + (size_t)row * 64 + c4) = make_uint2(h2bits(ha), h2bits(hb));
        }
    }
}

// ================= edge pass 1: fp16 gather -> fp16 A, f16 mma, 2-term W split =================
#define E1_SMEM 33792
#define E1_OFF_A 0        // fp16 A: 128 rows x 136B = 17408
#define E1_OFF_BH 17408   // Whi fp16 frags: 8192
#define E1_OFF_BL 25600   // Wlo fp16 frags: 8192

__global__ __launch_bounds__(256)
void k_edge1_mma(const __half* __restrict__ xu, const __half* __restrict__ xv,
                 const int* __restrict__ es, const int* __restrict__ ed,
                 const float* __restrict__ b, __half* __restrict__ out,
                 double* __restrict__ stats) {
    extern __shared__ __align__(16) char smem[];
    __shared__ float ssum[64], ssq[64];
    int t = threadIdx.x, lane = t & 31, w = t >> 5;
    int rowBase = blockIdx.x * 128;
    if (t < 64) { ssum[t] = 0.f; ssq[t] = 0.f; }

    // ---- B fragments (fp16 hi/lo): 2048 u32 each = 512 uint4 ----
    {
        const uint4* sH = (const uint4*)g_fragH;
        const uint4* sL = (const uint4*)g_fragL;
        uint4* dH = (uint4*)(smem + E1_OFF_BH);
        uint4* dL = (uint4*)(smem + E1_OFF_BL);
        dH[t] = __ldg(sH + t);
        dH[t + 256] = __ldg(sH + t + 256);
        dL[t] = __ldg(sL + t);
        dL[t + 256] = __ldg(sL + t + 256);
    }
    // ---- A: gather x_u*x_v, single fp16 tile (8B stores: AROW=136 is only 8-aligned) ----
    {
        int r = t >> 1, h = t & 1;
        int e = rowBase + r;
        char* aA = smem + E1_OFF_A + r * AROW + h * 64;
        if (e < ERc) {
            int s = __ldg(es + e), d = __ldg(ed + e);
            const uint4* pu = (const uint4*)(xu + (size_t)s * 64) + h * 4;   // 8 halves per uint4
            const uint4* pv = (const uint4*)(xv + (size_t)d * 64) + h * 4;
#pragma unroll
            for (int j = 0; j < 4; j++) {
                uint4 A = __ldg(pu + j), V = __ldg(pv + j);
                float2 a0 = __half22float2(*(const __half2*)&A.x);
                float2 a1 = __half22float2(*(const __half2*)&A.y);
                float2 a2 = __half22float2(*(const __half2*)&A.z);
                float2 a3 = __half22float2(*(const __half2*)&A.w);
                float2 v0 = __half22float2(*(const __half2*)&V.x);
                float2 v1 = __half22float2(*(const __half2*)&V.y);
                float2 v2 = __half22float2(*(const __half2*)&V.z);
                float2 v3 = __half22float2(*(const __half2*)&V.w);
                __half2 p0 = __floats2half2_rn(a0.x * v0.x, a0.y * v0.y);
                __half2 p1 = __floats2half2_rn(a1.x * v1.x, a1.y * v1.y);
                __half2 p2 = __floats2half2_rn(a2.x * v2.x, a2.y * v2.y);
                __half2 p3 = __floats2half2_rn(a3.x * v3.x, a3.y * v3.y);
                *(uint2*)(aA + j * 16) = make_uint2(h2bits(p0), h2bits(p1));
                *(uint2*)(aA + j * 16 + 8) = make_uint2(h2bits(p2), h2bits(p3));
            }
        } else {
#pragma unroll
            for (int j = 0; j < 8; j++)
                *(uint2*)(aA + j * 8) = make_uint2(0u, 0u);
        }
    }
    __syncthreads();

    // ---- mma mainloop: D = A*Whi + A*Wlo (A exact fp16) ----
    int g = lane >> 2, tig = lane & 3;
    int r0 = w * 16 + g;
    float acc[8][4] = {};
    const char* AA = smem + E1_OFF_A;
#pragma unroll
    for (int kt = 0; kt < 4; kt++) {
        int ka = kt * 32 + tig * 4;
        uint32_t a0 = *(const uint32_t*)(AA + r0 * AROW + ka);
        uint32_t a1 = *(const uint32_t*)(AA + (r0 + 8) * AROW + ka);
        uint32_t a2 = *(const uint32_t*)(AA + r0 * AROW + ka + 16);
        uint32_t a3 = *(const uint32_t*)(AA + (r0 + 8) * AROW + ka + 16);
#pragma unroll
        for (int nt = 0; nt < 8; nt++) {
            uint32_t boff = ((kt * 8 + nt) * 64 + lane * 2) * 4;
            uint2 bH = *(const uint2*)(smem + E1_OFF_BH + boff);
            uint2 bL = *(const uint2*)(smem + E1_OFF_BL + boff);
            mma16816h(acc[nt], a0, a1, a2, a3, bH.x, bH.y);
            mma16816h(acc[nt], a0, a1, a2, a3, bL.x, bL.y);
        }
    }
    __syncthreads();

    // ---- stage C to smem (stride-65 f32, 33280B <= 33792B) ----
    float* stage = (float*)smem;
#pragma unroll
    for (int nt = 0; nt < 8; nt++) {
        int c = nt * 8 + tig * 2;
        stage[r0 * 65 + c] = acc[nt][0];
        stage[r0 * 65 + c + 1] = acc[nt][1];
        stage[(r0 + 8) * 65 + c] = acc[nt][2];
        stage[(r0 + 8) * 65 + c + 1] = acc[nt][3];
    }
    __syncthreads();

    // ---- coalesced fp16 store + bias + stats ----
    int c4 = (t & 15) * 4;
    float4 bias = *(const float4*)(b + c4);
    float cs[4] = {0, 0, 0, 0}, cq[4] = {0, 0, 0, 0};
#pragma unroll
    for (int i = 0; i < 8; i++) {
        int r = (t >> 4) + 16 * i;
        int e = rowBase + r;
        if (e < ERc) {
            const float* sp = stage + r * 65 + c4;
            float v0 = sp[0] + bias.x, v1 = sp[1] + bias.y;
            float v2 = sp[2] + bias.z, v3 = sp[3] + bias.w;
            __half2 ha = __floats2half2_rn(v0, v1);
            __half2 hb = __floats2half2_rn(v2, v3);
            *(uint2*)(out + (size_t)e * 64 + c4) = make_uint2(h2bits(ha), h2bits(hb));
            cs[0] += v0; cq[0] += v0 * v0;
            cs[1] += v1; cq[1] += v1 * v1;
            cs[2] += v2; cq[2] += v2 * v2;
            cs[3] += v3; cq[3] += v3 * v3;
        }
    }
#pragma unroll
    for (int j = 0; j < 4; j++) {
        atomicAdd(&ssum[c4 + j], cs[j]);
        atomicAdd(&ssq[c4 + j], cq[j]);
    }
    __syncthreads();
    if (t < 64) atomicAdd(&stats[t], (double)ssum[t]);
    else if (t < 128) atomicAdd(&stats[t], (double)ssq[t - 64]);
}

// ================= edge pass 2: fp16 y1 in, f16 mma, 2-term W2 split =================
__global__ __launch_bounds__(256)
void k_edge2_mma(const __half* __restrict__ y1, const float* __restrict__ aff,
                 const float* __restrict__ b2, float* __restrict__ y2,
                 double* __restrict__ stats) {
    __shared__ float affS[128];
    __shared__ __align__(16) uint32_t f2H[512], f2L[512];
    __shared__ float ssum[16], ssq[16];
    int t = threadIdx.x, lane = t & 31, w = t >> 5;
    int rowBase = blockIdx.x * 128;
    if (t < 128) affS[t] = __ldg(aff + t);
    if (t < 16) { ssum[t] = 0.f; ssq[t] = 0.f; }
    {
        ((uint2*)f2H)[t] = __ldg((const uint2*)g_frag2H + t);
        ((uint2*)f2L)[t] = __ldg((const uint2*)g_frag2L + t);
    }
    __syncthreads();

    int g = lane >> 2, tig = lane & 3;
    int r0 = w * 16 + g;
    int e0 = rowBase + r0, e1 = e0 + 8;
    bool ok0 = e0 < ERc, ok1 = e1 < ERc;

    float acc2[2][4] = {};
#pragma unroll
    for (int kt = 0; kt < 4; kt++) {
        int c0 = kt * 16 + tig * 2;
        float2 z = make_float2(0.f, 0.f);
        float2 y00 = ok0 ? __half22float2(*(const __half2*)(y1 + (size_t)e0 * 64 + c0)) : z;
        float2 y10 = ok1 ? __half22float2(*(const __half2*)(y1 + (size_t)e1 * 64 + c0)) : z;
        float2 y01 = ok0 ? __half22float2(*(const __half2*)(y1 + (size_t)e0 * 64 + c0 + 8)) : z;
        float2 y11 = ok1 ? __half22float2(*(const __half2*)(y1 + (size_t)e1 * 64 + c0 + 8)) : z;
        float s0 = affS[c0], h0 = affS[64 + c0];
        float s1 = affS[c0 + 1], h1 = affS[64 + c0 + 1];
        float s2 = affS[c0 + 8], h2 = affS[64 + c0 + 8];
        float s3 = affS[c0 + 9], h3 = affS[64 + c0 + 9];
        uint32_t a0 = h2bits(__floats2half2_rn(fmaxf(y00.x * s0 + h0, 0.f),
                                               fmaxf(y00.y * s1 + h1, 0.f)));
        uint32_t a1 = h2bits(__floats2half2_rn(fmaxf(y10.x * s0 + h0, 0.f),
                                               fmaxf(y10.y * s1 + h1, 0.f)));
        uint32_t a2 = h2bits(__floats2half2_rn(fmaxf(y01.x * s2 + h2, 0.f),
                                               fmaxf(y01.y * s3 + h3, 0.f)));
        uint32_t a3 = h2bits(__floats2half2_rn(fmaxf(y11.x * s2 + h2, 0.f),
                                               fmaxf(y11.y * s3 + h3, 0.f)));
#pragma unroll
        for (int n2 = 0; n2 < 2; n2++) {
            int fo = (kt * 2 + n2) * 64 + lane * 2;
            uint2 bH = *(const uint2*)(f2H + fo);
            uint2 bL = *(const uint2*)(f2L + fo);
            mma16816h(acc2[n2], a0, a1, a2, a3, bH.x, bH.y);
            mma16816h(acc2[n2], a0, a1, a2, a3, bL.x, bL.y);
        }
    }

    float cs[4] = {0, 0, 0, 0}, cq[4] = {0, 0, 0, 0};
#pragma unroll
    for (int n2 = 0; n2 < 2; n2++) {
        int c = n2 * 8 + tig * 2;
        float bx = __ldg(b2 + c), by = __ldg(b2 + c + 1);
        float u0 = acc2[n2][0] + bx, u1 = acc2[n2][1] + by;
        float u2 = acc2[n2][2] + bx, u3 = acc2[n2][3] + by;
        if (ok0) {
            *(float2*)(y2 + (size_t)e0 * 16 + c) = make_float2(u0, u1);
            cs[n2 * 2] += u0; cq[n2 * 2] += u0 * u0;
            cs[n2 * 2 + 1] += u1; cq[n2 * 2 + 1] += u1 * u1;
        }
        if (ok1) {
            *(float2*)(y2 + (size_t)e1 * 16 + c) = make_float2(u2, u3);
            cs[n2 * 2] += u2; cq[n2 * 2] += u2 * u2;
            cs[n2 * 2 + 1] += u3; cq[n2 * 2 + 1] += u3 * u3;
        }
    }
#pragma unroll
    for (int n2 = 0; n2 < 2; n2++) {
#pragma unroll
        for (int j = 0; j < 2; j++) {
            int c = n2 * 8 + tig * 2 + j;
            atomicAdd(&ssum[c], cs[n2 * 2 + j]);
            atomicAdd(&ssq[c], cq[n2 * 2 + j]);
        }
    }
    __syncthreads();
    if (t < 16) atomicAdd(&stats[t], (double)ssum[t]);
    else if (t < 32) atomicAdd(&stats[t], (double)ssq[t - 16]);
}

// ---------------- edge pass 3: scores = relu(y2*a2+c2) . w3 + b3 ----------------
__global__ __launch_bounds__(256) void k_edge3(
    const float* __restrict__ y2, const float* __restrict__ aff,
    const float* __restrict__ w3, const float* __restrict__ b3,
    float* __restrict__ out) {
    int e = blockIdx.x * blockDim.x + threadIdx.x;
    if (e >= ERc) return;
    const float4* p = (const float4*)(y2 + (size_t)e * 16);
    float s = 0.f;
#pragma unroll
    for (int j = 0; j < 4; j++) {
        float4 v = __ldg(p + j);
        float4 a = *(const float4*)(aff + 4 * j);
        float4 c = *(const float4*)(aff + 16 + 4 * j);
        float4 w = *(const float4*)(w3 + 4 * j);
        s += fmaxf(v.x * a.x + c.x, 0.f) * w.x;
        s += fmaxf(v.y * a.y + c.y, 0.f) * w.y;
        s += fmaxf(v.z * a.z + c.z, 0.f) * w.z;
        s += fmaxf(v.w * a.w + c.w, 0.f) * w.w;
    }
    out[e] = s + __ldg(b3);
}

// ---------------- host ----------------
extern "C" void kernel_launch(void* const* d_in, const int* in_sizes, int n_in,
                              void* d_out, int out_size) {
    const float* u2e     = (const float*)d_in[0];
    const float* v2e     = (const float*)d_in[1];
    const float* W_self  = (const float*)d_in[2];
    const float* b_self  = (const float*)d_in[3];
    const float* W_neigh = (const float*)d_in[4];
    const float* Wur1 = (const float*)d_in[5];
    const float* bur1 = (const float*)d_in[6];
    const float* Wur2 = (const float*)d_in[7];
    const float* bur2 = (const float*)d_in[8];
    const float* Wvr1 = (const float*)d_in[9];
    const float* bvr1 = (const float*)d_in[10];
    const float* Wvr2 = (const float*)d_in[11];
    const float* bvr2 = (const float*)d_in[12];
    const float* Wuv1 = (const float*)d_in[13];
    const float* buv1 = (const float*)d_in[14];
    const float* Wuv2 = (const float*)d_in[15];
    const float* buv2 = (const float*)d_in[16];
    const float* Wuv3 = (const float*)d_in[17];
    const float* buv3 = (const float*)d_in[18];
    const float* bn_gamma  = (const float*)d_in[19];
    const float* bn_beta   = (const float*)d_in[20];
    const float* bn4_gamma = (const float*)d_in[21];
    const float* bn4_beta  = (const float*)d_in[22];
    const int* social_src = (const int*)d_in[23];
    const int* social_dst = (const int*)d_in[24];
    const int* rates_src  = (const int*)d_in[25];
    const int* rates_dst  = (const int*)d_in[26];
    float* out = (float*)d_out;

    void *p_ssoc, *p_sru, *p_srv, *p_degs, *p_degru, *p_degrv;
    void *p_tu, *p_tv, *p_xu, *p_xv, *p_y1, *p_y2;
    void *p_stU, *p_stV, *p_st1, *p_st2, *p_aU, *p_aV, *p_a1, *p_a2;
    void *p_nfH, *p_nfL;
    cudaGetSymbolAddress(&p_ssoc, g_s_social);
    cudaGetSymbolAddress(&p_sru, g_s_ru);
    cudaGetSymbolAddress(&p_srv, g_s_rv);
    cudaGetSymbolAddress(&p_degs, g_deg_s);
    cudaGetSymbolAddress(&p_degru, g_deg_ru);
    cudaGetSymbolAddress(&p_degrv, g_deg_rv);
    cudaGetSymbolAddress(&p_tu, g_tu);
    cudaGetSymbolAddress(&p_tv, g_tv);
    cudaGetSymbolAddress(&p_xu, g_xuh);
    cudaGetSymbolAddress(&p_xv, g_xvh);
    cudaGetSymbolAddress(&p_y1, g_y1h);
    cudaGetSymbolAddress(&p_y2, g_y2);
    cudaGetSymbolAddress(&p_stU, g_statU);
    cudaGetSymbolAddress(&p_stV, g_statV);
    cudaGetSymbolAddress(&p_st1, g_stat1);
    cudaGetSymbolAddress(&p_st2, g_stat2);
    cudaGetSymbolAddress(&p_aU, g_affU);
    cudaGetSymbolAddress(&p_aV, g_affV);
    cudaGetSymbolAddress(&p_a1, g_aff1);
    cudaGetSymbolAddress(&p_a2, g_aff2);
    cudaGetSymbolAddress(&p_nfH, g_nfH);
    cudaGetSymbolAddress(&p_nfL, g_nfL);

    cudaFuncSetAttribute(k_edge1_mma, cudaFuncAttributeMaxDynamicSharedMemorySize, E1_SMEM);

    const int NBn = (NUc + 127) / 128;   // 391 (NV == NU)
    const int NB_E1 = (ERc + 127) / 128;

    k_zero<<<2048, 256>>>();
    k_prepW<<<1, 256>>>(Wuv1, Wuv2);
    k_prepN<<<8, 256>>>(W_self, W_neigh, Wur1, Wvr1, Wur2, Wvr2);

    // segment sums: social (u->u) separate; both rates directions fused
    k_scatter<<<ESc / 16, 256>>>(u2e, social_src, social_dst,
                                 (float*)p_ssoc, (float*)p_degs, ESc);
    k_scatter2<<<ERc / 16, 256>>>(u2e, v2e, rates_src, rates_dst,
                                  (float*)p_srv, (float*)p_sru,
                                  (float*)p_degrv, (float*)p_degru);

    k_user1_mma<<<NBn, 256>>>(u2e, b_self, bur1, (float*)p_tu, (double*)p_stU);
    k_item1_mma<<<NBn, 256>>>(v2e, b_self, bvr1, (float*)p_tv, (double*)p_stV);
    k_fin<<<1, 64>>>((const double*)p_stU, bn_gamma + 0, bn_beta + 0, (float*)p_aU, 64, 1.0f / NUc);
    k_fin<<<1, 64>>>((const double*)p_stV, bn_gamma + 64, bn_beta + 64, (float*)p_aV, 64, 1.0f / NVc);
    k_tower2_mma<<<NBn, 256>>>((const float*)p_tu, (const float*)p_aU,
                               (const uint32_t*)p_nfH + 7 * 2048, (const uint32_t*)p_nfL + 7 * 2048,
                               bur2, (__half*)p_xu, NUc);
    k_tower2_mma<<<NBn, 256>>>((const float*)p_tv, (const float*)p_aV,
                               (const uint32_t*)p_nfH + 8 * 2048, (const uint32_t*)p_nfL + 8 * 2048,
                               bvr2, (__half*)p_xv, NVc);

    k_edge1_mma<<<NB_E1, 256, E1_SMEM>>>((const __half*)p_xu, (const __half*)p_xv,
                                         rates_src, rates_dst, buv1,
                                         (__half*)p_y1, (double*)p_st1);
    k_fin<<<1, 64>>>((const double*)p_st1, bn_gamma + 128, bn_beta + 128, (float*)p_a1, 64, 1.0f / ERc);
    k_edge2_mma<<<NB_E1, 256>>>((const __half*)p_y1, (const float*)p_a1, buv2,
                                (float*)p_y2, (double*)p_st2);
    k_fin<<<1, 16>>>((const double*)p_st2, bn4_gamma, bn4_beta, (float*)p_a2, 16, 1.0f / ERc);
    k_edge3<<<(ERc + 255) / 256, 256>>>((const float*)p_y2, (const float*)p_a2, Wuv3, buv3, out);

    (void)in_sizes; (void)n_in; (void)out_size;
}

// round 16
// speedup vs baseline: 1.7663x; 1.0437x over previous
#include <cuda_runtime.h>
#include <cuda_bf16.h>
#include <cuda_fp16.h>
#include <cstdint>

#define NUc 50000
#define NVc 50000
#define ESc 800000
#define ERc 1000000

// ---------------- device scratch (no allocations allowed) ----------------
__device__ __align__(16) float g_s_social[(size_t)NUc * 64];
__device__ __align__(16) float g_s_ru[(size_t)NUc * 64];
__device__ __align__(16) float g_s_rv[(size_t)NVc * 64];
__device__ float g_deg_s[NUc];
__device__ float g_deg_ru[NUc];
__device__ float g_deg_rv[NVc];
__device__ __align__(16) float g_tu[(size_t)NUc * 64];
__device__ __align__(16) float g_tv[(size_t)NVc * 64];
__device__ __align__(16) __half g_xuh[(size_t)NUc * 64];   // fp16 x tables
__device__ __align__(16) __half g_xvh[(size_t)NVc * 64];
__device__ __align__(16) __half g_y1h[(size_t)ERc * 64];   // fp16 y1 (128 MB)
__device__ __align__(16) float g_y2[(size_t)ERc * 16];     // 64 MB
__device__ double g_statU[128];
__device__ double g_statV[128];
__device__ double g_stat1[128];
__device__ double g_stat2[32];
__device__ __align__(16) float g_affU[128];
__device__ __align__(16) float g_affV[128];
__device__ __align__(16) float g_aff1[128];
__device__ __align__(16) float g_aff2[32];
// Wuv1 pre-packed per-lane m16n8k16 B-fragment order, fp16 hi/lo split
__device__ __align__(16) uint32_t g_fragH[2048];
__device__ __align__(16) uint32_t g_fragL[2048];
// Wuv2 (64x16) fp16 hi/lo: (kt*2+nt)*64 + lane*2 + r
__device__ __align__(16) uint32_t g_frag2H[512];
__device__ __align__(16) uint32_t g_frag2L[512];
// 9 node matrices (64x64 each) in bf16 hi/lo B-fragment order:
// 0:Wself0+Wself2  1:Wn0  2:Wn2  3:Wur1  4:Wself1  5:Wn1  6:Wvr1  7:Wur2  8:Wvr2
__device__ __align__(16) uint32_t g_nfH[9 * 2048];
__device__ __align__(16) uint32_t g_nfL[9 * 2048];

// ---------------- common mma helpers ----------------
__device__ __forceinline__ void mma16816(float c[4], uint32_t a0, uint32_t a1,
                                         uint32_t a2, uint32_t a3,
                                         uint32_t b0, uint32_t b1) {
    asm volatile(
        "mma.sync.aligned.m16n8k16.row.col.f32.bf16.bf16.f32 "
        "{%0,%1,%2,%3}, {%4,%5,%6,%7}, {%8,%9}, {%0,%1,%2,%3};"
        : "+f"(c[0]), "+f"(c[1]), "+f"(c[2]), "+f"(c[3])
        : "r"(a0), "r"(a1), "r"(a2), "r"(a3), "r"(b0), "r"(b1));
}

__device__ __forceinline__ void mma16816h(float c[4], uint32_t a0, uint32_t a1,
                                          uint32_t a2, uint32_t a3,
                                          uint32_t b0, uint32_t b1) {
    asm volatile(
        "mma.sync.aligned.m16n8k16.row.col.f32.f16.f16.f32 "
        "{%0,%1,%2,%3}, {%4,%5,%6,%7}, {%8,%9}, {%0,%1,%2,%3};"
        : "+f"(c[0]), "+f"(c[1]), "+f"(c[2]), "+f"(c[3])
        : "r"(a0), "r"(a1), "r"(a2), "r"(a3), "r"(b0), "r"(b1));
}

__device__ __forceinline__ uint32_t pack_split(float x, float y, uint32_t& lo) {
    __nv_bfloat162 h = __floats2bfloat162_rn(x, y);
    float rx = x - __bfloat162float(h.x);
    float ry = y - __bfloat162float(h.y);
    __nv_bfloat162 l = __floats2bfloat162_rn(rx, ry);
    lo = *(const uint32_t*)&l;
    return *(const uint32_t*)&h;
}

__device__ __forceinline__ uint32_t h2bits(__half2 h) { return *(const uint32_t*)&h; }

// fp16 hi/lo split (W to ~2^-22)
__device__ __forceinline__ uint32_t pack_splith(float x, float y, uint32_t& lo) {
    __half2 h = __floats2half2_rn(x, y);
    float2 hf = __half22float2(h);
    __half2 l = __floats2half2_rn(x - hf.x, y - hf.y);
    lo = h2bits(l);
    return h2bits(h);
}

#define AROW 136   // bytes per A row (64 x 16-bit = 128B + 8B pad); 8B-aligned only!
#define OFF_AH 0
#define OFF_AL 17408

// stage a [128 x 64] f32 tile (optionally scaled by 1/deg) into smem as bf16 hi/lo
__device__ __forceinline__ void stageA(char* smem, const float* __restrict__ src,
                                       const float* __restrict__ deg,
                                       int rowBase, int N, int t) {
    int r = t >> 1, h = t & 1;
    int row = rowBase + r;
    char* aH = smem + OFF_AH + r * AROW + h * 64;
    char* aL = smem + OFF_AL + r * AROW + h * 64;
    if (row < N) {
        float sc = deg ? (1.f / fmaxf(__ldg(deg + row), 1.f)) : 1.f;
        const float4* pu = (const float4*)(src + (size_t)row * 64) + h * 8;
#pragma unroll
        for (int j = 0; j < 8; j++) {
            float4 a = __ldg(pu + j);
            uint32_t lo01, lo23;
            uint32_t hi01 = pack_split(a.x * sc, a.y * sc, lo01);
            uint32_t hi23 = pack_split(a.z * sc, a.w * sc, lo23);
            *(uint2*)(aH + j * 8) = make_uint2(hi01, hi23);
            *(uint2*)(aL + j * 8) = make_uint2(lo01, lo23);
        }
    } else {
#pragma unroll
        for (int j = 0; j < 8; j++) {
            *(uint2*)(aH + j * 8) = make_uint2(0u, 0u);
            *(uint2*)(aL + j * 8) = make_uint2(0u, 0u);
        }
    }
}

// acc += A(smem) @ W(frags in global, 8 n-tiles), 3-term bf16 split
__device__ __forceinline__ void mma_AB(const char* smem,
                                       const uint32_t* __restrict__ fH,
                                       const uint32_t* __restrict__ fL,
                                       int r0, int tig, int lane, float acc[8][4]) {
    const char* AH = smem + OFF_AH;
    const char* AL = smem + OFF_AL;
#pragma unroll
    for (int kt = 0; kt < 4; kt++) {
        int ka = kt * 32 + tig * 4;
        uint32_t aH0 = *(const uint32_t*)(AH + r0 * AROW + ka);
        uint32_t aH1 = *(const uint32_t*)(AH + (r0 + 8) * AROW + ka);
        uint32_t aH2 = *(const uint32_t*)(AH + r0 * AROW + ka + 16);
        uint32_t aH3 = *(const uint32_t*)(AH + (r0 + 8) * AROW + ka + 16);
        uint32_t aL0 = *(const uint32_t*)(AL + r0 * AROW + ka);
        uint32_t aL1 = *(const uint32_t*)(AL + (r0 + 8) * AROW + ka);
        uint32_t aL2 = *(const uint32_t*)(AL + r0 * AROW + ka + 16);
        uint32_t aL3 = *(const uint32_t*)(AL + (r0 + 8) * AROW + ka + 16);
#pragma unroll
        for (int nt = 0; nt < 8; nt++) {
            int fo = (kt * 8 + nt) * 64 + lane * 2;
            uint2 bH = __ldg((const uint2*)(fH + fo));
            uint2 bL = __ldg((const uint2*)(fL + fo));
            mma16816(acc[nt], aH0, aH1, aH2, aH3, bH.x, bH.y);
            mma16816(acc[nt], aH0, aH1, aH2, aH3, bL.x, bL.y);
            mma16816(acc[nt], aL0, aL1, aL2, aL3, bH.x, bH.y);
        }
    }
}

// acc2 += (acc + bias[col]) @ W(frags), with C->A fragment identity mapping
__device__ __forceinline__ void frag_gemm64(const float acc[8][4],
                                            const float* __restrict__ biasS,
                                            const uint32_t* __restrict__ fH,
                                            const uint32_t* __restrict__ fL,
                                            int tig, int lane, float acc2[8][4]) {
#pragma unroll
    for (int kt = 0; kt < 4; kt++) {
        int c0 = kt * 16 + tig * 2;
        float b00 = biasS[c0], b01 = biasS[c0 + 1];
        float b02 = biasS[c0 + 8], b03 = biasS[c0 + 9];
        uint32_t l0, l1, l2, l3;
        uint32_t a0 = pack_split(acc[2 * kt][0] + b00, acc[2 * kt][1] + b01, l0);
        uint32_t a1 = pack_split(acc[2 * kt][2] + b00, acc[2 * kt][3] + b01, l1);
        uint32_t a2 = pack_split(acc[2 * kt + 1][0] + b02, acc[2 * kt + 1][1] + b03, l2);
        uint32_t a3 = pack_split(acc[2 * kt + 1][2] + b02, acc[2 * kt + 1][3] + b03, l3);
#pragma unroll
        for (int nt = 0; nt < 8; nt++) {
            int fo = (kt * 8 + nt) * 64 + lane * 2;
            uint2 bH = __ldg((const uint2*)(fH + fo));
            uint2 bL = __ldg((const uint2*)(fL + fo));
            mma16816(acc2[nt], a0, a1, a2, a3, bH.x, bH.y);
            mma16816(acc2[nt], a0, a1, a2, a3, bL.x, bL.y);
            mma16816(acc2[nt], l0, l1, l2, l3, bH.x, bH.y);
        }
    }
}

// ---------------- zero scratch ----------------
__global__ void k_zero() {
    size_t tid = (size_t)blockIdx.x * blockDim.x + threadIdx.x;
    size_t stride = (size_t)gridDim.x * blockDim.x;
    const size_t n4 = (size_t)NUc * 16;
    float4 z = make_float4(0.f, 0.f, 0.f, 0.f);
    for (size_t j = tid; j < n4; j += stride) {
        ((float4*)g_s_social)[j] = z;
        ((float4*)g_s_ru)[j] = z;
        ((float4*)g_s_rv)[j] = z;
    }
    for (size_t j = tid; j < NUc; j += stride) {
        g_deg_s[j] = 0.f;
        g_deg_ru[j] = 0.f;
        g_deg_rv[j] = 0.f;
    }
    if (tid < 128) { g_statU[tid] = 0.0; g_statV[tid] = 0.0; g_stat1[tid] = 0.0; }
    if (tid < 32) g_stat2[tid] = 0.0;
}

// ---------------- prep: edge weight fragments (Wuv1, Wuv2) fp16 hi/lo ----------------
__global__ void k_prepW(const float* __restrict__ W1, const float* __restrict__ W2) {
    int t = threadIdx.x;
    for (int idx = t; idx < 2048; idx += 256) {
        int r = idx & 1;
        int lane = (idx >> 1) & 31;
        int grp = idx >> 6;
        int kt = grp >> 3, nt = grp & 7;
        int g = lane >> 2, tig = lane & 3;
        int n = nt * 8 + g;
        int k0 = kt * 16 + 2 * tig + (r ? 8 : 0);
        uint32_t lo;
        uint32_t hi = pack_splith(__ldg(W1 + k0 * 64 + n), __ldg(W1 + (k0 + 1) * 64 + n), lo);
        g_fragH[idx] = hi;
        g_fragL[idx] = lo;
    }
    for (int idx = t; idx < 512; idx += 256) {
        int r = idx & 1;
        int lane = (idx >> 1) & 31;
        int grp = idx >> 6;
        int kt = grp >> 1, nt = grp & 1;
        int g = lane >> 2, tig = lane & 3;
        int n = nt * 8 + g;
        int k0 = kt * 16 + 2 * tig + (r ? 8 : 0);
        uint32_t lo;
        uint32_t hi = pack_splith(__ldg(W2 + k0 * 16 + n), __ldg(W2 + (k0 + 1) * 16 + n), lo);
        g_frag2H[idx] = hi;
        g_frag2L[idx] = lo;
    }
}

// ---------------- prep: 9 node weight matrices into bf16 fragments ----------------
__global__ void k_prepN(const float* __restrict__ Ws, const float* __restrict__ Wn,
                        const float* __restrict__ Wur1_, const float* __restrict__ Wvr1_,
                        const float* __restrict__ Wur2_, const float* __restrict__ Wvr2_) {
    int t = blockIdx.x * blockDim.x + threadIdx.x;
    if (t >= 2048) return;
    int r = t & 1;
    int lane = (t >> 1) & 31;
    int grp = t >> 6;
    int kt = grp >> 3, nt = grp & 7;
    int g = lane >> 2, tig = lane & 3;
    int n = nt * 8 + g;
    int k0 = kt * 16 + 2 * tig + (r ? 8 : 0);
    const float* base[9] = {nullptr, Wn, Wn + 2 * 4096, Wur1_, Ws + 4096,
                            Wn + 4096, Wvr1_, Wur2_, Wvr2_};
#pragma unroll
    for (int m = 0; m < 9; m++) {
        float w0, w1;
        if (m == 0) {
            w0 = __ldg(Ws + k0 * 64 + n) + __ldg(Ws + 2 * 4096 + k0 * 64 + n);
            w1 = __ldg(Ws + (k0 + 1) * 64 + n) + __ldg(Ws + 2 * 4096 + (k0 + 1) * 64 + n);
        } else {
            const float* W = base[m];
            w0 = __ldg(W + k0 * 64 + n);
            w1 = __ldg(W + (k0 + 1) * 64 + n);
        }
        uint32_t lo;
        uint32_t hi = pack_split(w0, w1, lo);
        g_nfH[m * 2048 + t] = hi;
        g_nfL[m * 2048 + t] = lo;
    }
}

// ---------------- fused scatter: all 3 segment sums, up to 3 chains/thread ----------------
__global__ __launch_bounds__(256) void k_scatAll(
    const float* __restrict__ u2e, const float* __restrict__ v2e,
    const int* __restrict__ ss, const int* __restrict__ sd,
    const int* __restrict__ rs, const int* __restrict__ rd,
    float* __restrict__ s_soc, float* __restrict__ s_rv, float* __restrict__ s_ru,
    float* __restrict__ deg_s, float* __restrict__ deg_rv, float* __restrict__ deg_ru) {
    int g = blockIdx.x * blockDim.x + threadIdx.x;
    int e = g >> 4;
    int q = g & 15;
    if (e >= ERc) return;
    int s = __ldg(rs + e);
    int d = __ldg(rd + e);
    bool soc = e < ESc;
    int s2 = 0, d2 = 0;
    if (soc) { s2 = __ldg(ss + e); d2 = __ldg(sd + e); }
    // issue all gathers first (3 independent chains)
    float4 a = __ldg((const float4*)u2e + (size_t)s * 16 + q);
    float4 b = __ldg((const float4*)v2e + (size_t)d * 16 + q);
    float4 c = make_float4(0.f, 0.f, 0.f, 0.f);
    if (soc) c = __ldg((const float4*)u2e + (size_t)s2 * 16 + q);
    float* p1 = s_rv + (size_t)d * 64 + q * 4;
    float* p2 = s_ru + (size_t)s * 64 + q * 4;
    asm volatile("red.global.add.v4.f32 [%0], {%1, %2, %3, %4};"
                 :: "l"(p1), "f"(a.x), "f"(a.y), "f"(a.z), "f"(a.w) : "memory");
    asm volatile("red.global.add.v4.f32 [%0], {%1, %2, %3, %4};"
                 :: "l"(p2), "f"(b.x), "f"(b.y), "f"(b.z), "f"(b.w) : "memory");
    if (soc) {
        float* p3 = s_soc + (size_t)d2 * 64 + q * 4;
        asm volatile("red.global.add.v4.f32 [%0], {%1, %2, %3, %4};"
                     :: "l"(p3), "f"(c.x), "f"(c.y), "f"(c.z), "f"(c.w) : "memory");
    }
    if (q == 0) {
        atomicAdd(deg_rv + d, 1.0f);
        atomicAdd(deg_ru + s, 1.0f);
        if (soc) atomicAdd(deg_s + d2, 1.0f);
    }
}

#define NBn ((NUc + 127) / 128)   // 391

// ---------------- merged node stage-1: user (blocks < NBn) / item (rest) ----------------
__global__ __launch_bounds__(256)
void k_node1_mma(const float* __restrict__ u2e, const float* __restrict__ v2e,
                 const float* __restrict__ bself,
                 const float* __restrict__ bu1, const float* __restrict__ bv1,
                 float* __restrict__ tu, float* __restrict__ tv,
                 double* __restrict__ stU, double* __restrict__ stV) {
    __shared__ __align__(16) char smem[34816];
    __shared__ float biasS[64];
    __shared__ float ssum[64], ssq[64];
    int t = threadIdx.x, lane = t & 31, w = t >> 5;
    int g = lane >> 2, tig = lane & 3;
    int r0 = w * 16 + g;
    bool isU = (int)blockIdx.x < NBn;
    int rowBase = (isU ? blockIdx.x : blockIdx.x - NBn) * 128;
    const float* in0 = isU ? u2e : v2e;
    const float* b1 = isU ? bu1 : bv1;
    float* out = isU ? tu : tv;
    double* stats = isU ? stU : stV;

    if (t < 64) {
        biasS[t] = isU ? (__ldg(bself + t) + __ldg(bself + 128 + t)) : __ldg(bself + 64 + t);
        ssum[t] = 0.f;
        ssq[t] = 0.f;
    }

    float acc[8][4] = {};
    stageA(smem, in0, nullptr, rowBase, NUc, t);
    __syncthreads();
    mma_AB(smem, g_nfH + (isU ? 0 : 4) * 2048, g_nfL + (isU ? 0 : 4) * 2048, r0, tig, lane, acc);
    __syncthreads();
    stageA(smem, isU ? g_s_social : g_s_rv, isU ? g_deg_s : g_deg_rv, rowBase, NUc, t);
    __syncthreads();
    mma_AB(smem, g_nfH + (isU ? 1 : 5) * 2048, g_nfL + (isU ? 1 : 5) * 2048, r0, tig, lane, acc);
    __syncthreads();
    if (isU) {
        stageA(smem, g_s_ru, g_deg_ru, rowBase, NUc, t);
        __syncthreads();
        mma_AB(smem, g_nfH + 2 * 2048, g_nfL + 2 * 2048, r0, tig, lane, acc);
        __syncthreads();
    }

    float acc2[8][4] = {};
    frag_gemm64(acc, biasS, g_nfH + (isU ? 3 : 6) * 2048, g_nfL + (isU ? 3 : 6) * 2048,
                tig, lane, acc2);

    float* stage = (float*)smem;
#pragma unroll
    for (int nt = 0; nt < 8; nt++) {
        int c = nt * 8 + tig * 2;
        stage[r0 * 65 + c] = acc2[nt][0];
        stage[r0 * 65 + c + 1] = acc2[nt][1];
        stage[(r0 + 8) * 65 + c] = acc2[nt][2];
        stage[(r0 + 8) * 65 + c + 1] = acc2[nt][3];
    }
    __syncthreads();

    int c4 = (t & 15) * 4;
    float4 bias = *(const float4*)(b1 + c4);
    float cs[4] = {0, 0, 0, 0}, cq[4] = {0, 0, 0, 0};
#pragma unroll
    for (int i = 0; i < 8; i++) {
        int r = (t >> 4) + 16 * i;
        int row = rowBase + r;
        if (row < NUc) {
            const float* sp = stage + r * 65 + c4;
            float v0 = sp[0] + bias.x, v1 = sp[1] + bias.y;
            float v2 = sp[2] + bias.z, v3 = sp[3] + bias.w;
            *(float4*)(out + (size_t)row * 64 + c4) = make_float4(v0, v1, v2, v3);
            cs[0] += v0; cq[0] += v0 * v0;
            cs[1] += v1; cq[1] += v1 * v1;
            cs[2] += v2; cq[2] += v2 * v2;
            cs[3] += v3; cq[3] += v3 * v3;
        }
    }
#pragma unroll
    for (int j = 0; j < 4; j++) {
        atomicAdd(&ssum[c4 + j], cs[j]);
        atomicAdd(&ssq[c4 + j], cq[j]);
    }
    __syncthreads();
    if (t < 64) atomicAdd(&stats[t], (double)ssum[t]);
    else if (t < 128) atomicAdd(&stats[t], (double)ssq[t - 64]);
}

// ---------------- BN finalize (one set) ----------------
__global__ void k_fin(const double* __restrict__ stats, const float* __restrict__ gamma,
                      const float* __restrict__ beta, float* __restrict__ aff,
                      int C, float invN) {
    int c = threadIdx.x;
    if (c < C) {
        float mean = (float)(stats[c] * (double)invN);
        float ex2 = (float)(stats[C + c] * (double)invN);
        float var = ex2 - mean * mean;
        float a = gamma[c] * rsqrtf(var + 1e-5f);
        aff[c] = a;
        aff[C + c] = beta[c] - mean * a;
    }
}

// ---------------- BN finalize for U and V in one launch ----------------
__global__ void k_fin2(const double* __restrict__ stU, const double* __restrict__ stV,
                       const float* __restrict__ gamma, const float* __restrict__ beta,
                       float* __restrict__ affU, float* __restrict__ affV) {
    int t = threadIdx.x;   // 128
    const double* st = (t < 64) ? stU : stV;
    float* aff = (t < 64) ? affU : affV;
    int c = t & 63;
    int go = (t < 64) ? 0 : 64;
    float invN = 1.0f / NUc;   // NU == NV
    float mean = (float)(st[c] * (double)invN);
    float ex2 = (float)(st[64 + c] * (double)invN);
    float var = ex2 - mean * mean;
    float a = __ldg(gamma + go + c) * rsqrtf(var + 1e-5f);
    aff[c] = a;
    aff[64 + c] = __ldg(beta + go + c) - mean * a;
}

// ---------------- merged tower2: user/item, bf16 3-term, fp16 out ----------------
__global__ __launch_bounds__(256)
void k_tower2m(const float* __restrict__ tu, const float* __restrict__ tv,
               const float* __restrict__ affU, const float* __restrict__ affV,
               const float* __restrict__ bu2, const float* __restrict__ bv2,
               __half* __restrict__ xu, __half* __restrict__ xv) {
    __shared__ float stage[128 * 65];
    __shared__ float affS[128];
    int t = threadIdx.x, lane = t & 31, w = t >> 5;
    int g = lane >> 2, tig = lane & 3;
    int r0 = w * 16 + g;
    bool isU = (int)blockIdx.x < NBn;
    int rowBase = (isU ? blockIdx.x : blockIdx.x - NBn) * 128;
    const float* in = isU ? tu : tv;
    const float* aff = isU ? affU : affV;
    const float* b2 = isU ? bu2 : bv2;
    __half* out = isU ? xu : xv;
    const uint32_t* fH = g_nfH + (isU ? 7 : 8) * 2048;
    const uint32_t* fL = g_nfL + (isU ? 7 : 8) * 2048;
    if (t < 128) affS[t] = __ldg(aff + t);
    __syncthreads();

    int e0 = rowBase + r0, e1 = e0 + 8;
    bool ok0 = e0 < NUc, ok1 = e1 < NUc;   // NU == NV

    float acc2[8][4] = {};
#pragma unroll
    for (int kt = 0; kt < 4; kt++) {
        int c0 = kt * 16 + tig * 2;
        float2 z = make_float2(0.f, 0.f);
        float2 y00 = ok0 ? *(const float2*)(in + (size_t)e0 * 64 + c0) : z;
        float2 y10 = ok0 ? *(const float2*)(in + (size_t)e0 * 64 + c0 + 8) : z;
        float2 y01 = ok1 ? *(const float2*)(in + (size_t)e1 * 64 + c0) : z;
        float2 y11 = ok1 ? *(const float2*)(in + (size_t)e1 * 64 + c0 + 8) : z;
        float s0 = affS[c0], h0 = affS[64 + c0];
        float s1 = affS[c0 + 1], h1 = affS[64 + c0 + 1];
        float s2 = affS[c0 + 8], h2 = affS[64 + c0 + 8];
        float s3 = affS[c0 + 9], h3 = affS[64 + c0 + 9];
        float v00 = fmaxf(y00.x * s0 + h0, 0.f), v01 = fmaxf(y00.y * s1 + h1, 0.f);
        float v10 = fmaxf(y01.x * s0 + h0, 0.f), v11 = fmaxf(y01.y * s1 + h1, 0.f);
        float w00 = fmaxf(y10.x * s2 + h2, 0.f), w01 = fmaxf(y10.y * s3 + h3, 0.f);
        float w10 = fmaxf(y11.x * s2 + h2, 0.f), w11 = fmaxf(y11.y * s3 + h3, 0.f);
        uint32_t l0, l1, l2, l3;
        uint32_t a0 = pack_split(v00, v01, l0);
        uint32_t a1 = pack_split(v10, v11, l1);
        uint32_t a2 = pack_split(w00, w01, l2);
        uint32_t a3 = pack_split(w10, w11, l3);
#pragma unroll
        for (int nt = 0; nt < 8; nt++) {
            int fo = (kt * 8 + nt) * 64 + lane * 2;
            uint2 bH = __ldg((const uint2*)(fH + fo));
            uint2 bL = __ldg((const uint2*)(fL + fo));
            mma16816(acc2[nt], a0, a1, a2, a3, bH.x, bH.y);
            mma16816(acc2[nt], a0, a1, a2, a3, bL.x, bL.y);
            mma16816(acc2[nt], l0, l1, l2, l3, bH.x, bH.y);
        }
    }

#pragma unroll
    for (int nt = 0; nt < 8; nt++) {
        int c = nt * 8 + tig * 2;
        stage[r0 * 65 + c] = acc2[nt][0];
        stage[r0 * 65 + c + 1] = acc2[nt][1];
        stage[(r0 + 8) * 65 + c] = acc2[nt][2];
        stage[(r0 + 8) * 65 + c + 1] = acc2[nt][3];
    }
    __syncthreads();

    int c4 = (t & 15) * 4;
    float4 bias = *(const float4*)(b2 + c4);
#pragma unroll
    for (int i = 0; i < 8; i++) {
        int r = (t >> 4) + 16 * i;
        int row = rowBase + r;
        if (row < NUc) {
            const float* sp = stage + r * 65 + c4;
            __half2 ha = __floats2half2_rn(sp[0] + bias.x, sp[1] + bias.y);
            __half2 hb = __floats2half2_rn(sp[2] + bias.z, sp[3] + bias.w);
            *(uint2*)(out + (size_t)row * 64 + c4) = make_uint2(h2bits(ha), h2bits(hb));
        }
    }
}

// ================= edge pass 1: fp16 gather -> fp16 A, f16 mma, 2-term W split =================
#define E1_SMEM 33792
#define E1_OFF_A 0        // fp16 A: 128 rows x 136B = 17408
#define E1_OFF_BH 17408   // Whi fp16 frags: 8192
#define E1_OFF_BL 25600   // Wlo fp16 frags: 8192

__global__ __launch_bounds__(256)
void k_edge1_mma(const __half* __restrict__ xu, const __half* __restrict__ xv,
                 const int* __restrict__ es, const int* __restrict__ ed,
                 const float* __restrict__ b, __half* __restrict__ out,
                 double* __restrict__ stats) {
    extern __shared__ __align__(16) char smem[];
    __shared__ float ssum[64], ssq[64];
    int t = threadIdx.x, lane = t & 31, w = t >> 5;
    int rowBase = blockIdx.x * 128;
    if (t < 64) { ssum[t] = 0.f; ssq[t] = 0.f; }

    {
        const uint4* sH = (const uint4*)g_fragH;
        const uint4* sL = (const uint4*)g_fragL;
        uint4* dH = (uint4*)(smem + E1_OFF_BH);
        uint4* dL = (uint4*)(smem + E1_OFF_BL);
        dH[t] = __ldg(sH + t);
        dH[t + 256] = __ldg(sH + t + 256);
        dL[t] = __ldg(sL + t);
        dL[t + 256] = __ldg(sL + t + 256);
    }
    {
        int r = t >> 1, h = t & 1;
        int e = rowBase + r;
        char* aA = smem + E1_OFF_A + r * AROW + h * 64;
        if (e < ERc) {
            int s = __ldg(es + e), d = __ldg(ed + e);
            const uint4* pu = (const uint4*)(xu + (size_t)s * 64) + h * 4;
            const uint4* pv = (const uint4*)(xv + (size_t)d * 64) + h * 4;
#pragma unroll
            for (int j = 0; j < 4; j++) {
                uint4 A = __ldg(pu + j), V = __ldg(pv + j);
                float2 a0 = __half22float2(*(const __half2*)&A.x);
                float2 a1 = __half22float2(*(const __half2*)&A.y);
                float2 a2 = __half22float2(*(const __half2*)&A.z);
                float2 a3 = __half22float2(*(const __half2*)&A.w);
                float2 v0 = __half22float2(*(const __half2*)&V.x);
                float2 v1 = __half22float2(*(const __half2*)&V.y);
                float2 v2 = __half22float2(*(const __half2*)&V.z);
                float2 v3 = __half22float2(*(const __half2*)&V.w);
                __half2 p0 = __floats2half2_rn(a0.x * v0.x, a0.y * v0.y);
                __half2 p1 = __floats2half2_rn(a1.x * v1.x, a1.y * v1.y);
                __half2 p2 = __floats2half2_rn(a2.x * v2.x, a2.y * v2.y);
                __half2 p3 = __floats2half2_rn(a3.x * v3.x, a3.y * v3.y);
                *(uint2*)(aA + j * 16) = make_uint2(h2bits(p0), h2bits(p1));
                *(uint2*)(aA + j * 16 + 8) = make_uint2(h2bits(p2), h2bits(p3));
            }
        } else {
#pragma unroll
            for (int j = 0; j < 8; j++)
                *(uint2*)(aA + j * 8) = make_uint2(0u, 0u);
        }
    }
    __syncthreads();

    int g = lane >> 2, tig = lane & 3;
    int r0 = w * 16 + g;
    float acc[8][4] = {};
    const char* AA = smem + E1_OFF_A;
#pragma unroll
    for (int kt = 0; kt < 4; kt++) {
        int ka = kt * 32 + tig * 4;
        uint32_t a0 = *(const uint32_t*)(AA + r0 * AROW + ka);
        uint32_t a1 = *(const uint32_t*)(AA + (r0 + 8) * AROW + ka);
        uint32_t a2 = *(const uint32_t*)(AA + r0 * AROW + ka + 16);
        uint32_t a3 = *(const uint32_t*)(AA + (r0 + 8) * AROW + ka + 16);
#pragma unroll
        for (int nt = 0; nt < 8; nt++) {
            uint32_t boff = ((kt * 8 + nt) * 64 + lane * 2) * 4;
            uint2 bH = *(const uint2*)(smem + E1_OFF_BH + boff);
            uint2 bL = *(const uint2*)(smem + E1_OFF_BL + boff);
            mma16816h(acc[nt], a0, a1, a2, a3, bH.x, bH.y);
            mma16816h(acc[nt], a0, a1, a2, a3, bL.x, bL.y);
        }
    }
    __syncthreads();

    float* stage = (float*)smem;
#pragma unroll
    for (int nt = 0; nt < 8; nt++) {
        int c = nt * 8 + tig * 2;
        stage[r0 * 65 + c] = acc[nt][0];
        stage[r0 * 65 + c + 1] = acc[nt][1];
        stage[(r0 + 8) * 65 + c] = acc[nt][2];
        stage[(r0 + 8) * 65 + c + 1] = acc[nt][3];
    }
    __syncthreads();

    int c4 = (t & 15) * 4;
    float4 bias = *(const float4*)(b + c4);
    float cs[4] = {0, 0, 0, 0}, cq[4] = {0, 0, 0, 0};
#pragma unroll
    for (int i = 0; i < 8; i++) {
        int r = (t >> 4) + 16 * i;
        int e = rowBase + r;
        if (e < ERc) {
            const float* sp = stage + r * 65 + c4;
            float v0 = sp[0] + bias.x, v1 = sp[1] + bias.y;
            float v2 = sp[2] + bias.z, v3 = sp[3] + bias.w;
            __half2 ha = __floats2half2_rn(v0, v1);
            __half2 hb = __floats2half2_rn(v2, v3);
            *(uint2*)(out + (size_t)e * 64 + c4) = make_uint2(h2bits(ha), h2bits(hb));
            cs[0] += v0; cq[0] += v0 * v0;
            cs[1] += v1; cq[1] += v1 * v1;
            cs[2] += v2; cq[2] += v2 * v2;
            cs[3] += v3; cq[3] += v3 * v3;
        }
    }
#pragma unroll
    for (int j = 0; j < 4; j++) {
        atomicAdd(&ssum[c4 + j], cs[j]);
        atomicAdd(&ssq[c4 + j], cq[j]);
    }
    __syncthreads();
    if (t < 64) atomicAdd(&stats[t], (double)ssum[t]);
    else if (t < 128) atomicAdd(&stats[t], (double)ssq[t - 64]);
}

// ================= edge pass 2: fp16 y1 in, f16 mma, 2-term W2 split =================
__global__ __launch_bounds__(256)
void k_edge2_mma(const __half* __restrict__ y1, const float* __restrict__ aff,
                 const float* __restrict__ b2, float* __restrict__ y2,
                 double* __restrict__ stats) {
    __shared__ float affS[128];
    __shared__ __align__(16) uint32_t f2H[512], f2L[512];
    __shared__ float ssum[16], ssq[16];
    int t = threadIdx.x, lane = t & 31, w = t >> 5;
    int rowBase = blockIdx.x * 128;
    if (t < 128) affS[t] = __ldg(aff + t);
    if (t < 16) { ssum[t] = 0.f; ssq[t] = 0.f; }
    {
        ((uint2*)f2H)[t] = __ldg((const uint2*)g_frag2H + t);
        ((uint2*)f2L)[t] = __ldg((const uint2*)g_frag2L + t);
    }
    __syncthreads();

    int g = lane >> 2, tig = lane & 3;
    int r0 = w * 16 + g;
    int e0 = rowBase + r0, e1 = e0 + 8;
    bool ok0 = e0 < ERc, ok1 = e1 < ERc;

    float acc2[2][4] = {};
#pragma unroll
    for (int kt = 0; kt < 4; kt++) {
        int c0 = kt * 16 + tig * 2;
        float2 z = make_float2(0.f, 0.f);
        float2 y00 = ok0 ? __half22float2(*(const __half2*)(y1 + (size_t)e0 * 64 + c0)) : z;
        float2 y10 = ok1 ? __half22float2(*(const __half2*)(y1 + (size_t)e1 * 64 + c0)) : z;
        float2 y01 = ok0 ? __half22float2(*(const __half2*)(y1 + (size_t)e0 * 64 + c0 + 8)) : z;
        float2 y11 = ok1 ? __half22float2(*(const __half2*)(y1 + (size_t)e1 * 64 + c0 + 8)) : z;
        float s0 = affS[c0], h0 = affS[64 + c0];
        float s1 = affS[c0 + 1], h1 = affS[64 + c0 + 1];
        float s2 = affS[c0 + 8], h2 = affS[64 + c0 + 8];
        float s3 = affS[c0 + 9], h3 = affS[64 + c0 + 9];
        uint32_t a0 = h2bits(__floats2half2_rn(fmaxf(y00.x * s0 + h0, 0.f),
                                               fmaxf(y00.y * s1 + h1, 0.f)));
        uint32_t a1 = h2bits(__floats2half2_rn(fmaxf(y10.x * s0 + h0, 0.f),
                                               fmaxf(y10.y * s1 + h1, 0.f)));
        uint32_t a2 = h2bits(__floats2half2_rn(fmaxf(y01.x * s2 + h2, 0.f),
                                               fmaxf(y01.y * s3 + h3, 0.f)));
        uint32_t a3 = h2bits(__floats2half2_rn(fmaxf(y11.x * s2 + h2, 0.f),
                                               fmaxf(y11.y * s3 + h3, 0.f)));
#pragma unroll
        for (int n2 = 0; n2 < 2; n2++) {
            int fo = (kt * 2 + n2) * 64 + lane * 2;
            uint2 bH = *(const uint2*)(f2H + fo);
            uint2 bL = *(const uint2*)(f2L + fo);
            mma16816h(acc2[n2], a0, a1, a2, a3, bH.x, bH.y);
            mma16816h(acc2[n2], a0, a1, a2, a3, bL.x, bL.y);
        }
    }

    float cs[4] = {0, 0, 0, 0}, cq[4] = {0, 0, 0, 0};
#pragma unroll
    for (int n2 = 0; n2 < 2; n2++) {
        int c = n2 * 8 + tig * 2;
        float bx = __ldg(b2 + c), by = __ldg(b2 + c + 1);
        float u0 = acc2[n2][0] + bx, u1 = acc2[n2][1] + by;
        float u2 = acc2[n2][2] + bx, u3 = acc2[n2][3] + by;
        if (ok0) {
            *(float2*)(y2 + (size_t)e0 * 16 + c) = make_float2(u0, u1);
            cs[n2 * 2] += u0; cq[n2 * 2] += u0 * u0;
            cs[n2 * 2 + 1] += u1; cq[n2 * 2 + 1] += u1 * u1;
        }
        if (ok1) {
            *(float2*)(y2 + (size_t)e1 * 16 + c) = make_float2(u2, u3);
            cs[n2 * 2] += u2; cq[n2 * 2] += u2 * u2;
            cs[n2 * 2 + 1] += u3; cq[n2 * 2 + 1] += u3 * u3;
        }
    }
#pragma unroll
    for (int n2 = 0; n2 < 2; n2++) {
#pragma unroll
        for (int j = 0; j < 2; j++) {
            int c = n2 * 8 + tig * 2 + j;
            atomicAdd(&ssum[c], cs[n2 * 2 + j]);
            atomicAdd(&ssq[c], cq[n2 * 2 + j]);
        }
    }
    __syncthreads();
    if (t < 16) atomicAdd(&stats[t], (double)ssum[t]);
    else if (t < 32) atomicAdd(&stats[t], (double)ssq[t - 16]);
}

// ---------------- edge pass 3: scores = relu(y2*a2+c2) . w3 + b3 ----------------
__global__ __launch_bounds__(256) void k_edge3(
    const float* __restrict__ y2, const float* __restrict__ aff,
    const float* __restrict__ w3, const float* __restrict__ b3,
    float* __restrict__ out) {
    int e = blockIdx.x * blockDim.x + threadIdx.x;
    if (e >= ERc) return;
    const float4* p = (const float4*)(y2 + (size_t)e * 16);
    float s = 0.f;
#pragma unroll
    for (int j = 0; j < 4; j++) {
        float4 v = __ldg(p + j);
        float4 a = *(const float4*)(aff + 4 * j);
        float4 c = *(const float4*)(aff + 16 + 4 * j);
        float4 w = *(const float4*)(w3 + 4 * j);
        s += fmaxf(v.x * a.x + c.x, 0.f) * w.x;
        s += fmaxf(v.y * a.y + c.y, 0.f) * w.y;
        s += fmaxf(v.z * a.z + c.z, 0.f) * w.z;
        s += fmaxf(v.w * a.w + c.w, 0.f) * w.w;
    }
    out[e] = s + __ldg(b3);
}

// ---------------- host ----------------
extern "C" void kernel_launch(void* const* d_in, const int* in_sizes, int n_in,
                              void* d_out, int out_size) {
    const float* u2e     = (const float*)d_in[0];
    const float* v2e     = (const float*)d_in[1];
    const float* W_self  = (const float*)d_in[2];
    const float* b_self  = (const float*)d_in[3];
    const float* W_neigh = (const float*)d_in[4];
    const float* Wur1 = (const float*)d_in[5];
    const float* bur1 = (const float*)d_in[6];
    const float* Wur2 = (const float*)d_in[7];
    const float* bur2 = (const float*)d_in[8];
    const float* Wvr1 = (const float*)d_in[9];
    const float* bvr1 = (const float*)d_in[10];
    const float* Wvr2 = (const float*)d_in[11];
    const float* bvr2 = (const float*)d_in[12];
    const float* Wuv1 = (const float*)d_in[13];
    const float* buv1 = (const float*)d_in[14];
    const float* Wuv2 = (const float*)d_in[15];
    const float* buv2 = (const float*)d_in[16];
    const float* Wuv3 = (const float*)d_in[17];
    const float* buv3 = (const float*)d_in[18];
    const float* bn_gamma  = (const float*)d_in[19];
    const float* bn_beta   = (const float*)d_in[20];
    const float* bn4_gamma = (const float*)d_in[21];
    const float* bn4_beta  = (const float*)d_in[22];
    const int* social_src = (const int*)d_in[23];
    const int* social_dst = (const int*)d_in[24];
    const int* rates_src  = (const int*)d_in[25];
    const int* rates_dst  = (const int*)d_in[26];
    float* out = (float*)d_out;

    void *p_ssoc, *p_sru, *p_srv, *p_degs, *p_degru, *p_degrv;
    void *p_tu, *p_tv, *p_xu, *p_xv, *p_y1, *p_y2;
    void *p_stU, *p_stV, *p_st1, *p_st2, *p_aU, *p_aV, *p_a1, *p_a2;
    cudaGetSymbolAddress(&p_ssoc, g_s_social);
    cudaGetSymbolAddress(&p_sru, g_s_ru);
    cudaGetSymbolAddress(&p_srv, g_s_rv);
    cudaGetSymbolAddress(&p_degs, g_deg_s);
    cudaGetSymbolAddress(&p_degru, g_deg_ru);
    cudaGetSymbolAddress(&p_degrv, g_deg_rv);
    cudaGetSymbolAddress(&p_tu, g_tu);
    cudaGetSymbolAddress(&p_tv, g_tv);
    cudaGetSymbolAddress(&p_xu, g_xuh);
    cudaGetSymbolAddress(&p_xv, g_xvh);
    cudaGetSymbolAddress(&p_y1, g_y1h);
    cudaGetSymbolAddress(&p_y2, g_y2);
    cudaGetSymbolAddress(&p_stU, g_statU);
    cudaGetSymbolAddress(&p_stV, g_statV);
    cudaGetSymbolAddress(&p_st1, g_stat1);
    cudaGetSymbolAddress(&p_st2, g_stat2);
    cudaGetSymbolAddress(&p_aU, g_affU);
    cudaGetSymbolAddress(&p_aV, g_affV);
    cudaGetSymbolAddress(&p_a1, g_aff1);
    cudaGetSymbolAddress(&p_a2, g_aff2);

    cudaFuncSetAttribute(k_edge1_mma, cudaFuncAttributeMaxDynamicSharedMemorySize, E1_SMEM);

    const int NB_E1 = (ERc + 127) / 128;

    k_zero<<<2048, 256>>>();
    k_prepW<<<1, 256>>>(Wuv1, Wuv2);
    k_prepN<<<8, 256>>>(W_self, W_neigh, Wur1, Wvr1, Wur2, Wvr2);

    // all three segment sums in one kernel (up to 3 gather+RED chains per thread)
    k_scatAll<<<ERc / 16, 256>>>(u2e, v2e, social_src, social_dst, rates_src, rates_dst,
                                 (float*)p_ssoc, (float*)p_srv, (float*)p_sru,
                                 (float*)p_degs, (float*)p_degrv, (float*)p_degru);

    k_node1_mma<<<2 * NBn, 256>>>(u2e, v2e, b_self, bur1, bvr1,
                                  (float*)p_tu, (float*)p_tv,
                                  (double*)p_stU, (double*)p_stV);
    k_fin2<<<1, 128>>>((const double*)p_stU, (const double*)p_stV,
                       bn_gamma, bn_beta, (float*)p_aU, (float*)p_aV);
    k_tower2m<<<2 * NBn, 256>>>((const float*)p_tu, (const float*)p_tv,
                                (const float*)p_aU, (const float*)p_aV,
                                bur2, bvr2, (__half*)p_xu, (__half*)p_xv);

    k_edge1_mma<<<NB_E1, 256, E1_SMEM>>>((const __half*)p_xu, (const __half*)p_xv,
                                         rates_src, rates_dst, buv1,
                                         (__half*)p_y1, (double*)p_st1);
    k_fin<<<1, 64>>>((const double*)p_st1, bn_gamma + 128, bn_beta + 128, (float*)p_a1, 64, 1.0f / ERc);
    k_edge2_mma<<<NB_E1, 256>>>((const __half*)p_y1, (const float*)p_a1, buv2,
                                (float*)p_y2, (double*)p_st2);
    k_fin<<<1, 16>>>((const double*)p_st2, bn4_gamma, bn4_beta, (float*)p_a2, 16, 1.0f / ERc);
    k_edge3<<<(ERc + 255) / 256, 256>>>((const float*)p_y2, (const float*)p_a2, Wuv3, buv3, out);

    (void)in_sizes; (void)n_in; (void)out_size;
}

// round 17
// speedup vs baseline: 1.8223x; 1.0317x over previous
#include <cuda_runtime.h>
#include <cuda_bf16.h>
#include <cuda_fp16.h>
#include <cstdint>

#define NUc 50000
#define NVc 50000
#define ESc 800000
#define ERc 1000000

// ---------------- device scratch (no allocations allowed) ----------------
__device__ __align__(16) float g_s_social[(size_t)NUc * 64];
__device__ __align__(16) float g_s_ru[(size_t)NUc * 64];
__device__ __align__(16) float g_s_rv[(size_t)NVc * 64];
__device__ float g_deg_s[NUc];
__device__ float g_deg_ru[NUc];
__device__ float g_deg_rv[NVc];
__device__ __align__(16) float g_tu[(size_t)NUc * 64];
__device__ __align__(16) float g_tv[(size_t)NVc * 64];
// fp16 tables: first hold fp16(u2e)/fp16(v2e) for the scatter gather,
// then are overwritten by tower2m with x_u/x_v (strictly later in the stream).
__device__ __align__(16) __half g_xuh[(size_t)NUc * 64];
__device__ __align__(16) __half g_xvh[(size_t)NVc * 64];
__device__ __align__(16) __half g_y1h[(size_t)ERc * 64];   // fp16 y1 (128 MB)
__device__ __align__(16) __half g_y2h[(size_t)ERc * 16];   // fp16 y2 (32 MB)
__device__ double g_statU[128];
__device__ double g_statV[128];
__device__ double g_stat1[128];
__device__ double g_stat2[32];
__device__ __align__(16) float g_affU[128];
__device__ __align__(16) float g_affV[128];
__device__ __align__(16) float g_aff1[128];
__device__ __align__(16) float g_aff2[32];
// Wuv1 pre-packed per-lane m16n8k16 B-fragment order, fp16 hi/lo split
__device__ __align__(16) uint32_t g_fragH[2048];
__device__ __align__(16) uint32_t g_fragL[2048];
// Wuv2 (64x16) fp16 hi/lo: (kt*2+nt)*64 + lane*2 + r
__device__ __align__(16) uint32_t g_frag2H[512];
__device__ __align__(16) uint32_t g_frag2L[512];
// 9 node matrices (64x64 each) in bf16 hi/lo B-fragment order:
// 0:Wself0+Wself2  1:Wn0  2:Wn2  3:Wur1  4:Wself1  5:Wn1  6:Wvr1  7:Wur2  8:Wvr2
__device__ __align__(16) uint32_t g_nfH[9 * 2048];
__device__ __align__(16) uint32_t g_nfL[9 * 2048];

// ---------------- common mma helpers ----------------
__device__ __forceinline__ void mma16816(float c[4], uint32_t a0, uint32_t a1,
                                         uint32_t a2, uint32_t a3,
                                         uint32_t b0, uint32_t b1) {
    asm volatile(
        "mma.sync.aligned.m16n8k16.row.col.f32.bf16.bf16.f32 "
        "{%0,%1,%2,%3}, {%4,%5,%6,%7}, {%8,%9}, {%0,%1,%2,%3};"
        : "+f"(c[0]), "+f"(c[1]), "+f"(c[2]), "+f"(c[3])
        : "r"(a0), "r"(a1), "r"(a2), "r"(a3), "r"(b0), "r"(b1));
}

__device__ __forceinline__ void mma16816h(float c[4], uint32_t a0, uint32_t a1,
                                          uint32_t a2, uint32_t a3,
                                          uint32_t b0, uint32_t b1) {
    asm volatile(
        "mma.sync.aligned.m16n8k16.row.col.f32.f16.f16.f32 "
        "{%0,%1,%2,%3}, {%4,%5,%6,%7}, {%8,%9}, {%0,%1,%2,%3};"
        : "+f"(c[0]), "+f"(c[1]), "+f"(c[2]), "+f"(c[3])
        : "r"(a0), "r"(a1), "r"(a2), "r"(a3), "r"(b0), "r"(b1));
}

__device__ __forceinline__ uint32_t pack_split(float x, float y, uint32_t& lo) {
    __nv_bfloat162 h = __floats2bfloat162_rn(x, y);
    float rx = x - __bfloat162float(h.x);
    float ry = y - __bfloat162float(h.y);
    __nv_bfloat162 l = __floats2bfloat162_rn(rx, ry);
    lo = *(const uint32_t*)&l;
    return *(const uint32_t*)&h;
}

__device__ __forceinline__ uint32_t h2bits(__half2 h) { return *(const uint32_t*)&h; }

// fp16 hi/lo split (W to ~2^-22)
__device__ __forceinline__ uint32_t pack_splith(float x, float y, uint32_t& lo) {
    __half2 h = __floats2half2_rn(x, y);
    float2 hf = __half22float2(h);
    __half2 l = __floats2half2_rn(x - hf.x, y - hf.y);
    lo = h2bits(l);
    return h2bits(h);
}

#define AROW 136   // bytes per A row (64 x 16-bit = 128B + 8B pad); 8B-aligned only!
#define OFF_AH 0
#define OFF_AL 17408

// stage a [128 x 64] f32 tile (optionally scaled by 1/deg) into smem as bf16 hi/lo
__device__ __forceinline__ void stageA(char* smem, const float* __restrict__ src,
                                       const float* __restrict__ deg,
                                       int rowBase, int N, int t) {
    int r = t >> 1, h = t & 1;
    int row = rowBase + r;
    char* aH = smem + OFF_AH + r * AROW + h * 64;
    char* aL = smem + OFF_AL + r * AROW + h * 64;
    if (row < N) {
        float sc = deg ? (1.f / fmaxf(__ldg(deg + row), 1.f)) : 1.f;
        const float4* pu = (const float4*)(src + (size_t)row * 64) + h * 8;
#pragma unroll
        for (int j = 0; j < 8; j++) {
            float4 a = __ldg(pu + j);
            uint32_t lo01, lo23;
            uint32_t hi01 = pack_split(a.x * sc, a.y * sc, lo01);
            uint32_t hi23 = pack_split(a.z * sc, a.w * sc, lo23);
            *(uint2*)(aH + j * 8) = make_uint2(hi01, hi23);
            *(uint2*)(aL + j * 8) = make_uint2(lo01, lo23);
        }
    } else {
#pragma unroll
        for (int j = 0; j < 8; j++) {
            *(uint2*)(aH + j * 8) = make_uint2(0u, 0u);
            *(uint2*)(aL + j * 8) = make_uint2(0u, 0u);
        }
    }
}

// acc += A(smem) @ W(frags in global, 8 n-tiles), 3-term bf16 split
__device__ __forceinline__ void mma_AB(const char* smem,
                                       const uint32_t* __restrict__ fH,
                                       const uint32_t* __restrict__ fL,
                                       int r0, int tig, int lane, float acc[8][4]) {
    const char* AH = smem + OFF_AH;
    const char* AL = smem + OFF_AL;
#pragma unroll
    for (int kt = 0; kt < 4; kt++) {
        int ka = kt * 32 + tig * 4;
        uint32_t aH0 = *(const uint32_t*)(AH + r0 * AROW + ka);
        uint32_t aH1 = *(const uint32_t*)(AH + (r0 + 8) * AROW + ka);
        uint32_t aH2 = *(const uint32_t*)(AH + r0 * AROW + ka + 16);
        uint32_t aH3 = *(const uint32_t*)(AH + (r0 + 8) * AROW + ka + 16);
        uint32_t aL0 = *(const uint32_t*)(AL + r0 * AROW + ka);
        uint32_t aL1 = *(const uint32_t*)(AL + (r0 + 8) * AROW + ka);
        uint32_t aL2 = *(const uint32_t*)(AL + r0 * AROW + ka + 16);
        uint32_t aL3 = *(const uint32_t*)(AL + (r0 + 8) * AROW + ka + 16);
#pragma unroll
        for (int nt = 0; nt < 8; nt++) {
            int fo = (kt * 8 + nt) * 64 + lane * 2;
            uint2 bH = __ldg((const uint2*)(fH + fo));
            uint2 bL = __ldg((const uint2*)(fL + fo));
            mma16816(acc[nt], aH0, aH1, aH2, aH3, bH.x, bH.y);
            mma16816(acc[nt], aH0, aH1, aH2, aH3, bL.x, bL.y);
            mma16816(acc[nt], aL0, aL1, aL2, aL3, bH.x, bH.y);
        }
    }
}

// acc2 += (acc + bias[col]) @ W(frags), with C->A fragment identity mapping
__device__ __forceinline__ void frag_gemm64(const float acc[8][4],
                                            const float* __restrict__ biasS,
                                            const uint32_t* __restrict__ fH,
                                            const uint32_t* __restrict__ fL,
                                            int tig, int lane, float acc2[8][4]) {
#pragma unroll
    for (int kt = 0; kt < 4; kt++) {
        int c0 = kt * 16 + tig * 2;
        float b00 = biasS[c0], b01 = biasS[c0 + 1];
        float b02 = biasS[c0 + 8], b03 = biasS[c0 + 9];
        uint32_t l0, l1, l2, l3;
        uint32_t a0 = pack_split(acc[2 * kt][0] + b00, acc[2 * kt][1] + b01, l0);
        uint32_t a1 = pack_split(acc[2 * kt][2] + b00, acc[2 * kt][3] + b01, l1);
        uint32_t a2 = pack_split(acc[2 * kt + 1][0] + b02, acc[2 * kt + 1][1] + b03, l2);
        uint32_t a3 = pack_split(acc[2 * kt + 1][2] + b02, acc[2 * kt + 1][3] + b03, l3);
#pragma unroll
        for (int nt = 0; nt < 8; nt++) {
            int fo = (kt * 8 + nt) * 64 + lane * 2;
            uint2 bH = __ldg((const uint2*)(fH + fo));
            uint2 bL = __ldg((const uint2*)(fL + fo));
            mma16816(acc2[nt], a0, a1, a2, a3, bH.x, bH.y);
            mma16816(acc2[nt], a0, a1, a2, a3, bL.x, bL.y);
            mma16816(acc2[nt], l0, l1, l2, l3, bH.x, bH.y);
        }
    }
}

// ---------------- zero scratch ----------------
__global__ void k_zero() {
    size_t tid = (size_t)blockIdx.x * blockDim.x + threadIdx.x;
    size_t stride = (size_t)gridDim.x * blockDim.x;
    const size_t n4 = (size_t)NUc * 16;
    float4 z = make_float4(0.f, 0.f, 0.f, 0.f);
    for (size_t j = tid; j < n4; j += stride) {
        ((float4*)g_s_social)[j] = z;
        ((float4*)g_s_ru)[j] = z;
        ((float4*)g_s_rv)[j] = z;
    }
    for (size_t j = tid; j < NUc; j += stride) {
        g_deg_s[j] = 0.f;
        g_deg_ru[j] = 0.f;
        g_deg_rv[j] = 0.f;
    }
    if (tid < 128) { g_statU[tid] = 0.0; g_statV[tid] = 0.0; g_stat1[tid] = 0.0; }
    if (tid < 32) g_stat2[tid] = 0.0;
}

// ---------------- prep: fp16 copies of u2e / v2e for the scatter gather ----------------
__global__ __launch_bounds__(256) void k_prepH(const float* __restrict__ u2e,
                                               const float* __restrict__ v2e) {
    size_t i = (size_t)blockIdx.x * blockDim.x + threadIdx.x;   // float4 index
    const size_t n4 = (size_t)NUc * 16;
    if (i >= n4) return;
    float4 a = __ldg((const float4*)u2e + i);
    float4 b = __ldg((const float4*)v2e + i);
    __half2 a0 = __floats2half2_rn(a.x, a.y), a1 = __floats2half2_rn(a.z, a.w);
    __half2 b0 = __floats2half2_rn(b.x, b.y), b1 = __floats2half2_rn(b.z, b.w);
    ((uint2*)g_xuh)[i] = make_uint2(h2bits(a0), h2bits(a1));
    ((uint2*)g_xvh)[i] = make_uint2(h2bits(b0), h2bits(b1));
}

// ---------------- prep: edge weight fragments (Wuv1, Wuv2) fp16 hi/lo ----------------
__global__ void k_prepW(const float* __restrict__ W1, const float* __restrict__ W2) {
    int t = threadIdx.x;
    for (int idx = t; idx < 2048; idx += 256) {
        int r = idx & 1;
        int lane = (idx >> 1) & 31;
        int grp = idx >> 6;
        int kt = grp >> 3, nt = grp & 7;
        int g = lane >> 2, tig = lane & 3;
        int n = nt * 8 + g;
        int k0 = kt * 16 + 2 * tig + (r ? 8 : 0);
        uint32_t lo;
        uint32_t hi = pack_splith(__ldg(W1 + k0 * 64 + n), __ldg(W1 + (k0 + 1) * 64 + n), lo);
        g_fragH[idx] = hi;
        g_fragL[idx] = lo;
    }
    for (int idx = t; idx < 512; idx += 256) {
        int r = idx & 1;
        int lane = (idx >> 1) & 31;
        int grp = idx >> 6;
        int kt = grp >> 1, nt = grp & 1;
        int g = lane >> 2, tig = lane & 3;
        int n = nt * 8 + g;
        int k0 = kt * 16 + 2 * tig + (r ? 8 : 0);
        uint32_t lo;
        uint32_t hi = pack_splith(__ldg(W2 + k0 * 16 + n), __ldg(W2 + (k0 + 1) * 16 + n), lo);
        g_frag2H[idx] = hi;
        g_frag2L[idx] = lo;
    }
}

// ---------------- prep: 9 node weight matrices into bf16 fragments ----------------
__global__ void k_prepN(const float* __restrict__ Ws, const float* __restrict__ Wn,
                        const float* __restrict__ Wur1_, const float* __restrict__ Wvr1_,
                        const float* __restrict__ Wur2_, const float* __restrict__ Wvr2_) {
    int t = blockIdx.x * blockDim.x + threadIdx.x;
    if (t >= 2048) return;
    int r = t & 1;
    int lane = (t >> 1) & 31;
    int grp = t >> 6;
    int kt = grp >> 3, nt = grp & 7;
    int g = lane >> 2, tig = lane & 3;
    int n = nt * 8 + g;
    int k0 = kt * 16 + 2 * tig + (r ? 8 : 0);
    const float* base[9] = {nullptr, Wn, Wn + 2 * 4096, Wur1_, Ws + 4096,
                            Wn + 4096, Wvr1_, Wur2_, Wvr2_};
#pragma unroll
    for (int m = 0; m < 9; m++) {
        float w0, w1;
        if (m == 0) {
            w0 = __ldg(Ws + k0 * 64 + n) + __ldg(Ws + 2 * 4096 + k0 * 64 + n);
            w1 = __ldg(Ws + (k0 + 1) * 64 + n) + __ldg(Ws + 2 * 4096 + (k0 + 1) * 64 + n);
        } else {
            const float* W = base[m];
            w0 = __ldg(W + k0 * 64 + n);
            w1 = __ldg(W + (k0 + 1) * 64 + n);
        }
        uint32_t lo;
        uint32_t hi = pack_split(w0, w1, lo);
        g_nfH[m * 2048 + t] = hi;
        g_nfL[m * 2048 + t] = lo;
    }
}

// ---------------- fused scatter: all 3 segment sums, fp16 gathers, fp32 REDs ----------------
__global__ __launch_bounds__(256) void k_scatAll(
    const __half* __restrict__ uh, const __half* __restrict__ vh,
    const int* __restrict__ ss, const int* __restrict__ sd,
    const int* __restrict__ rs, const int* __restrict__ rd,
    float* __restrict__ s_soc, float* __restrict__ s_rv, float* __restrict__ s_ru,
    float* __restrict__ deg_s, float* __restrict__ deg_rv, float* __restrict__ deg_ru) {
    int g = blockIdx.x * blockDim.x + threadIdx.x;
    int e = g >> 4;
    int q = g & 15;
    if (e >= ERc) return;
    int s = __ldg(rs + e);
    int d = __ldg(rd + e);
    bool soc = e < ESc;
    int s2 = 0, d2 = 0;
    if (soc) { s2 = __ldg(ss + e); d2 = __ldg(sd + e); }
    // issue all gathers first (3 independent chains), 8B each
    uint2 A = __ldg((const uint2*)(uh + (size_t)s * 64 + q * 4));
    uint2 B = __ldg((const uint2*)(vh + (size_t)d * 64 + q * 4));
    uint2 C = make_uint2(0u, 0u);
    if (soc) C = __ldg((const uint2*)(uh + (size_t)s2 * 64 + q * 4));
    float2 a01 = __half22float2(*(const __half2*)&A.x);
    float2 a23 = __half22float2(*(const __half2*)&A.y);
    float2 b01 = __half22float2(*(const __half2*)&B.x);
    float2 b23 = __half22float2(*(const __half2*)&B.y);
    float* p1 = s_rv + (size_t)d * 64 + q * 4;
    float* p2 = s_ru + (size_t)s * 64 + q * 4;
    asm volatile("red.global.add.v4.f32 [%0], {%1, %2, %3, %4};"
                 :: "l"(p1), "f"(a01.x), "f"(a01.y), "f"(a23.x), "f"(a23.y) : "memory");
    asm volatile("red.global.add.v4.f32 [%0], {%1, %2, %3, %4};"
                 :: "l"(p2), "f"(b01.x), "f"(b01.y), "f"(b23.x), "f"(b23.y) : "memory");
    if (soc) {
        float2 c01 = __half22float2(*(const __half2*)&C.x);
        float2 c23 = __half22float2(*(const __half2*)&C.y);
        float* p3 = s_soc + (size_t)d2 * 64 + q * 4;
        asm volatile("red.global.add.v4.f32 [%0], {%1, %2, %3, %4};"
                     :: "l"(p3), "f"(c01.x), "f"(c01.y), "f"(c23.x), "f"(c23.y) : "memory");
    }
    if (q == 0) {
        atomicAdd(deg_rv + d, 1.0f);
        atomicAdd(deg_ru + s, 1.0f);
        if (soc) atomicAdd(deg_s + d2, 1.0f);
    }
}

#define NBn ((NUc + 127) / 128)   // 391

// ---------------- merged node stage-1: user (blocks < NBn) / item (rest) ----------------
__global__ __launch_bounds__(256)
void k_node1_mma(const float* __restrict__ u2e, const float* __restrict__ v2e,
                 const float* __restrict__ bself,
                 const float* __restrict__ bu1, const float* __restrict__ bv1,
                 float* __restrict__ tu, float* __restrict__ tv,
                 double* __restrict__ stU, double* __restrict__ stV) {
    __shared__ __align__(16) char smem[34816];
    __shared__ float biasS[64];
    __shared__ float ssum[64], ssq[64];
    int t = threadIdx.x, lane = t & 31, w = t >> 5;
    int g = lane >> 2, tig = lane & 3;
    int r0 = w * 16 + g;
    bool isU = (int)blockIdx.x < NBn;
    int rowBase = (isU ? blockIdx.x : blockIdx.x - NBn) * 128;
    const float* in0 = isU ? u2e : v2e;
    const float* b1 = isU ? bu1 : bv1;
    float* out = isU ? tu : tv;
    double* stats = isU ? stU : stV;

    if (t < 64) {
        biasS[t] = isU ? (__ldg(bself + t) + __ldg(bself + 128 + t)) : __ldg(bself + 64 + t);
        ssum[t] = 0.f;
        ssq[t] = 0.f;
    }

    float acc[8][4] = {};
    stageA(smem, in0, nullptr, rowBase, NUc, t);
    __syncthreads();
    mma_AB(smem, g_nfH + (isU ? 0 : 4) * 2048, g_nfL + (isU ? 0 : 4) * 2048, r0, tig, lane, acc);
    __syncthreads();
    stageA(smem, isU ? g_s_social : g_s_rv, isU ? g_deg_s : g_deg_rv, rowBase, NUc, t);
    __syncthreads();
    mma_AB(smem, g_nfH + (isU ? 1 : 5) * 2048, g_nfL + (isU ? 1 : 5) * 2048, r0, tig, lane, acc);
    __syncthreads();
    if (isU) {
        stageA(smem, g_s_ru, g_deg_ru, rowBase, NUc, t);
        __syncthreads();
        mma_AB(smem, g_nfH + 2 * 2048, g_nfL + 2 * 2048, r0, tig, lane, acc);
        __syncthreads();
    }

    float acc2[8][4] = {};
    frag_gemm64(acc, biasS, g_nfH + (isU ? 3 : 6) * 2048, g_nfL + (isU ? 3 : 6) * 2048,
                tig, lane, acc2);

    float* stage = (float*)smem;
#pragma unroll
    for (int nt = 0; nt < 8; nt++) {
        int c = nt * 8 + tig * 2;
        stage[r0 * 65 + c] = acc2[nt][0];
        stage[r0 * 65 + c + 1] = acc2[nt][1];
        stage[(r0 + 8) * 65 + c] = acc2[nt][2];
        stage[(r0 + 8) * 65 + c + 1] = acc2[nt][3];
    }
    __syncthreads();

    int c4 = (t & 15) * 4;
    float4 bias = *(const float4*)(b1 + c4);
    float cs[4] = {0, 0, 0, 0}, cq[4] = {0, 0, 0, 0};
#pragma unroll
    for (int i = 0; i < 8; i++) {
        int r = (t >> 4) + 16 * i;
        int row = rowBase + r;
        if (row < NUc) {
            const float* sp = stage + r * 65 + c4;
            float v0 = sp[0] + bias.x, v1 = sp[1] + bias.y;
            float v2 = sp[2] + bias.z, v3 = sp[3] + bias.w;
            *(float4*)(out + (size_t)row * 64 + c4) = make_float4(v0, v1, v2, v3);
            cs[0] += v0; cq[0] += v0 * v0;
            cs[1] += v1; cq[1] += v1 * v1;
            cs[2] += v2; cq[2] += v2 * v2;
            cs[3] += v3; cq[3] += v3 * v3;
        }
    }
#pragma unroll
    for (int j = 0; j < 4; j++) {
        atomicAdd(&ssum[c4 + j], cs[j]);
        atomicAdd(&ssq[c4 + j], cq[j]);
    }
    __syncthreads();
    if (t < 64) atomicAdd(&stats[t], (double)ssum[t]);
    else if (t < 128) atomicAdd(&stats[t], (double)ssq[t - 64]);
}

// ---------------- BN finalize (one set) ----------------
__global__ void k_fin(const double* __restrict__ stats, const float* __restrict__ gamma,
                      const float* __restrict__ beta, float* __restrict__ aff,
                      int C, float invN) {
    int c = threadIdx.x;
    if (c < C) {
        float mean = (float)(stats[c] * (double)invN);
        float ex2 = (float)(stats[C + c] * (double)invN);
        float var = ex2 - mean * mean;
        float a = gamma[c] * rsqrtf(var + 1e-5f);
        aff[c] = a;
        aff[C + c] = beta[c] - mean * a;
    }
}

// ---------------- BN finalize for U and V in one launch ----------------
__global__ void k_fin2(const double* __restrict__ stU, const double* __restrict__ stV,
                       const float* __restrict__ gamma, const float* __restrict__ beta,
                       float* __restrict__ affU, float* __restrict__ affV) {
    int t = threadIdx.x;   // 128
    const double* st = (t < 64) ? stU : stV;
    float* aff = (t < 64) ? affU : affV;
    int c = t & 63;
    int go = (t < 64) ? 0 : 64;
    float invN = 1.0f / NUc;   // NU == NV
    float mean = (float)(st[c] * (double)invN);
    float ex2 = (float)(st[64 + c] * (double)invN);
    float var = ex2 - mean * mean;
    float a = __ldg(gamma + go + c) * rsqrtf(var + 1e-5f);
    aff[c] = a;
    aff[64 + c] = __ldg(beta + go + c) - mean * a;
}

// ---------------- merged tower2: user/item, bf16 3-term, fp16 out ----------------
__global__ __launch_bounds__(256)
void k_tower2m(const float* __restrict__ tu, const float* __restrict__ tv,
               const float* __restrict__ affU, const float* __restrict__ affV,
               const float* __restrict__ bu2, const float* __restrict__ bv2,
               __half* __restrict__ xu, __half* __restrict__ xv) {
    __shared__ float stage[128 * 65];
    __shared__ float affS[128];
    int t = threadIdx.x, lane = t & 31, w = t >> 5;
    int g = lane >> 2, tig = lane & 3;
    int r0 = w * 16 + g;
    bool isU = (int)blockIdx.x < NBn;
    int rowBase = (isU ? blockIdx.x : blockIdx.x - NBn) * 128;
    const float* in = isU ? tu : tv;
    const float* aff = isU ? affU : affV;
    const float* b2 = isU ? bu2 : bv2;
    __half* out = isU ? xu : xv;
    const uint32_t* fH = g_nfH + (isU ? 7 : 8) * 2048;
    const uint32_t* fL = g_nfL + (isU ? 7 : 8) * 2048;
    if (t < 128) affS[t] = __ldg(aff + t);
    __syncthreads();

    int e0 = rowBase + r0, e1 = e0 + 8;
    bool ok0 = e0 < NUc, ok1 = e1 < NUc;   // NU == NV

    float acc2[8][4] = {};
#pragma unroll
    for (int kt = 0; kt < 4; kt++) {
        int c0 = kt * 16 + tig * 2;
        float2 z = make_float2(0.f, 0.f);
        float2 y00 = ok0 ? *(const float2*)(in + (size_t)e0 * 64 + c0) : z;
        float2 y10 = ok0 ? *(const float2*)(in + (size_t)e0 * 64 + c0 + 8) : z;
        float2 y01 = ok1 ? *(const float2*)(in + (size_t)e1 * 64 + c0) : z;
        float2 y11 = ok1 ? *(const float2*)(in + (size_t)e1 * 64 + c0 + 8) : z;
        float s0 = affS[c0], h0 = affS[64 + c0];
        float s1 = affS[c0 + 1], h1 = affS[64 + c0 + 1];
        float s2 = affS[c0 + 8], h2 = affS[64 + c0 + 8];
        float s3 = affS[c0 + 9], h3 = affS[64 + c0 + 9];
        float v00 = fmaxf(y00.x * s0 + h0, 0.f), v01 = fmaxf(y00.y * s1 + h1, 0.f);
        float v10 = fmaxf(y01.x * s0 + h0, 0.f), v11 = fmaxf(y01.y * s1 + h1, 0.f);
        float w00 = fmaxf(y10.x * s2 + h2, 0.f), w01 = fmaxf(y10.y * s3 + h3, 0.f);
        float w10 = fmaxf(y11.x * s2 + h2, 0.f), w11 = fmaxf(y11.y * s3 + h3, 0.f);
        uint32_t l0, l1, l2, l3;
        uint32_t a0 = pack_split(v00, v01, l0);
        uint32_t a1 = pack_split(v10, v11, l1);
        uint32_t a2 = pack_split(w00, w01, l2);
        uint32_t a3 = pack_split(w10, w11, l3);
#pragma unroll
        for (int nt = 0; nt < 8; nt++) {
            int fo = (kt * 8 + nt) * 64 + lane * 2;
            uint2 bH = __ldg((const uint2*)(fH + fo));
            uint2 bL = __ldg((const uint2*)(fL + fo));
            mma16816(acc2[nt], a0, a1, a2, a3, bH.x, bH.y);
            mma16816(acc2[nt], a0, a1, a2, a3, bL.x, bL.y);
            mma16816(acc2[nt], l0, l1, l2, l3, bH.x, bH.y);
        }
    }

#pragma unroll
    for (int nt = 0; nt < 8; nt++) {
        int c = nt * 8 + tig * 2;
        stage[r0 * 65 + c] = acc2[nt][0];
        stage[r0 * 65 + c + 1] = acc2[nt][1];
        stage[(r0 + 8) * 65 + c] = acc2[nt][2];
        stage[(r0 + 8) * 65 + c + 1] = acc2[nt][3];
    }
    __syncthreads();

    int c4 = (t & 15) * 4;
    float4 bias = *(const float4*)(b2 + c4);
#pragma unroll
    for (int i = 0; i < 8; i++) {
        int r = (t >> 4) + 16 * i;
        int row = rowBase + r;
        if (row < NUc) {
            const float* sp = stage + r * 65 + c4;
            __half2 ha = __floats2half2_rn(sp[0] + bias.x, sp[1] + bias.y);
            __half2 hb = __floats2half2_rn(sp[2] + bias.z, sp[3] + bias.w);
            *(uint2*)(out + (size_t)row * 64 + c4) = make_uint2(h2bits(ha), h2bits(hb));
        }
    }
}

// ================= edge pass 1: fp16 gather -> fp16 A, f16 mma, 2-term W split =================
#define E1_SMEM 33792
#define E1_OFF_A 0        // fp16 A: 128 rows x 136B = 17408
#define E1_OFF_BH 17408   // Whi fp16 frags: 8192
#define E1_OFF_BL 25600   // Wlo fp16 frags: 8192

__global__ __launch_bounds__(256)
void k_edge1_mma(const __half* __restrict__ xu, const __half* __restrict__ xv,
                 const int* __restrict__ es, const int* __restrict__ ed,
                 const float* __restrict__ b, __half* __restrict__ out,
                 double* __restrict__ stats) {
    extern __shared__ __align__(16) char smem[];
    __shared__ float ssum[64], ssq[64];
    int t = threadIdx.x, lane = t & 31, w = t >> 5;
    int rowBase = blockIdx.x * 128;
    if (t < 64) { ssum[t] = 0.f; ssq[t] = 0.f; }

    {
        const uint4* sH = (const uint4*)g_fragH;
        const uint4* sL = (const uint4*)g_fragL;
        uint4* dH = (uint4*)(smem + E1_OFF_BH);
        uint4* dL = (uint4*)(smem + E1_OFF_BL);
        dH[t] = __ldg(sH + t);
        dH[t + 256] = __ldg(sH + t + 256);
        dL[t] = __ldg(sL + t);
        dL[t + 256] = __ldg(sL + t + 256);
    }
    {
        int r = t >> 1, h = t & 1;
        int e = rowBase + r;
        char* aA = smem + E1_OFF_A + r * AROW + h * 64;
        if (e < ERc) {
            int s = __ldg(es + e), d = __ldg(ed + e);
            const uint4* pu = (const uint4*)(xu + (size_t)s * 64) + h * 4;
            const uint4* pv = (const uint4*)(xv + (size_t)d * 64) + h * 4;
#pragma unroll
            for (int j = 0; j < 4; j++) {
                uint4 A = __ldg(pu + j), V = __ldg(pv + j);
                float2 a0 = __half22float2(*(const __half2*)&A.x);
                float2 a1 = __half22float2(*(const __half2*)&A.y);
                float2 a2 = __half22float2(*(const __half2*)&A.z);
                float2 a3 = __half22float2(*(const __half2*)&A.w);
                float2 v0 = __half22float2(*(const __half2*)&V.x);
                float2 v1 = __half22float2(*(const __half2*)&V.y);
                float2 v2 = __half22float2(*(const __half2*)&V.z);
                float2 v3 = __half22float2(*(const __half2*)&V.w);
                __half2 p0 = __floats2half2_rn(a0.x * v0.x, a0.y * v0.y);
                __half2 p1 = __floats2half2_rn(a1.x * v1.x, a1.y * v1.y);
                __half2 p2 = __floats2half2_rn(a2.x * v2.x, a2.y * v2.y);
                __half2 p3 = __floats2half2_rn(a3.x * v3.x, a3.y * v3.y);
                *(uint2*)(aA + j * 16) = make_uint2(h2bits(p0), h2bits(p1));
                *(uint2*)(aA + j * 16 + 8) = make_uint2(h2bits(p2), h2bits(p3));
            }
        } else {
#pragma unroll
            for (int j = 0; j < 8; j++)
                *(uint2*)(aA + j * 8) = make_uint2(0u, 0u);
        }
    }
    __syncthreads();

    int g = lane >> 2, tig = lane & 3;
    int r0 = w * 16 + g;
    float acc[8][4] = {};
    const char* AA = smem + E1_OFF_A;
#pragma unroll
    for (int kt = 0; kt < 4; kt++) {
        int ka = kt * 32 + tig * 4;
        uint32_t a0 = *(const uint32_t*)(AA + r0 * AROW + ka);
        uint32_t a1 = *(const uint32_t*)(AA + (r0 + 8) * AROW + ka);
        uint32_t a2 = *(const uint32_t*)(AA + r0 * AROW + ka + 16);
        uint32_t a3 = *(const uint32_t*)(AA + (r0 + 8) * AROW + ka + 16);
#pragma unroll
        for (int nt = 0; nt < 8; nt++) {
            uint32_t boff = ((kt * 8 + nt) * 64 + lane * 2) * 4;
            uint2 bH = *(const uint2*)(smem + E1_OFF_BH + boff);
            uint2 bL = *(const uint2*)(smem + E1_OFF_BL + boff);
            mma16816h(acc[nt], a0, a1, a2, a3, bH.x, bH.y);
            mma16816h(acc[nt], a0, a1, a2, a3, bL.x, bL.y);
        }
    }
    __syncthreads();

    float* stage = (float*)smem;
#pragma unroll
    for (int nt = 0; nt < 8; nt++) {
        int c = nt * 8 + tig * 2;
        stage[r0 * 65 + c] = acc[nt][0];
        stage[r0 * 65 + c + 1] = acc[nt][1];
        stage[(r0 + 8) * 65 + c] = acc[nt][2];
        stage[(r0 + 8) * 65 + c + 1] = acc[nt][3];
    }
    __syncthreads();

    int c4 = (t & 15) * 4;
    float4 bias = *(const float4*)(b + c4);
    float cs[4] = {0, 0, 0, 0}, cq[4] = {0, 0, 0, 0};
#pragma unroll
    for (int i = 0; i < 8; i++) {
        int r = (t >> 4) + 16 * i;
        int e = rowBase + r;
        if (e < ERc) {
            const float* sp = stage + r * 65 + c4;
            float v0 = sp[0] + bias.x, v1 = sp[1] + bias.y;
            float v2 = sp[2] + bias.z, v3 = sp[3] + bias.w;
            __half2 ha = __floats2half2_rn(v0, v1);
            __half2 hb = __floats2half2_rn(v2, v3);
            *(uint2*)(out + (size_t)e * 64 + c4) = make_uint2(h2bits(ha), h2bits(hb));
            cs[0] += v0; cq[0] += v0 * v0;
            cs[1] += v1; cq[1] += v1 * v1;
            cs[2] += v2; cq[2] += v2 * v2;
            cs[3] += v3; cq[3] += v3 * v3;
        }
    }
#pragma unroll
    for (int j = 0; j < 4; j++) {
        atomicAdd(&ssum[c4 + j], cs[j]);
        atomicAdd(&ssq[c4 + j], cq[j]);
    }
    __syncthreads();
    if (t < 64) atomicAdd(&stats[t], (double)ssum[t]);
    else if (t < 128) atomicAdd(&stats[t], (double)ssq[t - 64]);
}

// ================= edge pass 2: fp16 y1 in, f16 mma, 2-term W2 split, fp16 y2 out =================
__global__ __launch_bounds__(256)
void k_edge2_mma(const __half* __restrict__ y1, const float* __restrict__ aff,
                 const float* __restrict__ b2, __half* __restrict__ y2,
                 double* __restrict__ stats) {
    __shared__ float affS[128];
    __shared__ __align__(16) uint32_t f2H[512], f2L[512];
    __shared__ float ssum[16], ssq[16];
    int t = threadIdx.x, lane = t & 31, w = t >> 5;
    int rowBase = blockIdx.x * 128;
    if (t < 128) affS[t] = __ldg(aff + t);
    if (t < 16) { ssum[t] = 0.f; ssq[t] = 0.f; }
    {
        ((uint2*)f2H)[t] = __ldg((const uint2*)g_frag2H + t);
        ((uint2*)f2L)[t] = __ldg((const uint2*)g_frag2L + t);
    }
    __syncthreads();

    int g = lane >> 2, tig = lane & 3;
    int r0 = w * 16 + g;
    int e0 = rowBase + r0, e1 = e0 + 8;
    bool ok0 = e0 < ERc, ok1 = e1 < ERc;

    float acc2[2][4] = {};
#pragma unroll
    for (int kt = 0; kt < 4; kt++) {
        int c0 = kt * 16 + tig * 2;
        float2 z = make_float2(0.f, 0.f);
        float2 y00 = ok0 ? __half22float2(*(const __half2*)(y1 + (size_t)e0 * 64 + c0)) : z;
        float2 y10 = ok1 ? __half22float2(*(const __half2*)(y1 + (size_t)e1 * 64 + c0)) : z;
        float2 y01 = ok0 ? __half22float2(*(const __half2*)(y1 + (size_t)e0 * 64 + c0 + 8)) : z;
        float2 y11 = ok1 ? __half22float2(*(const __half2*)(y1 + (size_t)e1 * 64 + c0 + 8)) : z;
        float s0 = affS[c0], h0 = affS[64 + c0];
        float s1 = affS[c0 + 1], h1 = affS[64 + c0 + 1];
        float s2 = affS[c0 + 8], h2 = affS[64 + c0 + 8];
        float s3 = affS[c0 + 9], h3 = affS[64 + c0 + 9];
        uint32_t a0 = h2bits(__floats2half2_rn(fmaxf(y00.x * s0 + h0, 0.f),
                                               fmaxf(y00.y * s1 + h1, 0.f)));
        uint32_t a1 = h2bits(__floats2half2_rn(fmaxf(y10.x * s0 + h0, 0.f),
                                               fmaxf(y10.y * s1 + h1, 0.f)));
        uint32_t a2 = h2bits(__floats2half2_rn(fmaxf(y01.x * s2 + h2, 0.f),
                                               fmaxf(y01.y * s3 + h3, 0.f)));
        uint32_t a3 = h2bits(__floats2half2_rn(fmaxf(y11.x * s2 + h2, 0.f),
                                               fmaxf(y11.y * s3 + h3, 0.f)));
#pragma unroll
        for (int n2 = 0; n2 < 2; n2++) {
            int fo = (kt * 2 + n2) * 64 + lane * 2;
            uint2 bH = *(const uint2*)(f2H + fo);
            uint2 bL = *(const uint2*)(f2L + fo);
            mma16816h(acc2[n2], a0, a1, a2, a3, bH.x, bH.y);
            mma16816h(acc2[n2], a0, a1, a2, a3, bL.x, bL.y);
        }
    }

    float cs[4] = {0, 0, 0, 0}, cq[4] = {0, 0, 0, 0};
#pragma unroll
    for (int n2 = 0; n2 < 2; n2++) {
        int c = n2 * 8 + tig * 2;
        float bx = __ldg(b2 + c), by = __ldg(b2 + c + 1);
        float u0 = acc2[n2][0] + bx, u1 = acc2[n2][1] + by;
        float u2 = acc2[n2][2] + bx, u3 = acc2[n2][3] + by;
        if (ok0) {
            *(uint32_t*)(y2 + (size_t)e0 * 16 + c) = h2bits(__floats2half2_rn(u0, u1));
            cs[n2 * 2] += u0; cq[n2 * 2] += u0 * u0;
            cs[n2 * 2 + 1] += u1; cq[n2 * 2 + 1] += u1 * u1;
        }
        if (ok1) {
            *(uint32_t*)(y2 + (size_t)e1 * 16 + c) = h2bits(__floats2half2_rn(u2, u3));
            cs[n2 * 2] += u2; cq[n2 * 2] += u2 * u2;
            cs[n2 * 2 + 1] += u3; cq[n2 * 2 + 1] += u3 * u3;
        }
    }
#pragma unroll
    for (int n2 = 0; n2 < 2; n2++) {
#pragma unroll
        for (int j = 0; j < 2; j++) {
            int c = n2 * 8 + tig * 2 + j;
            atomicAdd(&ssum[c], cs[n2 * 2 + j]);
            atomicAdd(&ssq[c], cq[n2 * 2 + j]);
        }
    }
    __syncthreads();
    if (t < 16) atomicAdd(&stats[t], (double)ssum[t]);
    else if (t < 32) atomicAdd(&stats[t], (double)ssq[t - 16]);
}

// ---------------- edge pass 3: scores = relu(y2*a2+c2) . w3 + b3 (fp16 y2 in) ----------------
__global__ __launch_bounds__(256) void k_edge3(
    const __half* __restrict__ y2, const float* __restrict__ aff,
    const float* __restrict__ w3, const float* __restrict__ b3,
    float* __restrict__ out) {
    int e = blockIdx.x * blockDim.x + threadIdx.x;
    if (e >= ERc) return;
    const uint4* p = (const uint4*)(y2 + (size_t)e * 16);
    float s = 0.f;
#pragma unroll
    for (int j = 0; j < 2; j++) {
        uint4 V = __ldg(p + j);
        float2 v0 = __half22float2(*(const __half2*)&V.x);
        float2 v1 = __half22float2(*(const __half2*)&V.y);
        float2 v2 = __half22float2(*(const __half2*)&V.z);
        float2 v3 = __half22float2(*(const __half2*)&V.w);
        float vv[8] = {v0.x, v0.y, v1.x, v1.y, v2.x, v2.y, v3.x, v3.y};
#pragma unroll
        for (int k = 0; k < 8; k++) {
            int c = j * 8 + k;
            s += fmaxf(vv[k] * aff[c] + aff[16 + c], 0.f) * __ldg(w3 + c);
        }
    }
    out[e] = s + __ldg(b3);
}

// ---------------- host ----------------
extern "C" void kernel_launch(void* const* d_in, const int* in_sizes, int n_in,
                              void* d_out, int out_size) {
    const float* u2e     = (const float*)d_in[0];
    const float* v2e     = (const float*)d_in[1];
    const float* W_self  = (const float*)d_in[2];
    const float* b_self  = (const float*)d_in[3];
    const float* W_neigh = (const float*)d_in[4];
    const float* Wur1 = (const float*)d_in[5];
    const float* bur1 = (const float*)d_in[6];
    const float* Wur2 = (const float*)d_in[7];
    const float* bur2 = (const float*)d_in[8];
    const float* Wvr1 = (const float*)d_in[9];
    const float* bvr1 = (const float*)d_in[10];
    const float* Wvr2 = (const float*)d_in[11];
    const float* bvr2 = (const float*)d_in[12];
    const float* Wuv1 = (const float*)d_in[13];
    const float* buv1 = (const float*)d_in[14];
    const float* Wuv2 = (const float*)d_in[15];
    const float* buv2 = (const float*)d_in[16];
    const float* Wuv3 = (const float*)d_in[17];
    const float* buv3 = (const float*)d_in[18];
    const float* bn_gamma  = (const float*)d_in[19];
    const float* bn_beta   = (const float*)d_in[20];
    const float* bn4_gamma = (const float*)d_in[21];
    const float* bn4_beta  = (const float*)d_in[22];
    const int* social_src = (const int*)d_in[23];
    const int* social_dst = (const int*)d_in[24];
    const int* rates_src  = (const int*)d_in[25];
    const int* rates_dst  = (const int*)d_in[26];
    float* out = (float*)d_out;

    void *p_ssoc, *p_sru, *p_srv, *p_degs, *p_degru, *p_degrv;
    void *p_tu, *p_tv, *p_xu, *p_xv, *p_y1, *p_y2;
    void *p_stU, *p_stV, *p_st1, *p_st2, *p_aU, *p_aV, *p_a1, *p_a2;
    cudaGetSymbolAddress(&p_ssoc, g_s_social);
    cudaGetSymbolAddress(&p_sru, g_s_ru);
    cudaGetSymbolAddress(&p_srv, g_s_rv);
    cudaGetSymbolAddress(&p_degs, g_deg_s);
    cudaGetSymbolAddress(&p_degru, g_deg_ru);
    cudaGetSymbolAddress(&p_degrv, g_deg_rv);
    cudaGetSymbolAddress(&p_tu, g_tu);
    cudaGetSymbolAddress(&p_tv, g_tv);
    cudaGetSymbolAddress(&p_xu, g_xuh);
    cudaGetSymbolAddress(&p_xv, g_xvh);
    cudaGetSymbolAddress(&p_y1, g_y1h);
    cudaGetSymbolAddress(&p_y2, g_y2h);
    cudaGetSymbolAddress(&p_stU, g_statU);
    cudaGetSymbolAddress(&p_stV, g_statV);
    cudaGetSymbolAddress(&p_st1, g_stat1);
    cudaGetSymbolAddress(&p_st2, g_stat2);
    cudaGetSymbolAddress(&p_aU, g_affU);
    cudaGetSymbolAddress(&p_aV, g_affV);
    cudaGetSymbolAddress(&p_a1, g_aff1);
    cudaGetSymbolAddress(&p_a2, g_aff2);

    cudaFuncSetAttribute(k_edge1_mma, cudaFuncAttributeMaxDynamicSharedMemorySize, E1_SMEM);

    const int NB_E1 = (ERc + 127) / 128;

    k_zero<<<2048, 256>>>();
    k_prepH<<<(NUc * 16 + 255) / 256, 256>>>(u2e, v2e);   // fp16 tables for scatter
    k_prepW<<<1, 256>>>(Wuv1, Wuv2);
    k_prepN<<<8, 256>>>(W_self, W_neigh, Wur1, Wvr1, Wur2, Wvr2);

    // all three segment sums, fp16 gathers (g_xuh/g_xvh hold fp16 u2e/v2e here)
    k_scatAll<<<ERc / 16, 256>>>((const __half*)p_xu, (const __half*)p_xv,
                                 social_src, social_dst, rates_src, rates_dst,
                                 (float*)p_ssoc, (float*)p_srv, (float*)p_sru,
                                 (float*)p_degs, (float*)p_degrv, (float*)p_degru);

    k_node1_mma<<<2 * NBn, 256>>>(u2e, v2e, b_self, bur1, bvr1,
                                  (float*)p_tu, (float*)p_tv,
                                  (double*)p_stU, (double*)p_stV);
    k_fin2<<<1, 128>>>((const double*)p_stU, (const double*)p_stV,
                       bn_gamma, bn_beta, (float*)p_aU, (float*)p_aV);
    // tower2m overwrites g_xuh/g_xvh with x_u/x_v (scatAll is long done)
    k_tower2m<<<2 * NBn, 256>>>((const float*)p_tu, (const float*)p_tv,
                                (const float*)p_aU, (const float*)p_aV,
                                bur2, bvr2, (__half*)p_xu, (__half*)p_xv);

    k_edge1_mma<<<NB_E1, 256, E1_SMEM>>>((const __half*)p_xu, (const __half*)p_xv,
                                         rates_src, rates_dst, buv1,
                                         (__half*)p_y1, (double*)p_st1);
    k_fin<<<1, 64>>>((const double*)p_st1, bn_gamma + 128, bn_beta + 128, (float*)p_a1, 64, 1.0f / ERc);
    k_edge2_mma<<<NB_E1, 256>>>((const __half*)p_y1, (const float*)p_a1, buv2,
                                (__half*)p_y2, (double*)p_st2);
    k_fin<<<1, 16>>>((const double*)p_st2, bn4_gamma, bn4_beta, (float*)p_a2, 16, 1.0f / ERc);
    k_edge3<<<(ERc + 255) / 256, 256>>>((const __half*)p_y2, (const float*)p_a2, Wuv3, buv3, out);

    (void)in_sizes; (void)n_in; (void)out_size;
}